// round 1
// baseline (speedup 1.0000x reference)
#include <cuda_runtime.h>
#include <math.h>
#include <stdint.h>

#define Bb 4
#define Nn 2048
#define Dd 256
#define Hh 4
#define HDd 64
#define M2 (2*Bb*Nn)            // 16384 rows when desc0||desc1 concatenated
#define BND ((size_t)Bb*Nn*Dd)  // 2097152

// ---------------- static scratch (no cudaMalloc allowed) ----------------
__device__ float g_x  [(size_t)M2*Dd];          // current x for both descriptors
__device__ float g_qkv[(size_t)M2*3*Dd];
__device__ float g_q  [(size_t)2*Bb*Hh*Nn*HDd]; // heads layout (32 batches x N x HD)
__device__ float g_k  [(size_t)2*Bb*Hh*Nn*HDd];
__device__ float g_v  [(size_t)2*Bb*Hh*Nn*HDd];
__device__ float g_sim[(size_t)2*Bb*Hh*Nn*Nn];  // 536MB: self=32 batches, cross=16(S)+16(P10)
__device__ float g_ctx [(size_t)2*Bb*Hh*Nn*HDd];
__device__ float g_ctx2[(size_t)Bb*Hh*Nn*HDd];
__device__ float g_tmp[(size_t)M2*Dd];
__device__ float g_msg[(size_t)M2*Dd];
__device__ float g_cat[(size_t)M2*2*Dd];
__device__ float g_h  [(size_t)M2*2*Dd];

// ---------------- generic tiled fp32 GEMM ----------------
// C[m][n] = scale * sum_k opA(A)[m][k] * opB(B)[k][n]  (+bias[n]) (+Res[m][n])
// AT=false: A[m*lda+k]         AT=true:  A[k*lda+m]
// BT=false: B[k*ldb+n]         BT=true:  B[n*ldb+k]   (i.e. W row-major, W^T applied)
template<int BM,int BN,int BK,int TM,int TN,bool AT,bool BT>
__global__ void __launch_bounds__((BM/TM)*(BN/TN))
gemm_k(const float* __restrict__ A, int lda, size_t sA,
       const float* __restrict__ Bm, int ldb, size_t sB,
       float* __restrict__ C, int ldc, size_t sC,
       const float* __restrict__ bias,
       const float* __restrict__ Res, int ldr,
       float scale, int M, int Ncols, int K)
{
    constexpr int NTHR = (BM/TM)*(BN/TN);
    __shared__ float As[BK][BM+4];
    __shared__ float Bs[BK][BN+4];
    const int bz = blockIdx.z;
    A  += sA*(size_t)bz; Bm += sB*(size_t)bz; C += sC*(size_t)bz;
    const int bm = blockIdx.y*BM, bn = blockIdx.x*BN;
    const int tid = threadIdx.x;
    const int ncol = BN/TN;
    const int tx = tid % ncol, ty = tid / ncol;

    float acc[TM][TN];
    #pragma unroll
    for (int i=0;i<TM;i++)
        #pragma unroll
        for (int j=0;j<TN;j++) acc[i][j]=0.f;

    for (int k0=0;k0<K;k0+=BK) {
        if (!AT) {
            #pragma unroll
            for (int it=0; it<BM*BK/NTHR; it++) {
                int t = tid + it*NTHR;
                int k = t % BK, m = t / BK;
                As[k][m] = A[(size_t)(bm+m)*lda + k0 + k];
            }
        } else {
            #pragma unroll
            for (int it=0; it<BM*BK/NTHR; it++) {
                int t = tid + it*NTHR;
                int m = t % BM, k = t / BM;
                As[k][m] = A[(size_t)(k0+k)*lda + bm + m];
            }
        }
        if (BT) {
            #pragma unroll
            for (int it=0; it<BN*BK/NTHR; it++) {
                int t = tid + it*NTHR;
                int k = t % BK, n = t / BK;
                Bs[k][n] = Bm[(size_t)(bn+n)*ldb + k0 + k];
            }
        } else {
            #pragma unroll
            for (int it=0; it<BN*BK/NTHR; it++) {
                int t = tid + it*NTHR;
                int n = t % BN, k = t / BN;
                Bs[k][n] = Bm[(size_t)(k0+k)*ldb + bn + n];
            }
        }
        __syncthreads();
        #pragma unroll
        for (int k=0;k<BK;k++) {
            float a[TM], b[TN];
            #pragma unroll
            for (int i=0;i<TM;i++) a[i] = As[k][ty*TM+i];
            #pragma unroll
            for (int j=0;j<TN;j++) b[j] = Bs[k][tx*TN+j];
            #pragma unroll
            for (int i=0;i<TM;i++)
                #pragma unroll
                for (int j=0;j<TN;j++) acc[i][j] += a[i]*b[j];
        }
        __syncthreads();
    }

    #pragma unroll
    for (int i=0;i<TM;i++) {
        int r = bm + ty*TM + i;
        #pragma unroll
        for (int j=0;j<TN;j++) {
            int c = bn + tx*TN + j;
            float vv = acc[i][j]*scale;
            if (bias) vv += bias[c];
            if (Res)  vv += Res[(size_t)r*ldr + c];
            C[(size_t)r*ldc + c] = vv;
        }
    }
}

// ---------------- split QKV + RoPE into heads layout ----------------
__global__ void qkv_rope_k(const float* __restrict__ qkv,
                           const float* __restrict__ enc0,
                           const float* __restrict__ enc1,
                           float* __restrict__ Q, float* __restrict__ K,
                           float* __restrict__ V)
{
    int idx = blockIdx.x*blockDim.x + threadIdx.x;
    const int total = 2*Bb*Hh*Nn*(HDd/2);
    if (idx >= total) return;
    int p = idx % (HDd/2); int t = idx / (HDd/2);
    int n = t % Nn; t /= Nn;
    int h = t % Hh; t /= Hh;
    int b = t % Bb; int s = t / Bb;
    size_t r = (size_t)(s*Bb + b)*Nn + n;
    const float* row = qkv + r*(3*Dd);
    int d0 = 2*p, d1 = 2*p+1;
    float q0 = row[h*192 + d0*3 + 0], q1 = row[h*192 + d1*3 + 0];
    float k0 = row[h*192 + d0*3 + 1], k1 = row[h*192 + d1*3 + 1];
    float v0 = row[h*192 + d0*3 + 2], v1 = row[h*192 + d1*3 + 2];
    const float* enc = s ? enc1 : enc0;
    size_t eoff = ((size_t)b*Nn + n)*HDd;
    float c = enc[eoff + d0];                        // cos (repeated pairwise)
    float si = enc[(size_t)Bb*Nn*HDd + eoff + d0];   // sin
    // rotate_half: out[2i] = x[2i]*c - x[2i+1]*s ; out[2i+1] = x[2i+1]*c + x[2i]*s
    float qo0 = q0*c - q1*si, qo1 = q1*c + q0*si;
    float ko0 = k0*c - k1*si, ko1 = k1*c + k0*si;
    size_t bh = (size_t)(s*Bb + b)*Hh + h;
    size_t o = (bh*Nn + n)*HDd;
    Q[o+d0]=qo0; Q[o+d1]=qo1;
    K[o+d0]=ko0; K[o+d1]=ko1;
    V[o+d0]=v0;  V[o+d1]=v1;
}

// ---------------- row softmax (in place), row length N ----------------
__global__ void row_softmax_k(float* __restrict__ S)
{
    float* p = S + (size_t)blockIdx.x * Nn;
    int tid = threadIdx.x;
    float v[8];
    float m = -1e30f;
    #pragma unroll
    for (int i=0;i<8;i++){ v[i] = p[tid + i*256]; m = fmaxf(m, v[i]); }
    __shared__ float sm[8];
    #pragma unroll
    for (int o=16;o;o>>=1) m = fmaxf(m, __shfl_xor_sync(0xffffffffu, m, o));
    if ((tid&31)==0) sm[tid>>5] = m;
    __syncthreads();
    m = sm[0];
    #pragma unroll
    for (int t=1;t<8;t++) m = fmaxf(m, sm[t]);
    __syncthreads();
    float s = 0.f;
    #pragma unroll
    for (int i=0;i<8;i++){ v[i] = __expf(v[i]-m); s += v[i]; }
    #pragma unroll
    for (int o=16;o;o>>=1) s += __shfl_xor_sync(0xffffffffu, s, o);
    if ((tid&31)==0) sm[tid>>5] = s;
    __syncthreads();
    s = 0.f;
    #pragma unroll
    for (int t=0;t<8;t++) s += sm[t];
    float inv = 1.0f/s;
    #pragma unroll
    for (int i=0;i<8;i++) p[tid + i*256] = v[i]*inv;
}

// ---------------- column softmax S(rows x N) -> P ----------------
__global__ void col_softmax_k(const float* __restrict__ S, float* __restrict__ P)
{
    const size_t boff = (size_t)blockIdx.y * Nn * Nn;
    const float* Sb = S + boff;
    float* Pb = P + boff;
    int j = blockIdx.x*64 + threadIdx.x;
    int ty = threadIdx.y;                // 0..7
    __shared__ float red[8][64];
    float m = -1e30f;
    for (int i=ty;i<Nn;i+=8) m = fmaxf(m, Sb[(size_t)i*Nn + j]);
    red[ty][threadIdx.x] = m;
    __syncthreads();
    if (ty==0){ float mm=red[0][threadIdx.x];
        #pragma unroll
        for (int t=1;t<8;t++) mm=fmaxf(mm,red[t][threadIdx.x]);
        red[0][threadIdx.x]=mm; }
    __syncthreads();
    m = red[0][threadIdx.x];
    __syncthreads();
    float s = 0.f;
    for (int i=ty;i<Nn;i+=8) s += __expf(Sb[(size_t)i*Nn + j]-m);
    red[ty][threadIdx.x] = s;
    __syncthreads();
    if (ty==0){ float ss=0.f;
        #pragma unroll
        for (int t=0;t<8;t++) ss+=red[t][threadIdx.x];
        red[0][threadIdx.x]=ss; }
    __syncthreads();
    float inv = 1.0f/red[0][threadIdx.x];
    for (int i=ty;i<Nn;i+=8)
        Pb[(size_t)i*Nn + j] = __expf(Sb[(size_t)i*Nn + j]-m)*inv;
}

// ---------------- heads <-> flat transposes ----------------
__global__ void from_heads_k(const float* __restrict__ in, float* __restrict__ out, int total)
{
    int idx = blockIdx.x*blockDim.x + threadIdx.x;
    if (idx >= total) return;
    int d = idx % HDd; int t = idx / HDd;
    int n = t % Nn; int bh = t / Nn;
    int sb = bh / Hh, h = bh % Hh;
    out[((size_t)sb*Nn + n)*Dd + h*HDd + d] = in[idx];
}
__global__ void to_heads_k(const float* __restrict__ in, float* __restrict__ out, int total)
{
    int idx = blockIdx.x*blockDim.x + threadIdx.x;
    if (idx >= total) return;
    int d = idx % HDd; int t = idx / HDd;
    int n = t % Nn; int bh = t / Nn;
    int sb = bh / Hh, h = bh % Hh;
    out[idx] = in[((size_t)sb*Nn + n)*Dd + h*HDd + d];
}

// ---------------- concat [x | msg] -> 512 wide ----------------
__global__ void concat_k(const float* __restrict__ a, const float* __restrict__ b,
                         float* __restrict__ out)
{
    int idx = blockIdx.x*blockDim.x + threadIdx.x;
    const int total = M2*2*Dd;
    if (idx >= total) return;
    int c = idx % (2*Dd); int r = idx / (2*Dd);
    out[idx] = (c < Dd) ? a[(size_t)r*Dd + c] : b[(size_t)r*Dd + c - Dd];
}

// ---------------- fused LayerNorm(512) + exact GELU, in place ----------------
__global__ void ln_gelu_k(float* __restrict__ X, const float* __restrict__ g,
                          const float* __restrict__ be)
{
    float* p = X + (size_t)blockIdx.x * 512;
    int tid = threadIdx.x;
    float a = p[tid], b = p[tid+256];
    float s = a + b;
    float sq = a*a + b*b;
    #pragma unroll
    for (int o=16;o;o>>=1){ s += __shfl_xor_sync(0xffffffffu,s,o);
                            sq += __shfl_xor_sync(0xffffffffu,sq,o); }
    __shared__ float ss[8], sqs[8];
    if ((tid&31)==0){ ss[tid>>5]=s; sqs[tid>>5]=sq; }
    __syncthreads();
    s = 0.f; sq = 0.f;
    #pragma unroll
    for (int t=0;t<8;t++){ s+=ss[t]; sq+=sqs[t]; }
    float mean = s * (1.0f/512.0f);
    float var  = sq * (1.0f/512.0f) - mean*mean;
    float inv = rsqrtf(var + 1e-5f);
    float y0 = (a-mean)*inv*g[tid]     + be[tid];
    float y1 = (b-mean)*inv*g[tid+256] + be[tid+256];
    p[tid]     = 0.5f*y0*(1.0f+erff(y0*0.70710678118f));
    p[tid+256] = 0.5f*y1*(1.0f+erff(y1*0.70710678118f));
}

// ================= host orchestration =================
extern "C" void kernel_launch(void* const* d_in, const int* in_sizes, int n_in,
                              void* d_out, int out_size)
{
    const float* desc0  = (const float*)d_in[0];
    const float* desc1  = (const float*)d_in[1];
    const float* enc0   = (const float*)d_in[2];
    const float* enc1   = (const float*)d_in[3];
    const float* s_Wqkv = (const float*)d_in[4];
    const float* s_bqkv = (const float*)d_in[5];
    const float* s_Wout = (const float*)d_in[6];
    const float* s_bout = (const float*)d_in[7];
    const float* s_W1   = (const float*)d_in[8];
    const float* s_b1   = (const float*)d_in[9];
    const float* s_g    = (const float*)d_in[10];
    const float* s_be   = (const float*)d_in[11];
    const float* s_W2   = (const float*)d_in[12];
    const float* s_b2   = (const float*)d_in[13];
    const float* c_Wqk  = (const float*)d_in[14];
    const float* c_bqk  = (const float*)d_in[15];
    const float* c_Wv   = (const float*)d_in[16];
    const float* c_bv   = (const float*)d_in[17];
    const float* c_Wo   = (const float*)d_in[18];
    const float* c_bo   = (const float*)d_in[19];
    const float* c_W1   = (const float*)d_in[20];
    const float* c_b1   = (const float*)d_in[21];
    const float* c_g    = (const float*)d_in[22];
    const float* c_be   = (const float*)d_in[23];
    const float* c_W2   = (const float*)d_in[24];
    const float* c_b2   = (const float*)d_in[25];
    float* out = (float*)d_out;

    float *x,*qkv,*q,*k,*v,*sim,*ctx,*ctx2,*tmp,*msg,*cat,*hb;
    cudaGetSymbolAddress((void**)&x,   g_x);
    cudaGetSymbolAddress((void**)&qkv, g_qkv);
    cudaGetSymbolAddress((void**)&q,   g_q);
    cudaGetSymbolAddress((void**)&k,   g_k);
    cudaGetSymbolAddress((void**)&v,   g_v);
    cudaGetSymbolAddress((void**)&sim, g_sim);
    cudaGetSymbolAddress((void**)&ctx, g_ctx);
    cudaGetSymbolAddress((void**)&ctx2,g_ctx2);
    cudaGetSymbolAddress((void**)&tmp, g_tmp);
    cudaGetSymbolAddress((void**)&msg, g_msg);
    cudaGetSymbolAddress((void**)&cat, g_cat);
    cudaGetSymbolAddress((void**)&hb,  g_h);

    const size_t HS = (size_t)Nn*HDd;          // per-head stride 131072
    const size_t SS = (size_t)Nn*Nn;           // per-head sim stride
    float* sim2 = sim + 16*SS;                 // cross: P10 region (upper half)

    // linear: C(M x Nc) = A(M x K) @ W(Nc x K)^T + bias (+Res)
    auto NT = [&](const float* A,int lda,size_t sA,const float* W,int ldb,size_t sB,
                  float* C,int ldc,size_t sC,const float* bias,const float* Res,int ldr,
                  float scale,int M,int Nc,int K,int batch){
        dim3 gr(Nc/128, M/128, batch);
        gemm_k<128,128,8,8,8,false,true><<<gr,256>>>(A,lda,sA,W,ldb,sB,C,ldc,sC,bias,Res,ldr,scale,M,Nc,K);
    };
    auto NN64 = [&](const float* A,int lda,size_t sA,const float* Bm,int ldb,size_t sB,
                    float* C,int ldc,size_t sC,int M,int Nc,int K,int batch){
        dim3 gr(Nc/64, M/128, batch);
        gemm_k<128,64,8,8,4,false,false><<<gr,256>>>(A,lda,sA,Bm,ldb,sB,C,ldc,sC,nullptr,nullptr,0,1.0f,M,Nc,K);
    };
    auto TN64 = [&](const float* A,int lda,size_t sA,const float* Bm,int ldb,size_t sB,
                    float* C,int ldc,size_t sC,int M,int Nc,int K,int batch){
        dim3 gr(Nc/64, M/128, batch);
        gemm_k<128,64,8,8,4,true,false><<<gr,256>>>(A,lda,sA,Bm,ldb,sB,C,ldc,sC,nullptr,nullptr,0,1.0f,M,Nc,K);
    };

    // ======== SELF blocks (desc0 and desc1 concatenated, shared weights) ========
    cudaMemcpyAsync(x,       desc0, BND*sizeof(float), cudaMemcpyDeviceToDevice);
    cudaMemcpyAsync(x + BND, desc1, BND*sizeof(float), cudaMemcpyDeviceToDevice);

    // QKV
    NT(x,Dd,0, s_Wqkv,Dd,0, qkv,3*Dd,0, s_bqkv,nullptr,0, 1.0f, M2,3*Dd,Dd, 1);
    // split + RoPE
    {
        int total = 2*Bb*Hh*Nn*(HDd/2);
        qkv_rope_k<<<(total+255)/256,256>>>(qkv, enc0, enc1, q, k, v);
    }
    // sim = 0.125 * Q K^T   (32 batches)
    NT(q,HDd,HS, k,HDd,HS, sim,Nn,SS, nullptr,nullptr,0, 0.125f, Nn,Nn,HDd, 32);
    // softmax rows
    row_softmax_k<<<32*Nn,256>>>(sim);
    // ctx = P V
    NN64(sim,Nn,SS, v,HDd,HS, ctx,HDd,HS, Nn,HDd,Nn, 32);
    // unheads
    from_heads_k<<<(32*(int)HS+255)/256,256>>>(ctx, tmp, 32*(int)HS);
    // msg = ctx @ Wout^T + bout
    NT(tmp,Dd,0, s_Wout,Dd,0, msg,Dd,0, s_bout,nullptr,0, 1.0f, M2,Dd,Dd, 1);
    // cat = [x | msg]
    concat_k<<<(M2*2*Dd+255)/256,256>>>(x, msg, cat);
    // FFN
    NT(cat,2*Dd,0, s_W1,2*Dd,0, hb,2*Dd,0, s_b1,nullptr,0, 1.0f, M2,2*Dd,2*Dd, 1);
    ln_gelu_k<<<M2,256>>>(hb, s_g, s_be);
    NT(hb,2*Dd,0, s_W2,2*Dd,0, x,Dd,0, s_b2, x,Dd, 1.0f, M2,Dd,2*Dd, 1);  // x = x + ffn

    // ======== CROSS block ========
    // qk = x @ Wqk^T + bqk  -> heads (32 batches: s=0 first 16, s=1 next 16)
    NT(x,Dd,0, c_Wqk,Dd,0, tmp,Dd,0, c_bqk,nullptr,0, 1.0f, M2,Dd,Dd, 1);
    to_heads_k<<<(32*(int)HS+255)/256,256>>>(tmp, q, 32*(int)HS);
    // v = x @ Wv^T + bv -> heads
    NT(x,Dd,0, c_Wv,Dd,0, msg,Dd,0, c_bv,nullptr,0, 1.0f, M2,Dd,Dd, 1);
    to_heads_k<<<(32*(int)HS+255)/256,256>>>(msg, v, 32*(int)HS);
    // sim = 0.125 * qk0 qk1^T  (16 batches)  [s*s = HD^-0.5 folded in]
    NT(q,HDd,HS, q+16*HS,HDd,HS, sim,Nn,SS, nullptr,nullptr,0, 0.125f, Nn,Nn,HDd, 16);
    // P10 = colsoftmax(S) (must run BEFORE in-place row softmax)
    {
        dim3 gr(Nn/64, 16); dim3 bl(64,8);
        col_softmax_k<<<gr,bl>>>(sim, sim2);
    }
    // P01 = rowsoftmax(S) in place
    row_softmax_k<<<16*Nn,256>>>(sim);
    // m0 = P01 @ v1
    NN64(sim,Nn,SS, v+16*HS,HDd,HS, ctx,HDd,HS, Nn,HDd,Nn, 16);
    // m1[j,d] = sum_i P10[i,j] v0[i,d]  (A transposed)
    TN64(sim2,Nn,SS, v,HDd,HS, ctx2,HDd,HS, Nn,HDd,Nn, 16);
    // unheads: m0 -> rows of desc0, m1 -> rows of desc1
    from_heads_k<<<(16*(int)HS+255)/256,256>>>(ctx,  tmp,                    16*(int)HS);
    from_heads_k<<<(16*(int)HS+255)/256,256>>>(ctx2, tmp + (size_t)Bb*Nn*Dd, 16*(int)HS);
    // msg = m @ Wo^T + bo (both descriptors together)
    NT(tmp,Dd,0, c_Wo,Dd,0, msg,Dd,0, c_bo,nullptr,0, 1.0f, M2,Dd,Dd, 1);
    // cat = [x | msg]
    concat_k<<<(M2*2*Dd+255)/256,256>>>(x, msg, cat);
    // FFN -> out = x + ffn(cat)
    NT(cat,2*Dd,0, c_W1,2*Dd,0, hb,2*Dd,0, c_b1,nullptr,0, 1.0f, M2,2*Dd,2*Dd, 1);
    ln_gelu_k<<<M2,256>>>(hb, c_g, c_be);
    NT(hb,2*Dd,0, c_W2,2*Dd,0, out,Dd,0, c_b2, x,Dd, 1.0f, M2,Dd,2*Dd, 1);
}

// round 2
// speedup vs baseline: 1.3972x; 1.3972x over previous
#include <cuda_runtime.h>
#include <mma.h>
#include <math.h>
#include <stdint.h>

using namespace nvcuda;

#define Bb 4
#define Nn 2048
#define Dd 256
#define Hh 4
#define HDd 64
#define M2 (2*Bb*Nn)            // 16384 rows when desc0||desc1 concatenated
#define BND ((size_t)Bb*Nn*Dd)  // 2097152

// ---------------- static scratch (no cudaMalloc allowed) ----------------
__device__ float g_x  [(size_t)M2*Dd];
__device__ float g_qkv[(size_t)M2*3*Dd];
__device__ float g_q  [(size_t)2*Bb*Hh*Nn*HDd];
__device__ float g_k  [(size_t)2*Bb*Hh*Nn*HDd];
__device__ float g_v  [(size_t)2*Bb*Hh*Nn*HDd];
__device__ float g_sim[(size_t)2*Bb*Hh*Nn*Nn];  // self: 32 batches; cross: 16(S)+16(P10)
__device__ float g_ctx [(size_t)2*Bb*Hh*Nn*HDd];
__device__ float g_ctx2[(size_t)Bb*Hh*Nn*HDd];
__device__ float g_tmp[(size_t)M2*Dd];
__device__ float g_msg[(size_t)M2*Dd];
__device__ float g_cat[(size_t)M2*2*Dd];
__device__ float g_h  [(size_t)M2*2*Dd];

__device__ __forceinline__ float tf32r(float x){
    float y; asm("cvt.rna.tf32.f32 %0, %1;" : "=f"(y) : "f"(x)); return y;
}

// ---------------- TF32 tensor-core GEMM ----------------
// C[m][n] = scale * sum_k opA(A)[m][k] * opB(B)[k][n]  (+bias[n]) (+Res[m][n])
// AT=false: A[m*lda+k]   AT=true: A[k*lda+m]
// BT=false: B[k*ldb+n]   BT=true: B[n*ldb+k]  (W row-major, W^T applied)
// 256 threads = 8 warps in 4x2; warp tile 32 x (BN/2).
template<int BM,int BN,int BK,bool AT,bool BT>
__global__ void __launch_bounds__(256)
tgemm_k(const float* __restrict__ A, int lda, size_t sA,
        const float* __restrict__ Bm, int ldb, size_t sB,
        float* __restrict__ C, int ldc, size_t sC,
        const float* __restrict__ bias,
        const float* __restrict__ Res, int ldr,
        float scale, int K)
{
    constexpr int PAD = 8;
    constexpr int NTHR = 256;
    constexpr int WN = BN/2;
    constexpr int FN = WN/16;
    __shared__ float As[BK][BM+PAD];
    __shared__ float Bs[BK][BN+PAD];
    __shared__ float Ep[8][256];

    const int bz = blockIdx.z;
    A  += sA*(size_t)bz; Bm += sB*(size_t)bz; C += sC*(size_t)bz;
    const int bm = blockIdx.y*BM, bn = blockIdx.x*BN;
    const int tid = threadIdx.x;
    const int warp = tid>>5, lane = tid&31;
    const int wm = warp>>1, wn = warp&1;

    wmma::fragment<wmma::accumulator,16,16,8,float> acc[2][FN];
    #pragma unroll
    for (int i=0;i<2;i++)
        #pragma unroll
        for (int j=0;j<FN;j++) wmma::fill_fragment(acc[i][j], 0.0f);

    for (int k0=0;k0<K;k0+=BK) {
        if (!AT) {
            #pragma unroll
            for (int it=0; it<BM*BK/NTHR; it++) {
                int t = tid + it*NTHR;
                int k = t % BK, m = t / BK;
                As[k][m] = tf32r(A[(size_t)(bm+m)*lda + k0 + k]);
            }
        } else {
            #pragma unroll
            for (int it=0; it<BM*BK/NTHR; it++) {
                int t = tid + it*NTHR;
                int m = t % BM, k = t / BM;
                As[k][m] = tf32r(A[(size_t)(k0+k)*lda + bm + m]);
            }
        }
        if (BT) {
            #pragma unroll
            for (int it=0; it<BN*BK/NTHR; it++) {
                int t = tid + it*NTHR;
                int k = t % BK, n = t / BK;
                Bs[k][n] = tf32r(Bm[(size_t)(bn+n)*ldb + k0 + k]);
            }
        } else {
            #pragma unroll
            for (int it=0; it<BN*BK/NTHR; it++) {
                int t = tid + it*NTHR;
                int n = t % BN, k = t / BN;
                Bs[k][n] = tf32r(Bm[(size_t)(k0+k)*ldb + bn + n]);
            }
        }
        __syncthreads();
        #pragma unroll
        for (int ks=0;ks<BK;ks+=8) {
            wmma::fragment<wmma::matrix_a,16,16,8,wmma::precision::tf32,wmma::col_major> af[2];
            wmma::fragment<wmma::matrix_b,16,16,8,wmma::precision::tf32,wmma::row_major> bf[FN];
            #pragma unroll
            for (int i=0;i<2;i++)
                wmma::load_matrix_sync(af[i], &As[ks][wm*32 + i*16], BM+PAD);
            #pragma unroll
            for (int j=0;j<FN;j++)
                wmma::load_matrix_sync(bf[j], &Bs[ks][wn*WN + j*16], BN+PAD);
            #pragma unroll
            for (int i=0;i<2;i++)
                #pragma unroll
                for (int j=0;j<FN;j++)
                    wmma::mma_sync(acc[i][j], af[i], bf[j], acc[i][j]);
        }
        __syncthreads();
    }

    // epilogue: stage each 16x16 fragment through smem, fuse scale/bias/residual
    #pragma unroll
    for (int i=0;i<2;i++)
        #pragma unroll
        for (int j=0;j<FN;j++) {
            wmma::store_matrix_sync(Ep[warp], acc[i][j], 16, wmma::mem_row_major);
            __syncwarp();
            #pragma unroll
            for (int p=0;p<8;p++) {
                int idx = p*32 + lane;          // conflict-free, coalesced
                int r = idx >> 4, c = idx & 15;
                int gr = bm + wm*32 + i*16 + r;
                int gc = bn + wn*WN + j*16 + c;
                float v = Ep[warp][idx]*scale;
                if (bias) v += bias[gc];
                if (Res)  v += Res[(size_t)gr*ldr + gc];
                C[(size_t)gr*ldc + gc] = v;
            }
            __syncwarp();
        }
}

// ---------------- split QKV + RoPE into heads layout ----------------
__global__ void qkv_rope_k(const float* __restrict__ qkv,
                           const float* __restrict__ enc0,
                           const float* __restrict__ enc1,
                           float* __restrict__ Q, float* __restrict__ K,
                           float* __restrict__ V)
{
    int idx = blockIdx.x*blockDim.x + threadIdx.x;
    const int total = 2*Bb*Hh*Nn*(HDd/2);
    if (idx >= total) return;
    int p = idx % (HDd/2); int t = idx / (HDd/2);
    int n = t % Nn; t /= Nn;
    int h = t % Hh; t /= Hh;
    int b = t % Bb; int s = t / Bb;
    size_t r = (size_t)(s*Bb + b)*Nn + n;
    const float* row = qkv + r*(3*Dd);
    int d0 = 2*p, d1 = 2*p+1;
    float q0 = row[h*192 + d0*3 + 0], q1 = row[h*192 + d1*3 + 0];
    float k0 = row[h*192 + d0*3 + 1], k1 = row[h*192 + d1*3 + 1];
    float v0 = row[h*192 + d0*3 + 2], v1 = row[h*192 + d1*3 + 2];
    const float* enc = s ? enc1 : enc0;
    size_t eoff = ((size_t)b*Nn + n)*HDd;
    float c = enc[eoff + d0];
    float si = enc[(size_t)Bb*Nn*HDd + eoff + d0];
    float qo0 = q0*c - q1*si, qo1 = q1*c + q0*si;
    float ko0 = k0*c - k1*si, ko1 = k1*c + k0*si;
    size_t bh = (size_t)(s*Bb + b)*Hh + h;
    size_t o = (bh*Nn + n)*HDd;
    Q[o+d0]=qo0; Q[o+d1]=qo1;
    K[o+d0]=ko0; K[o+d1]=ko1;
    V[o+d0]=v0;  V[o+d1]=v1;
}

// ---------------- row softmax (in place) ----------------
__global__ void row_softmax_k(float* __restrict__ S)
{
    float* p = S + (size_t)blockIdx.x * Nn;
    int tid = threadIdx.x;
    float v[8];
    float m = -1e30f;
    #pragma unroll
    for (int i=0;i<8;i++){ v[i] = p[tid + i*256]; m = fmaxf(m, v[i]); }
    __shared__ float sm[8];
    #pragma unroll
    for (int o=16;o;o>>=1) m = fmaxf(m, __shfl_xor_sync(0xffffffffu, m, o));
    if ((tid&31)==0) sm[tid>>5] = m;
    __syncthreads();
    m = sm[0];
    #pragma unroll
    for (int t=1;t<8;t++) m = fmaxf(m, sm[t]);
    __syncthreads();
    float s = 0.f;
    #pragma unroll
    for (int i=0;i<8;i++){ v[i] = __expf(v[i]-m); s += v[i]; }
    #pragma unroll
    for (int o=16;o;o>>=1) s += __shfl_xor_sync(0xffffffffu, s, o);
    if ((tid&31)==0) sm[tid>>5] = s;
    __syncthreads();
    s = 0.f;
    #pragma unroll
    for (int t=0;t<8;t++) s += sm[t];
    float inv = 1.0f/s;
    #pragma unroll
    for (int i=0;i<8;i++) p[tid + i*256] = v[i]*inv;
}

// ---------------- column softmax ----------------
__global__ void col_softmax_k(const float* __restrict__ S, float* __restrict__ P)
{
    const size_t boff = (size_t)blockIdx.y * Nn * Nn;
    const float* Sb = S + boff;
    float* Pb = P + boff;
    int j = blockIdx.x*64 + threadIdx.x;
    int ty = threadIdx.y;
    __shared__ float red[8][64];
    float m = -1e30f;
    for (int i=ty;i<Nn;i+=8) m = fmaxf(m, Sb[(size_t)i*Nn + j]);
    red[ty][threadIdx.x] = m;
    __syncthreads();
    if (ty==0){ float mm=red[0][threadIdx.x];
        #pragma unroll
        for (int t=1;t<8;t++) mm=fmaxf(mm,red[t][threadIdx.x]);
        red[0][threadIdx.x]=mm; }
    __syncthreads();
    m = red[0][threadIdx.x];
    __syncthreads();
    float s = 0.f;
    for (int i=ty;i<Nn;i+=8) s += __expf(Sb[(size_t)i*Nn + j]-m);
    red[ty][threadIdx.x] = s;
    __syncthreads();
    if (ty==0){ float ss=0.f;
        #pragma unroll
        for (int t=0;t<8;t++) ss+=red[t][threadIdx.x];
        red[0][threadIdx.x]=ss; }
    __syncthreads();
    float inv = 1.0f/red[0][threadIdx.x];
    for (int i=ty;i<Nn;i+=8)
        Pb[(size_t)i*Nn + j] = __expf(Sb[(size_t)i*Nn + j]-m)*inv;
}

// ---------------- heads <-> flat ----------------
__global__ void from_heads_k(const float* __restrict__ in, float* __restrict__ out, int total)
{
    int idx = blockIdx.x*blockDim.x + threadIdx.x;
    if (idx >= total) return;
    int d = idx % HDd; int t = idx / HDd;
    int n = t % Nn; int bh = t / Nn;
    int sb = bh / Hh, h = bh % Hh;
    out[((size_t)sb*Nn + n)*Dd + h*HDd + d] = in[idx];
}
__global__ void to_heads_k(const float* __restrict__ in, float* __restrict__ out, int total)
{
    int idx = blockIdx.x*blockDim.x + threadIdx.x;
    if (idx >= total) return;
    int d = idx % HDd; int t = idx / HDd;
    int n = t % Nn; int bh = t / Nn;
    int sb = bh / Hh, h = bh % Hh;
    out[idx] = in[((size_t)sb*Nn + n)*Dd + h*HDd + d];
}

// copy x into left half of cat (float4)
__global__ void copy_left_k(const float* __restrict__ x, float* __restrict__ cat)
{
    int idx = blockIdx.x*blockDim.x + threadIdx.x;
    const int total = M2*(Dd/4);
    if (idx >= total) return;
    int c = idx % (Dd/4); int r = idx / (Dd/4);
    reinterpret_cast<float4*>(cat)[(size_t)r*(2*Dd/4) + c] =
        reinterpret_cast<const float4*>(x)[idx];
}

// ---------------- fused LayerNorm(512) + exact GELU ----------------
__global__ void ln_gelu_k(float* __restrict__ X, const float* __restrict__ g,
                          const float* __restrict__ be)
{
    float* p = X + (size_t)blockIdx.x * 512;
    int tid = threadIdx.x;
    float a = p[tid], b = p[tid+256];
    float s = a + b;
    float sq = a*a + b*b;
    #pragma unroll
    for (int o=16;o;o>>=1){ s += __shfl_xor_sync(0xffffffffu,s,o);
                            sq += __shfl_xor_sync(0xffffffffu,sq,o); }
    __shared__ float ss[8], sqs[8];
    if ((tid&31)==0){ ss[tid>>5]=s; sqs[tid>>5]=sq; }
    __syncthreads();
    s = 0.f; sq = 0.f;
    #pragma unroll
    for (int t=0;t<8;t++){ s+=ss[t]; sq+=sqs[t]; }
    float mean = s * (1.0f/512.0f);
    float var  = sq * (1.0f/512.0f) - mean*mean;
    float inv = rsqrtf(var + 1e-5f);
    float y0 = (a-mean)*inv*g[tid]     + be[tid];
    float y1 = (b-mean)*inv*g[tid+256] + be[tid+256];
    p[tid]     = 0.5f*y0*(1.0f+erff(y0*0.70710678118f));
    p[tid+256] = 0.5f*y1*(1.0f+erff(y1*0.70710678118f));
}

// ================= host orchestration =================
extern "C" void kernel_launch(void* const* d_in, const int* in_sizes, int n_in,
                              void* d_out, int out_size)
{
    const float* desc0  = (const float*)d_in[0];
    const float* desc1  = (const float*)d_in[1];
    const float* enc0   = (const float*)d_in[2];
    const float* enc1   = (const float*)d_in[3];
    const float* s_Wqkv = (const float*)d_in[4];
    const float* s_bqkv = (const float*)d_in[5];
    const float* s_Wout = (const float*)d_in[6];
    const float* s_bout = (const float*)d_in[7];
    const float* s_W1   = (const float*)d_in[8];
    const float* s_b1   = (const float*)d_in[9];
    const float* s_g    = (const float*)d_in[10];
    const float* s_be   = (const float*)d_in[11];
    const float* s_W2   = (const float*)d_in[12];
    const float* s_b2   = (const float*)d_in[13];
    const float* c_Wqk  = (const float*)d_in[14];
    const float* c_bqk  = (const float*)d_in[15];
    const float* c_Wv   = (const float*)d_in[16];
    const float* c_bv   = (const float*)d_in[17];
    const float* c_Wo   = (const float*)d_in[18];
    const float* c_bo   = (const float*)d_in[19];
    const float* c_W1   = (const float*)d_in[20];
    const float* c_b1   = (const float*)d_in[21];
    const float* c_g    = (const float*)d_in[22];
    const float* c_be   = (const float*)d_in[23];
    const float* c_W2   = (const float*)d_in[24];
    const float* c_b2   = (const float*)d_in[25];
    float* out = (float*)d_out;

    float *x,*qkv,*q,*k,*v,*sim,*ctx,*ctx2,*tmp,*msg,*cat,*hb;
    cudaGetSymbolAddress((void**)&x,   g_x);
    cudaGetSymbolAddress((void**)&qkv, g_qkv);
    cudaGetSymbolAddress((void**)&q,   g_q);
    cudaGetSymbolAddress((void**)&k,   g_k);
    cudaGetSymbolAddress((void**)&v,   g_v);
    cudaGetSymbolAddress((void**)&sim, g_sim);
    cudaGetSymbolAddress((void**)&ctx, g_ctx);
    cudaGetSymbolAddress((void**)&ctx2,g_ctx2);
    cudaGetSymbolAddress((void**)&tmp, g_tmp);
    cudaGetSymbolAddress((void**)&msg, g_msg);
    cudaGetSymbolAddress((void**)&cat, g_cat);
    cudaGetSymbolAddress((void**)&hb,  g_h);

    const size_t HS = (size_t)Nn*HDd;
    const size_t SS = (size_t)Nn*Nn;
    float* sim2 = sim + 16*SS;

    auto NT = [&](const float* A,int lda,size_t sA,const float* W,int ldb,size_t sB,
                  float* C,int ldc,size_t sC,const float* bias,const float* Res,int ldr,
                  float scale,int M,int Nc,int K,int batch){
        dim3 gr(Nc/128, M/128, batch);
        tgemm_k<128,128,16,false,true><<<gr,256>>>(A,lda,sA,W,ldb,sB,C,ldc,sC,bias,Res,ldr,scale,K);
    };
    auto NN64 = [&](const float* A,int lda,size_t sA,const float* Bm,int ldb,size_t sB,
                    float* C,int ldc,size_t sC,int M,int Nc,int K,int batch){
        dim3 gr(Nc/64, M/128, batch);
        tgemm_k<128,64,16,false,false><<<gr,256>>>(A,lda,sA,Bm,ldb,sB,C,ldc,sC,nullptr,nullptr,0,1.0f,K);
    };
    auto TN64 = [&](const float* A,int lda,size_t sA,const float* Bm,int ldb,size_t sB,
                    float* C,int ldc,size_t sC,int M,int Nc,int K,int batch){
        dim3 gr(Nc/64, M/128, batch);
        tgemm_k<128,64,16,true,false><<<gr,256>>>(A,lda,sA,Bm,ldb,sB,C,ldc,sC,nullptr,nullptr,0,1.0f,K);
    };

    // ======== SELF blocks (desc0||desc1, shared weights) ========
    cudaMemcpyAsync(x,       desc0, BND*sizeof(float), cudaMemcpyDeviceToDevice);
    cudaMemcpyAsync(x + BND, desc1, BND*sizeof(float), cudaMemcpyDeviceToDevice);

    NT(x,Dd,0, s_Wqkv,Dd,0, qkv,3*Dd,0, s_bqkv,nullptr,0, 1.0f, M2,3*Dd,Dd, 1);
    {
        int total = 2*Bb*Hh*Nn*(HDd/2);
        qkv_rope_k<<<(total+255)/256,256>>>(qkv, enc0, enc1, q, k, v);
    }
    NT(q,HDd,HS, k,HDd,HS, sim,Nn,SS, nullptr,nullptr,0, 0.125f, Nn,Nn,HDd, 32);
    row_softmax_k<<<32*Nn,256>>>(sim);
    NN64(sim,Nn,SS, v,HDd,HS, ctx,HDd,HS, Nn,HDd,Nn, 32);
    from_heads_k<<<(32*(int)HS+255)/256,256>>>(ctx, tmp, 32*(int)HS);
    // msg written directly into right half of cat
    NT(tmp,Dd,0, s_Wout,Dd,0, cat+Dd,2*Dd,0, s_bout,nullptr,0, 1.0f, M2,Dd,Dd, 1);
    copy_left_k<<<(M2*(Dd/4)+255)/256,256>>>(x, cat);
    NT(cat,2*Dd,0, s_W1,2*Dd,0, hb,2*Dd,0, s_b1,nullptr,0, 1.0f, M2,2*Dd,2*Dd, 1);
    ln_gelu_k<<<M2,256>>>(hb, s_g, s_be);
    NT(hb,2*Dd,0, s_W2,2*Dd,0, x,Dd,0, s_b2, x,Dd, 1.0f, M2,Dd,2*Dd, 1);

    // ======== CROSS block ========
    NT(x,Dd,0, c_Wqk,Dd,0, tmp,Dd,0, c_bqk,nullptr,0, 1.0f, M2,Dd,Dd, 1);
    to_heads_k<<<(32*(int)HS+255)/256,256>>>(tmp, q, 32*(int)HS);
    NT(x,Dd,0, c_Wv,Dd,0, msg,Dd,0, c_bv,nullptr,0, 1.0f, M2,Dd,Dd, 1);
    to_heads_k<<<(32*(int)HS+255)/256,256>>>(msg, v, 32*(int)HS);
    NT(q,HDd,HS, q+16*HS,HDd,HS, sim,Nn,SS, nullptr,nullptr,0, 0.125f, Nn,Nn,HDd, 16);
    {
        dim3 gr(Nn/64, 16); dim3 bl(64,8);
        col_softmax_k<<<gr,bl>>>(sim, sim2);
    }
    row_softmax_k<<<16*Nn,256>>>(sim);
    NN64(sim,Nn,SS, v+16*HS,HDd,HS, ctx,HDd,HS, Nn,HDd,Nn, 16);
    TN64(sim2,Nn,SS, v,HDd,HS, ctx2,HDd,HS, Nn,HDd,Nn, 16);
    from_heads_k<<<(16*(int)HS+255)/256,256>>>(ctx,  tmp,                    16*(int)HS);
    from_heads_k<<<(16*(int)HS+255)/256,256>>>(ctx2, tmp + (size_t)Bb*Nn*Dd, 16*(int)HS);
    NT(tmp,Dd,0, c_Wo,Dd,0, cat+Dd,2*Dd,0, c_bo,nullptr,0, 1.0f, M2,Dd,Dd, 1);
    copy_left_k<<<(M2*(Dd/4)+255)/256,256>>>(x, cat);
    NT(cat,2*Dd,0, c_W1,2*Dd,0, hb,2*Dd,0, c_b1,nullptr,0, 1.0f, M2,2*Dd,2*Dd, 1);
    ln_gelu_k<<<M2,256>>>(hb, c_g, c_be);
    NT(hb,2*Dd,0, c_W2,2*Dd,0, out,Dd,0, c_b2, x,Dd, 1.0f, M2,Dd,2*Dd, 1);
}

// round 3
// speedup vs baseline: 1.8844x; 1.3487x over previous
#include <cuda_runtime.h>
#include <mma.h>
#include <math.h>
#include <stdint.h>

using namespace nvcuda;

#define Bb 4
#define Nn 2048
#define Dd 256
#define Hh 4
#define HDd 64
#define M2 (2*Bb*Nn)
#define BND ((size_t)Bb*Nn*Dd)

// ---------------- static scratch ----------------
__device__ float g_x  [(size_t)M2*Dd];
__device__ float g_qkv[(size_t)M2*3*Dd];   // self: qkv output; cross: reused as ctx_flat
__device__ float g_q  [(size_t)2*Bb*Hh*Nn*HDd];
__device__ float g_k  [(size_t)2*Bb*Hh*Nn*HDd];
__device__ float g_v  [(size_t)2*Bb*Hh*Nn*HDd];
__device__ float g_tmp[(size_t)M2*Dd];
__device__ float g_msg[(size_t)M2*Dd];
__device__ float g_cat[(size_t)M2*2*Dd];
__device__ float g_h  [(size_t)M2*2*Dd];

__device__ __forceinline__ float tf32f(float x){
    float y; asm("cvt.rna.tf32.f32 %0, %1;" : "=f"(y) : "f"(x)); return y;
}

// ---------------- TF32 tensor-core GEMM (linear layers) ----------------
template<int BM,int BN,int BK,bool AT,bool BT>
__global__ void __launch_bounds__(256)
tgemm_k(const float* __restrict__ A, int lda, size_t sA,
        const float* __restrict__ Bm, int ldb, size_t sB,
        float* __restrict__ C, int ldc, size_t sC,
        const float* __restrict__ bias,
        const float* __restrict__ Res, int ldr,
        float scale, int K)
{
    constexpr int PAD = 8;
    constexpr int NTHR = 256;
    constexpr int WN = BN/2;
    constexpr int FN = WN/16;
    __shared__ float As[BK][BM+PAD];
    __shared__ float Bs[BK][BN+PAD];
    __shared__ float Ep[8][256];

    const int bz = blockIdx.z;
    A  += sA*(size_t)bz; Bm += sB*(size_t)bz; C += sC*(size_t)bz;
    const int bm = blockIdx.y*BM, bn = blockIdx.x*BN;
    const int tid = threadIdx.x;
    const int warp = tid>>5, lane = tid&31;
    const int wm = warp>>1, wn = warp&1;

    wmma::fragment<wmma::accumulator,16,16,8,float> acc[2][FN];
    #pragma unroll
    for (int i=0;i<2;i++)
        #pragma unroll
        for (int j=0;j<FN;j++) wmma::fill_fragment(acc[i][j], 0.0f);

    for (int k0=0;k0<K;k0+=BK) {
        if (!AT) {
            #pragma unroll
            for (int it=0; it<BM*BK/NTHR; it++) {
                int t = tid + it*NTHR;
                int k = t % BK, m = t / BK;
                As[k][m] = tf32f(A[(size_t)(bm+m)*lda + k0 + k]);
            }
        } else {
            #pragma unroll
            for (int it=0; it<BM*BK/NTHR; it++) {
                int t = tid + it*NTHR;
                int m = t % BM, k = t / BM;
                As[k][m] = tf32f(A[(size_t)(k0+k)*lda + bm + m]);
            }
        }
        if (BT) {
            #pragma unroll
            for (int it=0; it<BN*BK/NTHR; it++) {
                int t = tid + it*NTHR;
                int k = t % BK, n = t / BK;
                Bs[k][n] = tf32f(Bm[(size_t)(bn+n)*ldb + k0 + k]);
            }
        } else {
            #pragma unroll
            for (int it=0; it<BN*BK/NTHR; it++) {
                int t = tid + it*NTHR;
                int n = t % BN, k = t / BN;
                Bs[k][n] = tf32f(Bm[(size_t)(k0+k)*ldb + bn + n]);
            }
        }
        __syncthreads();
        #pragma unroll
        for (int ks=0;ks<BK;ks+=8) {
            wmma::fragment<wmma::matrix_a,16,16,8,wmma::precision::tf32,wmma::col_major> af[2];
            wmma::fragment<wmma::matrix_b,16,16,8,wmma::precision::tf32,wmma::row_major> bf[FN];
            #pragma unroll
            for (int i=0;i<2;i++)
                wmma::load_matrix_sync(af[i], &As[ks][wm*32 + i*16], BM+PAD);
            #pragma unroll
            for (int j=0;j<FN;j++)
                wmma::load_matrix_sync(bf[j], &Bs[ks][wn*WN + j*16], BN+PAD);
            #pragma unroll
            for (int i=0;i<2;i++)
                #pragma unroll
                for (int j=0;j<FN;j++)
                    wmma::mma_sync(acc[i][j], af[i], bf[j], acc[i][j]);
        }
        __syncthreads();
    }

    #pragma unroll
    for (int i=0;i<2;i++)
        #pragma unroll
        for (int j=0;j<FN;j++) {
            wmma::store_matrix_sync(Ep[warp], acc[i][j], 16, wmma::mem_row_major);
            __syncwarp();
            #pragma unroll
            for (int p=0;p<8;p++) {
                int idx = p*32 + lane;
                int r = idx >> 4, c = idx & 15;
                int gr = bm + wm*32 + i*16 + r;
                int gc = bn + wn*WN + j*16 + c;
                float v = Ep[warp][idx]*scale;
                if (bias) v += bias[gc];
                if (Res)  v += Res[(size_t)gr*ldr + gc];
                C[(size_t)gr*ldc + gc] = v;
            }
            __syncwarp();
        }
}

// ---------------- mma.sync m16n8k8 tf32 ----------------
__device__ __forceinline__ void mma_tf32(float* c, const float* a, const float* b){
    asm volatile(
      "mma.sync.aligned.m16n8k8.row.col.f32.tf32.tf32.f32 "
      "{%0,%1,%2,%3},{%4,%5,%6,%7},{%8,%9},{%0,%1,%2,%3};\n"
      : "+f"(c[0]),"+f"(c[1]),"+f"(c[2]),"+f"(c[3])
      : "r"(__float_as_uint(a[0])),"r"(__float_as_uint(a[1])),
        "r"(__float_as_uint(a[2])),"r"(__float_as_uint(a[3])),
        "r"(__float_as_uint(b[0])),"r"(__float_as_uint(b[1])));
}

// ---------------- flash attention (HD=64, N=2048) ----------------
// BM=128 q-rows per block, BN=64 k-cols per tile, 8 warps x 16 rows.
// qheads/kvheads: 1 = heads layout [z][n][64] (row stride 64),
//                 0 = flat layout  [(z>>2)*N + n][256] + (z&3)*64 (row stride 256)
// Output always flat. scale 0.125 folded into Q.
#define QP_LD 68
#define KS_LD 68
#define VT_LD 65
#define FA_SMEM ((128*QP_LD + 64*KS_LD + 64*VT_LD)*4)

__global__ void __launch_bounds__(256)
flash_k(const float* __restrict__ Qb, const float* __restrict__ Kb,
        const float* __restrict__ Vb, float* __restrict__ Ob,
        int qheads, int kvheads)
{
    extern __shared__ float smf[];
    float* QP = smf;                        // [128][QP_LD] : Q, then P
    float* Ks = smf + 128*QP_LD;            // [64][KS_LD]
    float* Vt = Ks + 64*KS_LD;              // [64][VT_LD]  (transposed V)

    const int z = blockIdx.y, it = blockIdx.x;
    const int tid = threadIdx.x, warp = tid>>5, lane = tid&31;
    const int gq = lane>>2, tq = lane&3;

    size_t qoff, kvoff;
    int qld, kld;
    if (qheads){ qoff = (size_t)z*Nn*HDd; qld = HDd; }
    else       { qoff = (size_t)(z>>2)*Nn*Dd + (size_t)(z&3)*HDd; qld = Dd; }
    if (kvheads){ kvoff = (size_t)z*Nn*HDd; kld = HDd; }
    else        { kvoff = (size_t)(z>>2)*Nn*Dd + (size_t)(z&3)*HDd; kld = Dd; }
    const size_t ooff = (size_t)(z>>2)*Nn*Dd + (size_t)(z&3)*HDd;

    const float* Q = Qb + qoff + (size_t)it*128*qld;
    const float* K = Kb + kvoff;
    const float* V = Vb + kvoff;
    float* O = Ob + ooff + (size_t)it*128*Dd;

    // stage Q (scaled by 0.125, tf32-rounded)
    #pragma unroll
    for (int r=0;r<8;r++){
        int idx = tid + r*256;
        int row = idx>>4, c4 = idx&15;
        float4 qv = *reinterpret_cast<const float4*>(Q + (size_t)row*qld + c4*4);
        QP[row*QP_LD + c4*4+0] = tf32f(qv.x*0.125f);
        QP[row*QP_LD + c4*4+1] = tf32f(qv.y*0.125f);
        QP[row*QP_LD + c4*4+2] = tf32f(qv.z*0.125f);
        QP[row*QP_LD + c4*4+3] = tf32f(qv.w*0.125f);
    }
    __syncthreads();

    // load Q a-fragments to registers (kept across whole j loop)
    float aq[8][4];
    const int r0 = warp*16 + gq;
    #pragma unroll
    for (int kk=0;kk<8;kk++){
        aq[kk][0] = QP[ r0   *QP_LD + kk*8 + tq];
        aq[kk][1] = QP[(r0+8)*QP_LD + kk*8 + tq];
        aq[kk][2] = QP[ r0   *QP_LD + kk*8 + tq + 4];
        aq[kk][3] = QP[(r0+8)*QP_LD + kk*8 + tq + 4];
    }

    float o[8][4];
    #pragma unroll
    for (int i=0;i<8;i++){ o[i][0]=0.f;o[i][1]=0.f;o[i][2]=0.f;o[i][3]=0.f; }
    float m0=-1e30f, m1=-1e30f, l0=0.f, l1=0.f;

    for (int j0=0;j0<Nn;j0+=64){
        __syncthreads();   // previous tile's Ks/Vt reads + Q reads done
        // stage K [64][64] (natural layout serves as col-major B)
        #pragma unroll
        for (int r=0;r<4;r++){
            int idx = tid + r*256;
            int row = idx>>4, c4 = idx&15;
            float4 kv = *reinterpret_cast<const float4*>(K + (size_t)(j0+row)*kld + c4*4);
            Ks[row*KS_LD + c4*4+0] = tf32f(kv.x);
            Ks[row*KS_LD + c4*4+1] = tf32f(kv.y);
            Ks[row*KS_LD + c4*4+2] = tf32f(kv.z);
            Ks[row*KS_LD + c4*4+3] = tf32f(kv.w);
        }
        // stage V transposed: Vt[d][j]
        #pragma unroll
        for (int r=0;r<16;r++){
            int idx = tid + r*256;
            int row = idx>>6, d = idx&63;
            Vt[d*VT_LD + row] = tf32f(V[(size_t)(j0+row)*kld + d]);
        }
        __syncthreads();

        // S = (Q*scale) K^T
        float c[8][4];
        #pragma unroll
        for (int nf=0;nf<8;nf++){
            c[nf][0]=0.f;c[nf][1]=0.f;c[nf][2]=0.f;c[nf][3]=0.f;
            #pragma unroll
            for (int kk=0;kk<8;kk++){
                float b[2];
                b[0] = Ks[(nf*8+gq)*KS_LD + kk*8 + tq];
                b[1] = Ks[(nf*8+gq)*KS_LD + kk*8 + tq + 4];
                mma_tf32(c[nf], aq[kk], b);
            }
        }
        // online softmax (rows r0 and r0+8)
        float mx0=-1e30f, mx1=-1e30f;
        #pragma unroll
        for (int nf=0;nf<8;nf++){
            mx0 = fmaxf(mx0, fmaxf(c[nf][0], c[nf][1]));
            mx1 = fmaxf(mx1, fmaxf(c[nf][2], c[nf][3]));
        }
        mx0 = fmaxf(mx0, __shfl_xor_sync(0xffffffffu, mx0, 1));
        mx0 = fmaxf(mx0, __shfl_xor_sync(0xffffffffu, mx0, 2));
        mx1 = fmaxf(mx1, __shfl_xor_sync(0xffffffffu, mx1, 1));
        mx1 = fmaxf(mx1, __shfl_xor_sync(0xffffffffu, mx1, 2));
        float nm0 = fmaxf(m0, mx0), nm1 = fmaxf(m1, mx1);
        float al0 = __expf(m0-nm0), al1 = __expf(m1-nm1);
        float s0=0.f, s1=0.f;
        #pragma unroll
        for (int nf=0;nf<8;nf++){
            c[nf][0]=__expf(c[nf][0]-nm0); c[nf][1]=__expf(c[nf][1]-nm0);
            c[nf][2]=__expf(c[nf][2]-nm1); c[nf][3]=__expf(c[nf][3]-nm1);
            s0 += c[nf][0]+c[nf][1]; s1 += c[nf][2]+c[nf][3];
        }
        s0 += __shfl_xor_sync(0xffffffffu, s0, 1);
        s0 += __shfl_xor_sync(0xffffffffu, s0, 2);
        s1 += __shfl_xor_sync(0xffffffffu, s1, 1);
        s1 += __shfl_xor_sync(0xffffffffu, s1, 2);
        l0 = l0*al0 + s0; l1 = l1*al1 + s1;
        m0 = nm0; m1 = nm1;
        #pragma unroll
        for (int nd=0;nd<8;nd++){
            o[nd][0]*=al0; o[nd][1]*=al0; o[nd][2]*=al1; o[nd][3]*=al1;
        }
        // P -> smem (warp-local region of QP)
        #pragma unroll
        for (int nf=0;nf<8;nf++){
            QP[ r0   *QP_LD + nf*8 + 2*tq  ] = tf32f(c[nf][0]);
            QP[ r0   *QP_LD + nf*8 + 2*tq+1] = tf32f(c[nf][1]);
            QP[(r0+8)*QP_LD + nf*8 + 2*tq  ] = tf32f(c[nf][2]);
            QP[(r0+8)*QP_LD + nf*8 + 2*tq+1] = tf32f(c[nf][3]);
        }
        __syncwarp();
        // O += P V
        #pragma unroll
        for (int kk=0;kk<8;kk++){
            float ap[4];
            ap[0] = QP[ r0   *QP_LD + kk*8 + tq];
            ap[1] = QP[(r0+8)*QP_LD + kk*8 + tq];
            ap[2] = QP[ r0   *QP_LD + kk*8 + tq + 4];
            ap[3] = QP[(r0+8)*QP_LD + kk*8 + tq + 4];
            #pragma unroll
            for (int nd=0;nd<8;nd++){
                float b[2];
                b[0] = Vt[(nd*8+gq)*VT_LD + kk*8 + tq];
                b[1] = Vt[(nd*8+gq)*VT_LD + kk*8 + tq + 4];
                mma_tf32(o[nd], ap, b);
            }
        }
    }

    const float inv0 = 1.f/l0, inv1 = 1.f/l1;
    #pragma unroll
    for (int nd=0;nd<8;nd++){
        float2 w0; w0.x = o[nd][0]*inv0; w0.y = o[nd][1]*inv0;
        float2 w1; w1.x = o[nd][2]*inv1; w1.y = o[nd][3]*inv1;
        *reinterpret_cast<float2*>(O + (size_t) r0   *Dd + nd*8 + 2*tq) = w0;
        *reinterpret_cast<float2*>(O + (size_t)(r0+8)*Dd + nd*8 + 2*tq) = w1;
    }
}

// ---------------- split QKV + RoPE into heads layout ----------------
__global__ void qkv_rope_k(const float* __restrict__ qkv,
                           const float* __restrict__ enc0,
                           const float* __restrict__ enc1,
                           float* __restrict__ Q, float* __restrict__ K,
                           float* __restrict__ V)
{
    int idx = blockIdx.x*blockDim.x + threadIdx.x;
    const int total = 2*Bb*Hh*Nn*(HDd/2);
    if (idx >= total) return;
    int p = idx % (HDd/2); int t = idx / (HDd/2);
    int n = t % Nn; t /= Nn;
    int h = t % Hh; t /= Hh;
    int b = t % Bb; int s = t / Bb;
    size_t r = (size_t)(s*Bb + b)*Nn + n;
    const float* row = qkv + r*(3*Dd);
    int d0 = 2*p, d1 = 2*p+1;
    float q0 = row[h*192 + d0*3 + 0], q1 = row[h*192 + d1*3 + 0];
    float k0 = row[h*192 + d0*3 + 1], k1 = row[h*192 + d1*3 + 1];
    float v0 = row[h*192 + d0*3 + 2], v1 = row[h*192 + d1*3 + 2];
    const float* enc = s ? enc1 : enc0;
    size_t eoff = ((size_t)b*Nn + n)*HDd;
    float c = enc[eoff + d0];
    float si = enc[(size_t)Bb*Nn*HDd + eoff + d0];
    float qo0 = q0*c - q1*si, qo1 = q1*c + q0*si;
    float ko0 = k0*c - k1*si, ko1 = k1*c + k0*si;
    size_t bh = (size_t)(s*Bb + b)*Hh + h;
    size_t o = (bh*Nn + n)*HDd;
    Q[o+d0]=qo0; Q[o+d1]=qo1;
    K[o+d0]=ko0; K[o+d1]=ko1;
    V[o+d0]=v0;  V[o+d1]=v1;
}

// copy x into left half of cat (float4)
__global__ void copy_left_k(const float* __restrict__ x, float* __restrict__ cat)
{
    int idx = blockIdx.x*blockDim.x + threadIdx.x;
    const int total = M2*(Dd/4);
    if (idx >= total) return;
    int c = idx % (Dd/4); int r = idx / (Dd/4);
    reinterpret_cast<float4*>(cat)[(size_t)r*(2*Dd/4) + c] =
        reinterpret_cast<const float4*>(x)[idx];
}

// ---------------- fused LayerNorm(512) + exact GELU ----------------
__global__ void ln_gelu_k(float* __restrict__ X, const float* __restrict__ g,
                          const float* __restrict__ be)
{
    float* p = X + (size_t)blockIdx.x * 512;
    int tid = threadIdx.x;
    float a = p[tid], b = p[tid+256];
    float s = a + b;
    float sq = a*a + b*b;
    #pragma unroll
    for (int o=16;o;o>>=1){ s += __shfl_xor_sync(0xffffffffu,s,o);
                            sq += __shfl_xor_sync(0xffffffffu,sq,o); }
    __shared__ float ss[8], sqs[8];
    if ((tid&31)==0){ ss[tid>>5]=s; sqs[tid>>5]=sq; }
    __syncthreads();
    s = 0.f; sq = 0.f;
    #pragma unroll
    for (int t=0;t<8;t++){ s+=ss[t]; sq+=sqs[t]; }
    float mean = s * (1.0f/512.0f);
    float var  = sq * (1.0f/512.0f) - mean*mean;
    float inv = rsqrtf(var + 1e-5f);
    float y0 = (a-mean)*inv*g[tid]     + be[tid];
    float y1 = (b-mean)*inv*g[tid+256] + be[tid+256];
    p[tid]     = 0.5f*y0*(1.0f+erff(y0*0.70710678118f));
    p[tid+256] = 0.5f*y1*(1.0f+erff(y1*0.70710678118f));
}

// ================= host orchestration =================
extern "C" void kernel_launch(void* const* d_in, const int* in_sizes, int n_in,
                              void* d_out, int out_size)
{
    const float* desc0  = (const float*)d_in[0];
    const float* desc1  = (const float*)d_in[1];
    const float* enc0   = (const float*)d_in[2];
    const float* enc1   = (const float*)d_in[3];
    const float* s_Wqkv = (const float*)d_in[4];
    const float* s_bqkv = (const float*)d_in[5];
    const float* s_Wout = (const float*)d_in[6];
    const float* s_bout = (const float*)d_in[7];
    const float* s_W1   = (const float*)d_in[8];
    const float* s_b1   = (const float*)d_in[9];
    const float* s_g    = (const float*)d_in[10];
    const float* s_be   = (const float*)d_in[11];
    const float* s_W2   = (const float*)d_in[12];
    const float* s_b2   = (const float*)d_in[13];
    const float* c_Wqk  = (const float*)d_in[14];
    const float* c_bqk  = (const float*)d_in[15];
    const float* c_Wv   = (const float*)d_in[16];
    const float* c_bv   = (const float*)d_in[17];
    const float* c_Wo   = (const float*)d_in[18];
    const float* c_bo   = (const float*)d_in[19];
    const float* c_W1   = (const float*)d_in[20];
    const float* c_b1   = (const float*)d_in[21];
    const float* c_g    = (const float*)d_in[22];
    const float* c_be   = (const float*)d_in[23];
    const float* c_W2   = (const float*)d_in[24];
    const float* c_b2   = (const float*)d_in[25];
    float* out = (float*)d_out;

    float *x,*qkv,*q,*k,*v,*tmp,*msg,*cat,*hb;
    cudaGetSymbolAddress((void**)&x,   g_x);
    cudaGetSymbolAddress((void**)&qkv, g_qkv);
    cudaGetSymbolAddress((void**)&q,   g_q);
    cudaGetSymbolAddress((void**)&k,   g_k);
    cudaGetSymbolAddress((void**)&v,   g_v);
    cudaGetSymbolAddress((void**)&tmp, g_tmp);
    cudaGetSymbolAddress((void**)&msg, g_msg);
    cudaGetSymbolAddress((void**)&cat, g_cat);
    cudaGetSymbolAddress((void**)&hb,  g_h);

    cudaFuncSetAttribute(flash_k, cudaFuncAttributeMaxDynamicSharedMemorySize, FA_SMEM);

    auto NT = [&](const float* A,int lda,const float* W,int ldb,
                  float* C,int ldc,const float* bias,const float* Res,int ldr,
                  int M,int Nc,int K){
        dim3 gr(Nc/128, M/128, 1);
        tgemm_k<128,128,16,false,true><<<gr,256>>>(A,lda,0,W,ldb,0,C,ldc,0,bias,Res,ldr,1.0f,K);
    };

    // ======== SELF blocks (desc0||desc1, shared weights) ========
    cudaMemcpyAsync(x,       desc0, BND*sizeof(float), cudaMemcpyDeviceToDevice);
    cudaMemcpyAsync(x + BND, desc1, BND*sizeof(float), cudaMemcpyDeviceToDevice);

    NT(x,Dd, s_Wqkv,Dd, qkv,3*Dd, s_bqkv,nullptr,0, M2,3*Dd,Dd);
    {
        int total = 2*Bb*Hh*Nn*(HDd/2);
        qkv_rope_k<<<(total+255)/256,256>>>(qkv, enc0, enc1, q, k, v);
    }
    {   // flash self attention -> tmp (flat layout, both descriptors)
        dim3 gr(Nn/128, 2*Bb*Hh);
        flash_k<<<gr,256,FA_SMEM>>>(q, k, v, tmp, 1, 1);
    }
    NT(tmp,Dd, s_Wout,Dd, cat+Dd,2*Dd, s_bout,nullptr,0, M2,Dd,Dd);
    copy_left_k<<<(M2*(Dd/4)+255)/256,256>>>(x, cat);
    NT(cat,2*Dd, s_W1,2*Dd, hb,2*Dd, s_b1,nullptr,0, M2,2*Dd,2*Dd);
    ln_gelu_k<<<M2,256>>>(hb, s_g, s_be);
    NT(hb,2*Dd, s_W2,2*Dd, x,Dd, s_b2, x,Dd, M2,Dd,2*Dd);

    // ======== CROSS block ========
    NT(x,Dd, c_Wqk,Dd, tmp,Dd, c_bqk,nullptr,0, M2,Dd,Dd);   // qk (flat)
    NT(x,Dd, c_Wv, Dd, msg,Dd, c_bv, nullptr,0, M2,Dd,Dd);   // v  (flat)
    {   // m0 = attn(q=qk0, k=qk1, v=v1) ; m1 = attn(q=qk1, k=qk0, v=v0)
        dim3 gr(Nn/128, Bb*Hh);
        flash_k<<<gr,256,FA_SMEM>>>(tmp,     tmp+BND, msg+BND, qkv,     0, 0);
        flash_k<<<gr,256,FA_SMEM>>>(tmp+BND, tmp,     msg,     qkv+BND, 0, 0);
    }
    NT(qkv,Dd, c_Wo,Dd, cat+Dd,2*Dd, c_bo,nullptr,0, M2,Dd,Dd);
    copy_left_k<<<(M2*(Dd/4)+255)/256,256>>>(x, cat);
    NT(cat,2*Dd, c_W1,2*Dd, hb,2*Dd, c_b1,nullptr,0, M2,2*Dd,2*Dd);
    ln_gelu_k<<<M2,256>>>(hb, c_g, c_be);
    NT(hb,2*Dd, c_W2,2*Dd, out,Dd, c_b2, x,Dd, M2,Dd,2*Dd);
}

// round 4
// speedup vs baseline: 2.7246x; 1.4459x over previous
#include <cuda_runtime.h>
#include <mma.h>
#include <math.h>
#include <stdint.h>

using namespace nvcuda;

#define Bb 4
#define Nn 2048
#define Dd 256
#define Hh 4
#define HDd 64
#define M2 (2*Bb*Nn)
#define BND ((size_t)Bb*Nn*Dd)

// ---------------- static scratch ----------------
__device__ float g_x  [(size_t)M2*Dd];
__device__ float g_qkv[(size_t)M2*3*Dd];   // self: qkv output; cross: ctx_flat
__device__ float g_q  [(size_t)2*Bb*Hh*Nn*HDd];
__device__ float g_k  [(size_t)2*Bb*Hh*Nn*HDd];
__device__ float g_v  [(size_t)2*Bb*Hh*Nn*HDd];
__device__ float g_tmp[(size_t)M2*Dd];
__device__ float g_msg[(size_t)M2*Dd];
__device__ float g_cat[(size_t)M2*2*Dd];
__device__ float g_h  [(size_t)M2*2*Dd];

__device__ __forceinline__ float tf32f(float x){
    float y; asm("cvt.rna.tf32.f32 %0, %1;" : "=f"(y) : "f"(x)); return y;
}

// ---------------- cp.async helpers ----------------
__device__ __forceinline__ void cpa16(void* s, const void* g){
    uint32_t sa = (uint32_t)__cvta_generic_to_shared(s);
    asm volatile("cp.async.cg.shared.global [%0], [%1], 16;\n" :: "r"(sa), "l"(g));
}
__device__ __forceinline__ void cpa_commit(){ asm volatile("cp.async.commit_group;\n"); }
template<int N> __device__ __forceinline__ void cpa_wait(){
    asm volatile("cp.async.wait_group %0;\n" :: "n"(N));
}

// ---------------- NT tf32 GEMM, cp.async double-buffered ----------------
// C[m][n] = sum_k A[m][k] * W[n][k]  (+bias[n]) (+Res[m][n])
#define GLD 20   // 16 + pad 4 (keeps rows 16B-aligned for cp.async)
__global__ void __launch_bounds__(256,2)
tgemm_nt(const float* __restrict__ A, int lda,
         const float* __restrict__ W, int ldb,
         float* __restrict__ C, int ldc,
         const float* __restrict__ bias,
         const float* __restrict__ Res, int ldr, int K)
{
    __shared__ float As[2][128][GLD];
    __shared__ float Bs[2][128][GLD];
    const int bm = blockIdx.y*128, bn = blockIdx.x*128;
    const int tid = threadIdx.x, warp = tid>>5, lane = tid&31;
    const int wm = warp>>1, wn = warp&1;

    wmma::fragment<wmma::accumulator,16,16,8,float> acc[2][4];
    #pragma unroll
    for (int i=0;i<2;i++)
        #pragma unroll
        for (int j=0;j<4;j++) wmma::fill_fragment(acc[i][j], 0.0f);

    const int row_l = tid>>2, col_l = (tid&3)*4;
    const int row_h = (tid+256)>>2, col_h = ((tid+256)&3)*4;

    // prologue
    {
        cpa16(&As[0][row_l][col_l], A + (size_t)(bm+row_l)*lda + col_l);
        cpa16(&As[0][row_h][col_h], A + (size_t)(bm+row_h)*lda + col_h);
        cpa16(&Bs[0][row_l][col_l], W + (size_t)(bn+row_l)*ldb + col_l);
        cpa16(&Bs[0][row_h][col_h], W + (size_t)(bn+row_h)*ldb + col_h);
        cpa_commit();
    }

    const int KT = K/16;
    for (int kt=0; kt<KT; kt++){
        const int buf = kt&1;
        if (kt+1 < KT){
            const int k0 = (kt+1)*16, nb = buf^1;
            cpa16(&As[nb][row_l][col_l], A + (size_t)(bm+row_l)*lda + k0 + col_l);
            cpa16(&As[nb][row_h][col_h], A + (size_t)(bm+row_h)*lda + k0 + col_h);
            cpa16(&Bs[nb][row_l][col_l], W + (size_t)(bn+row_l)*ldb + k0 + col_l);
            cpa16(&Bs[nb][row_h][col_h], W + (size_t)(bn+row_h)*ldb + k0 + col_h);
            cpa_commit();
            cpa_wait<1>();
        } else {
            cpa_wait<0>();
        }
        __syncthreads();
        #pragma unroll
        for (int ks=0; ks<16; ks+=8){
            wmma::fragment<wmma::matrix_a,16,16,8,wmma::precision::tf32,wmma::row_major> af[2];
            wmma::fragment<wmma::matrix_b,16,16,8,wmma::precision::tf32,wmma::col_major> bf[4];
            #pragma unroll
            for (int i=0;i<2;i++){
                wmma::load_matrix_sync(af[i], &As[buf][wm*32 + i*16][ks], GLD);
                #pragma unroll
                for (int e=0;e<af[i].num_elements;e++) af[i].x[e] = tf32f(af[i].x[e]);
            }
            #pragma unroll
            for (int j=0;j<4;j++){
                wmma::load_matrix_sync(bf[j], &Bs[buf][wn*64 + j*16][ks], GLD);
                #pragma unroll
                for (int e=0;e<bf[j].num_elements;e++) bf[j].x[e] = tf32f(bf[j].x[e]);
            }
            #pragma unroll
            for (int i=0;i<2;i++)
                #pragma unroll
                for (int j=0;j<4;j++)
                    wmma::mma_sync(acc[i][j], af[i], bf[j], acc[i][j]);
        }
        __syncthreads();
    }

    // epilogue through reused As smem
    float* Ep = &As[0][0][0] + warp*256;
    #pragma unroll
    for (int i=0;i<2;i++)
        #pragma unroll
        for (int j=0;j<4;j++){
            wmma::store_matrix_sync(Ep, acc[i][j], 16, wmma::mem_row_major);
            __syncwarp();
            #pragma unroll
            for (int p=0;p<8;p++){
                int idx = p*32 + lane;
                int r = idx>>4, c = idx&15;
                int gr = bm + wm*32 + i*16 + r;
                int gc = bn + wn*64 + j*16 + c;
                float v = Ep[idx];
                if (bias) v += bias[gc];
                if (Res)  v += Res[(size_t)gr*ldr + gc];
                C[(size_t)gr*ldc + gc] = v;
            }
            __syncwarp();
        }
}

// ---------------- mma.sync m16n8k8 tf32 ----------------
__device__ __forceinline__ void mma_tf32(float* c, const float* a, const float* b){
    asm volatile(
      "mma.sync.aligned.m16n8k8.row.col.f32.tf32.tf32.f32 "
      "{%0,%1,%2,%3},{%4,%5,%6,%7},{%8,%9},{%0,%1,%2,%3};\n"
      : "+f"(c[0]),"+f"(c[1]),"+f"(c[2]),"+f"(c[3])
      : "r"(__float_as_uint(a[0])),"r"(__float_as_uint(a[1])),
        "r"(__float_as_uint(a[2])),"r"(__float_as_uint(a[3])),
        "r"(__float_as_uint(b[0])),"r"(__float_as_uint(b[1])));
}

// ---------------- flash attention (HD=64, N=2048), cp.async pipelined ----------------
// mode 0: self — Q/K/V in heads layout [z][n][64], O flat. 32 z.
// mode 1: cross — flat layout; z<16: (q0 -> kv1), z>=16: (q1 -> kv0). 32 z.
#define QP_LD 68
#define KV_LD 68
#define FA_SMEM ((128*QP_LD + 2*64*KV_LD + 2*64*KV_LD)*4)

__global__ void __launch_bounds__(256)
flash_k(const float* __restrict__ Qb, const float* __restrict__ Kb,
        const float* __restrict__ Vb, float* __restrict__ Ob, int mode)
{
    extern __shared__ float smf[];
    float* QP = smf;                           // [128][QP_LD] : Q then P
    float* Ks = smf + 128*QP_LD;               // [2][64][KV_LD]
    float* Vs = Ks + 2*64*KV_LD;               // [2][64][KV_LD]

    const int z = blockIdx.y, it = blockIdx.x;
    const int tid = threadIdx.x, warp = tid>>5, lane = tid&31;
    const int gq = lane>>2, tq = lane&3;

    size_t qoff, kvoff, ooff;
    int qld, kld;
    if (mode == 0){
        qoff = (size_t)z*Nn*HDd; kvoff = qoff;
        ooff = (size_t)(z>>2)*Nn*Dd + (size_t)(z&3)*HDd;
        qld = HDd; kld = HDd;
    } else {
        int h = z>>4, zz = z&15;
        size_t f = (size_t)(zz>>2)*Nn*Dd + (size_t)(zz&3)*HDd;
        qoff  = (size_t)h*BND + f;
        kvoff = (size_t)(1-h)*BND + f;
        ooff  = (size_t)h*BND + f;
        qld = Dd; kld = Dd;
    }

    const float* Q = Qb + qoff + (size_t)it*128*qld;
    const float* K = Kb + kvoff;
    const float* V = Vb + kvoff;
    float* O = Ob + ooff + (size_t)it*128*Dd;

    // K/V tile loader: 64 rows x 64 floats each, raw cp.async
    const int kr = tid>>4, kc = (tid&15)*4;   // 256 threads cover 4 rows-chunks each
    auto load_kv = [&](int buf, int j0){
        #pragma unroll
        for (int itr=0; itr<4; itr++){
            int row = kr + itr*16;
            cpa16(Ks + ((size_t)buf*64 + row)*KV_LD + kc, K + (size_t)(j0+row)*kld + kc);
        }
        #pragma unroll
        for (int itr=0; itr<4; itr++){
            int row = kr + itr*16;
            cpa16(Vs + ((size_t)buf*64 + row)*KV_LD + kc, V + (size_t)(j0+row)*kld + kc);
        }
        cpa_commit();
    };

    load_kv(0, 0);   // prefetch tile 0 immediately

    // stage Q (scaled, tf32-rounded)
    #pragma unroll
    for (int r=0;r<8;r++){
        int idx = tid + r*256;
        int row = idx>>4, c4 = idx&15;
        float4 qv = *reinterpret_cast<const float4*>(Q + (size_t)row*qld + c4*4);
        QP[row*QP_LD + c4*4+0] = tf32f(qv.x*0.125f);
        QP[row*QP_LD + c4*4+1] = tf32f(qv.y*0.125f);
        QP[row*QP_LD + c4*4+2] = tf32f(qv.z*0.125f);
        QP[row*QP_LD + c4*4+3] = tf32f(qv.w*0.125f);
    }
    __syncthreads();

    float aq[8][4];
    const int r0 = warp*16 + gq;
    #pragma unroll
    for (int kk=0;kk<8;kk++){
        aq[kk][0] = QP[ r0   *QP_LD + kk*8 + tq];
        aq[kk][1] = QP[(r0+8)*QP_LD + kk*8 + tq];
        aq[kk][2] = QP[ r0   *QP_LD + kk*8 + tq + 4];
        aq[kk][3] = QP[(r0+8)*QP_LD + kk*8 + tq + 4];
    }

    float o[8][4];
    #pragma unroll
    for (int i=0;i<8;i++){ o[i][0]=0.f;o[i][1]=0.f;o[i][2]=0.f;o[i][3]=0.f; }
    float m0=-1e30f, m1=-1e30f, l0=0.f, l1=0.f;

    const int NT = Nn/64;
    for (int j=0;j<NT;j++){
        const int buf = j&1;
        if (j+1 < NT){ load_kv(buf^1, (j+1)*64); cpa_wait<1>(); }
        else         { cpa_wait<0>(); }
        __syncthreads();

        const float* Kb_ = Ks + (size_t)buf*64*KV_LD;
        const float* Vb_ = Vs + (size_t)buf*64*KV_LD;

        // S = (Q*scale) K^T
        float c[8][4];
        #pragma unroll
        for (int nf=0;nf<8;nf++){
            c[nf][0]=0.f;c[nf][1]=0.f;c[nf][2]=0.f;c[nf][3]=0.f;
            #pragma unroll
            for (int kk=0;kk<8;kk++){
                float b[2];
                b[0] = tf32f(Kb_[(nf*8+gq)*KV_LD + kk*8 + tq]);
                b[1] = tf32f(Kb_[(nf*8+gq)*KV_LD + kk*8 + tq + 4]);
                mma_tf32(c[nf], aq[kk], b);
            }
        }
        // online softmax
        float mx0=-1e30f, mx1=-1e30f;
        #pragma unroll
        for (int nf=0;nf<8;nf++){
            mx0 = fmaxf(mx0, fmaxf(c[nf][0], c[nf][1]));
            mx1 = fmaxf(mx1, fmaxf(c[nf][2], c[nf][3]));
        }
        mx0 = fmaxf(mx0, __shfl_xor_sync(0xffffffffu, mx0, 1));
        mx0 = fmaxf(mx0, __shfl_xor_sync(0xffffffffu, mx0, 2));
        mx1 = fmaxf(mx1, __shfl_xor_sync(0xffffffffu, mx1, 1));
        mx1 = fmaxf(mx1, __shfl_xor_sync(0xffffffffu, mx1, 2));
        float nm0 = fmaxf(m0, mx0), nm1 = fmaxf(m1, mx1);
        float al0 = __expf(m0-nm0), al1 = __expf(m1-nm1);
        float s0=0.f, s1=0.f;
        #pragma unroll
        for (int nf=0;nf<8;nf++){
            c[nf][0]=__expf(c[nf][0]-nm0); c[nf][1]=__expf(c[nf][1]-nm0);
            c[nf][2]=__expf(c[nf][2]-nm1); c[nf][3]=__expf(c[nf][3]-nm1);
            s0 += c[nf][0]+c[nf][1]; s1 += c[nf][2]+c[nf][3];
        }
        s0 += __shfl_xor_sync(0xffffffffu, s0, 1);
        s0 += __shfl_xor_sync(0xffffffffu, s0, 2);
        s1 += __shfl_xor_sync(0xffffffffu, s1, 1);
        s1 += __shfl_xor_sync(0xffffffffu, s1, 2);
        l0 = l0*al0 + s0; l1 = l1*al1 + s1;
        m0 = nm0; m1 = nm1;
        #pragma unroll
        for (int nd=0;nd<8;nd++){
            o[nd][0]*=al0; o[nd][1]*=al0; o[nd][2]*=al1; o[nd][3]*=al1;
        }
        // P -> smem (warp-local rows)
        #pragma unroll
        for (int nf=0;nf<8;nf++){
            QP[ r0   *QP_LD + nf*8 + 2*tq  ] = tf32f(c[nf][0]);
            QP[ r0   *QP_LD + nf*8 + 2*tq+1] = tf32f(c[nf][1]);
            QP[(r0+8)*QP_LD + nf*8 + 2*tq  ] = tf32f(c[nf][2]);
            QP[(r0+8)*QP_LD + nf*8 + 2*tq+1] = tf32f(c[nf][3]);
        }
        __syncwarp();
        // O += P V   (V natural layout [j][d])
        #pragma unroll
        for (int kk=0;kk<8;kk++){
            float ap[4];
            ap[0] = QP[ r0   *QP_LD + kk*8 + tq];
            ap[1] = QP[(r0+8)*QP_LD + kk*8 + tq];
            ap[2] = QP[ r0   *QP_LD + kk*8 + tq + 4];
            ap[3] = QP[(r0+8)*QP_LD + kk*8 + tq + 4];
            #pragma unroll
            for (int nd=0;nd<8;nd++){
                float b[2];
                b[0] = tf32f(Vb_[(kk*8+tq  )*KV_LD + nd*8 + gq]);
                b[1] = tf32f(Vb_[(kk*8+tq+4)*KV_LD + nd*8 + gq]);
                mma_tf32(o[nd], ap, b);
            }
        }
        __syncthreads();
    }

    const float inv0 = 1.f/l0, inv1 = 1.f/l1;
    #pragma unroll
    for (int nd=0;nd<8;nd++){
        float2 w0; w0.x = o[nd][0]*inv0; w0.y = o[nd][1]*inv0;
        float2 w1; w1.x = o[nd][2]*inv1; w1.y = o[nd][3]*inv1;
        *reinterpret_cast<float2*>(O + (size_t) r0   *Dd + nd*8 + 2*tq) = w0;
        *reinterpret_cast<float2*>(O + (size_t)(r0+8)*Dd + nd*8 + 2*tq) = w1;
    }
}

// ---------------- split QKV + RoPE into heads layout ----------------
__global__ void qkv_rope_k(const float* __restrict__ qkv,
                           const float* __restrict__ enc0,
                           const float* __restrict__ enc1,
                           float* __restrict__ Q, float* __restrict__ K,
                           float* __restrict__ V)
{
    int idx = blockIdx.x*blockDim.x + threadIdx.x;
    const int total = 2*Bb*Hh*Nn*(HDd/2);
    if (idx >= total) return;
    int p = idx % (HDd/2); int t = idx / (HDd/2);
    int n = t % Nn; t /= Nn;
    int h = t % Hh; t /= Hh;
    int b = t % Bb; int s = t / Bb;
    size_t r = (size_t)(s*Bb + b)*Nn + n;
    const float* row = qkv + r*(3*Dd);
    int d0 = 2*p, d1 = 2*p+1;
    float q0 = row[h*192 + d0*3 + 0], q1 = row[h*192 + d1*3 + 0];
    float k0 = row[h*192 + d0*3 + 1], k1 = row[h*192 + d1*3 + 1];
    float v0 = row[h*192 + d0*3 + 2], v1 = row[h*192 + d1*3 + 2];
    const float* enc = s ? enc1 : enc0;
    size_t eoff = ((size_t)b*Nn + n)*HDd;
    float c = enc[eoff + d0];
    float si = enc[(size_t)Bb*Nn*HDd + eoff + d0];
    float qo0 = q0*c - q1*si, qo1 = q1*c + q0*si;
    float ko0 = k0*c - k1*si, ko1 = k1*c + k0*si;
    size_t bh = (size_t)(s*Bb + b)*Hh + h;
    size_t o = (bh*Nn + n)*HDd;
    Q[o+d0]=qo0; Q[o+d1]=qo1;
    K[o+d0]=ko0; K[o+d1]=ko1;
    V[o+d0]=v0;  V[o+d1]=v1;
}

// copy x into left half of cat (float4)
__global__ void copy_left_k(const float* __restrict__ x, float* __restrict__ cat)
{
    int idx = blockIdx.x*blockDim.x + threadIdx.x;
    const int total = M2*(Dd/4);
    if (idx >= total) return;
    int c = idx % (Dd/4); int r = idx / (Dd/4);
    reinterpret_cast<float4*>(cat)[(size_t)r*(2*Dd/4) + c] =
        reinterpret_cast<const float4*>(x)[idx];
}

// ---------------- fused LayerNorm(512) + exact GELU ----------------
__global__ void ln_gelu_k(float* __restrict__ X, const float* __restrict__ g,
                          const float* __restrict__ be)
{
    float* p = X + (size_t)blockIdx.x * 512;
    int tid = threadIdx.x;
    float a = p[tid], b = p[tid+256];
    float s = a + b;
    float sq = a*a + b*b;
    #pragma unroll
    for (int o=16;o;o>>=1){ s += __shfl_xor_sync(0xffffffffu,s,o);
                            sq += __shfl_xor_sync(0xffffffffu,sq,o); }
    __shared__ float ss[8], sqs[8];
    if ((tid&31)==0){ ss[tid>>5]=s; sqs[tid>>5]=sq; }
    __syncthreads();
    s = 0.f; sq = 0.f;
    #pragma unroll
    for (int t=0;t<8;t++){ s+=ss[t]; sq+=sqs[t]; }
    float mean = s * (1.0f/512.0f);
    float var  = sq * (1.0f/512.0f) - mean*mean;
    float inv = rsqrtf(var + 1e-5f);
    float y0 = (a-mean)*inv*g[tid]     + be[tid];
    float y1 = (b-mean)*inv*g[tid+256] + be[tid+256];
    p[tid]     = 0.5f*y0*(1.0f+erff(y0*0.70710678118f));
    p[tid+256] = 0.5f*y1*(1.0f+erff(y1*0.70710678118f));
}

// ================= host orchestration =================
extern "C" void kernel_launch(void* const* d_in, const int* in_sizes, int n_in,
                              void* d_out, int out_size)
{
    const float* desc0  = (const float*)d_in[0];
    const float* desc1  = (const float*)d_in[1];
    const float* enc0   = (const float*)d_in[2];
    const float* enc1   = (const float*)d_in[3];
    const float* s_Wqkv = (const float*)d_in[4];
    const float* s_bqkv = (const float*)d_in[5];
    const float* s_Wout = (const float*)d_in[6];
    const float* s_bout = (const float*)d_in[7];
    const float* s_W1   = (const float*)d_in[8];
    const float* s_b1   = (const float*)d_in[9];
    const float* s_g    = (const float*)d_in[10];
    const float* s_be   = (const float*)d_in[11];
    const float* s_W2   = (const float*)d_in[12];
    const float* s_b2   = (const float*)d_in[13];
    const float* c_Wqk  = (const float*)d_in[14];
    const float* c_bqk  = (const float*)d_in[15];
    const float* c_Wv   = (const float*)d_in[16];
    const float* c_bv   = (const float*)d_in[17];
    const float* c_Wo   = (const float*)d_in[18];
    const float* c_bo   = (const float*)d_in[19];
    const float* c_W1   = (const float*)d_in[20];
    const float* c_b1   = (const float*)d_in[21];
    const float* c_g    = (const float*)d_in[22];
    const float* c_be   = (const float*)d_in[23];
    const float* c_W2   = (const float*)d_in[24];
    const float* c_b2   = (const float*)d_in[25];
    float* out = (float*)d_out;

    float *x,*qkv,*q,*k,*v,*tmp,*msg,*cat,*hb;
    cudaGetSymbolAddress((void**)&x,   g_x);
    cudaGetSymbolAddress((void**)&qkv, g_qkv);
    cudaGetSymbolAddress((void**)&q,   g_q);
    cudaGetSymbolAddress((void**)&k,   g_k);
    cudaGetSymbolAddress((void**)&v,   g_v);
    cudaGetSymbolAddress((void**)&tmp, g_tmp);
    cudaGetSymbolAddress((void**)&msg, g_msg);
    cudaGetSymbolAddress((void**)&cat, g_cat);
    cudaGetSymbolAddress((void**)&hb,  g_h);

    cudaFuncSetAttribute(flash_k, cudaFuncAttributeMaxDynamicSharedMemorySize, FA_SMEM);

    auto NT = [&](const float* A,int lda,const float* W,int ldb,
                  float* C,int ldc,const float* bias,const float* Res,int ldr,
                  int M,int Nc,int K){
        dim3 gr(Nc/128, M/128);
        tgemm_nt<<<gr,256>>>(A,lda,W,ldb,C,ldc,bias,Res,ldr,K);
    };

    // ======== SELF blocks (desc0||desc1, shared weights) ========
    cudaMemcpyAsync(x,       desc0, BND*sizeof(float), cudaMemcpyDeviceToDevice);
    cudaMemcpyAsync(x + BND, desc1, BND*sizeof(float), cudaMemcpyDeviceToDevice);

    NT(x,Dd, s_Wqkv,Dd, qkv,3*Dd, s_bqkv,nullptr,0, M2,3*Dd,Dd);
    {
        int total = 2*Bb*Hh*Nn*(HDd/2);
        qkv_rope_k<<<(total+255)/256,256>>>(qkv, enc0, enc1, q, k, v);
    }
    {   // flash self attention -> tmp (flat layout)
        dim3 gr(Nn/128, 2*Bb*Hh);
        flash_k<<<gr,256,FA_SMEM>>>(q, k, v, tmp, 0);
    }
    NT(tmp,Dd, s_Wout,Dd, cat+Dd,2*Dd, s_bout,nullptr,0, M2,Dd,Dd);
    copy_left_k<<<(M2*(Dd/4)+255)/256,256>>>(x, cat);
    NT(cat,2*Dd, s_W1,2*Dd, hb,2*Dd, s_b1,nullptr,0, M2,2*Dd,2*Dd);
    ln_gelu_k<<<M2,256>>>(hb, s_g, s_be);
    NT(hb,2*Dd, s_W2,2*Dd, x,Dd, s_b2, x,Dd, M2,Dd,2*Dd);

    // ======== CROSS block ========
    NT(x,Dd, c_Wqk,Dd, tmp,Dd, c_bqk,nullptr,0, M2,Dd,Dd);   // qk (flat)
    NT(x,Dd, c_Wv, Dd, msg,Dd, c_bv, nullptr,0, M2,Dd,Dd);   // v  (flat)
    {   // both directions in one launch
        dim3 gr(Nn/128, 2*Bb*Hh);
        flash_k<<<gr,256,FA_SMEM>>>(tmp, tmp, msg, qkv, 1);
    }
    NT(qkv,Dd, c_Wo,Dd, cat+Dd,2*Dd, c_bo,nullptr,0, M2,Dd,Dd);
    copy_left_k<<<(M2*(Dd/4)+255)/256,256>>>(x, cat);
    NT(cat,2*Dd, c_W1,2*Dd, hb,2*Dd, c_b1,nullptr,0, M2,2*Dd,2*Dd);
    ln_gelu_k<<<M2,256>>>(hb, c_g, c_be);
    NT(hb,2*Dd, c_W2,2*Dd, out,Dd, c_b2, x,Dd, M2,Dd,2*Dd);
}

// round 6
// speedup vs baseline: 2.8191x; 1.0346x over previous
#include <cuda_runtime.h>
#include <mma.h>
#include <math.h>
#include <stdint.h>

using namespace nvcuda;

#define Bb 4
#define Nn 2048
#define Dd 256
#define Hh 4
#define HDd 64
#define M2 (2*Bb*Nn)
#define BND ((size_t)Bb*Nn*Dd)

// ---------------- static scratch ----------------
__device__ float g_x  [(size_t)M2*Dd];
__device__ float g_xr [(size_t)M2*Dd];           // tf32-rounded copy of x
__device__ float g_qkv[(size_t)M2*3*Dd];         // self: qkv; cross: ctx
__device__ float g_q  [(size_t)2*Bb*Hh*Nn*HDd];
__device__ float g_k  [(size_t)2*Bb*Hh*Nn*HDd];
__device__ float g_v  [(size_t)2*Bb*Hh*Nn*HDd];
__device__ float g_tmp[(size_t)M2*Dd];
__device__ float g_cat[(size_t)M2*2*Dd];
__device__ float g_h  [(size_t)M2*2*Dd];
// pre-rounded weights
__device__ float w_qkv [768*256];
__device__ float w_out [256*256];
__device__ float w_s1  [512*512];
__device__ float w_s2  [256*512];
__device__ float w_cqkv[512*256];   // [c_Wqk ; c_Wv]
__device__ float w_co  [256*256];
__device__ float w_c1  [512*512];
__device__ float w_c2  [256*512];

__device__ __forceinline__ float tf32f(float x){
    float y; asm("cvt.rna.tf32.f32 %0, %1;" : "=f"(y) : "f"(x)); return y;
}

// ---------------- cp.async helpers ----------------
__device__ __forceinline__ void cpa16(void* s, const void* g){
    uint32_t sa = (uint32_t)__cvta_generic_to_shared(s);
    asm volatile("cp.async.cg.shared.global [%0], [%1], 16;\n" :: "r"(sa), "l"(g));
}
__device__ __forceinline__ void cpa_commit(){ asm volatile("cp.async.commit_group;\n"); }
template<int N> __device__ __forceinline__ void cpa_wait(){
    asm volatile("cp.async.wait_group %0;\n" :: "n"(N));
}

// ---------------- NT tf32 GEMM, 3-stage cp.async, no in-loop cvt ----------------
// Inputs MUST be pre-rounded to tf32. C = A@W^T (+bias)(+Res); optional rounded
// secondary output Cr; round_out rounds C itself.
#define GLD 20
#define TG_SMEM (3*128*GLD*2*4)
__global__ void __launch_bounds__(256,2)
tgemm_nt(const float* __restrict__ A, int lda,
         const float* __restrict__ W, int ldb,
         float* __restrict__ C, int ldc,
         const float* __restrict__ bias,
         const float* __restrict__ Res, int ldr,
         int K, int round_out, float* __restrict__ Cr)
{
    extern __shared__ float dsm[];
    float (*As)[128][GLD] = reinterpret_cast<float(*)[128][GLD]>(dsm);
    float (*Bs)[128][GLD] = reinterpret_cast<float(*)[128][GLD]>(dsm + 3*128*GLD);

    const int bm = blockIdx.y*128, bn = blockIdx.x*128;
    const int tid = threadIdx.x, warp = tid>>5, lane = tid&31;
    const int wm = warp>>1, wn = warp&1;

    wmma::fragment<wmma::accumulator,16,16,8,float> acc[2][4];
    #pragma unroll
    for (int i=0;i<2;i++)
        #pragma unroll
        for (int j=0;j<4;j++) wmma::fill_fragment(acc[i][j], 0.0f);

    const int row_l = tid>>2, col_l = (tid&3)*4;
    const int row_h = (tid+256)>>2, col_h = ((tid+256)&3)*4;

    auto load_st = [&](int st, int k0){
        cpa16(&As[st][row_l][col_l], A + (size_t)(bm+row_l)*lda + k0 + col_l);
        cpa16(&As[st][row_h][col_h], A + (size_t)(bm+row_h)*lda + k0 + col_h);
        cpa16(&Bs[st][row_l][col_l], W + (size_t)(bn+row_l)*ldb + k0 + col_l);
        cpa16(&Bs[st][row_h][col_h], W + (size_t)(bn+row_h)*ldb + k0 + col_h);
        cpa_commit();
    };

    const int KT = K/16;
    load_st(0, 0);
    if (KT > 1) load_st(1, 16);

    for (int kt=0; kt<KT; kt++){
        const int buf = kt%3;
        if (kt+1 < KT) cpa_wait<1>(); else cpa_wait<0>();
        __syncthreads();
        if (kt+2 < KT) load_st((kt+2)%3, (kt+2)*16);
        #pragma unroll
        for (int ks=0; ks<16; ks+=8){
            wmma::fragment<wmma::matrix_a,16,16,8,wmma::precision::tf32,wmma::row_major> af[2];
            wmma::fragment<wmma::matrix_b,16,16,8,wmma::precision::tf32,wmma::col_major> bf[4];
            #pragma unroll
            for (int i=0;i<2;i++)
                wmma::load_matrix_sync(af[i], &As[buf][wm*32 + i*16][ks], GLD);
            #pragma unroll
            for (int j=0;j<4;j++)
                wmma::load_matrix_sync(bf[j], &Bs[buf][wn*64 + j*16][ks], GLD);
            #pragma unroll
            for (int i=0;i<2;i++)
                #pragma unroll
                for (int j=0;j<4;j++)
                    wmma::mma_sync(acc[i][j], af[i], bf[j], acc[i][j]);
        }
    }
    __syncthreads();

    float* Ep = dsm + warp*256;
    #pragma unroll
    for (int i=0;i<2;i++)
        #pragma unroll
        for (int j=0;j<4;j++){
            wmma::store_matrix_sync(Ep, acc[i][j], 16, wmma::mem_row_major);
            __syncwarp();
            #pragma unroll
            for (int p=0;p<8;p++){
                int idx = p*32 + lane;
                int r = idx>>4, c = idx&15;
                int gr = bm + wm*32 + i*16 + r;
                int gc = bn + wn*64 + j*16 + c;
                float v = Ep[idx];
                if (bias) v += bias[gc];
                if (Res)  v += Res[(size_t)gr*ldr + gc];
                C[(size_t)gr*ldc + gc] = round_out ? tf32f(v) : v;
                if (Cr) Cr[(size_t)gr*ldc + gc] = tf32f(v);
            }
            __syncwarp();
        }
}

// ---------------- mma.sync m16n8k8 tf32 ----------------
__device__ __forceinline__ void mma_tf32(float* c, const float* a, const float* b){
    asm volatile(
      "mma.sync.aligned.m16n8k8.row.col.f32.tf32.tf32.f32 "
      "{%0,%1,%2,%3},{%4,%5,%6,%7},{%8,%9},{%0,%1,%2,%3};\n"
      : "+f"(c[0]),"+f"(c[1]),"+f"(c[2]),"+f"(c[3])
      : "r"(__float_as_uint(a[0])),"r"(__float_as_uint(a[1])),
        "r"(__float_as_uint(a[2])),"r"(__float_as_uint(a[3])),
        "r"(__float_as_uint(b[0])),"r"(__float_as_uint(b[1])));
}

// ---------------- flash attention (HD=64, N=2048) ----------------
// mode 0: self — heads layout [z][n][64]; out flat [row][256].
// mode 1: cross — packed hb layout ld=512 (qk at col 0, v at col 256);
//         z<16: q=desc0,kv=desc1 ; z>=16: reversed. out flat.
#define QP_LD 68
#define KV_LD 68
#define FA_SMEM ((128*QP_LD + 2*64*KV_LD + 2*64*KV_LD)*4)

__global__ void __launch_bounds__(256,2)
flash_k(const float* __restrict__ Qb, const float* __restrict__ Kb,
        const float* __restrict__ Vb, float* __restrict__ Ob, int mode)
{
    extern __shared__ float smf[];
    float* QP = smf;
    float* Ks = smf + 128*QP_LD;
    float* Vs = Ks + 2*64*KV_LD;

    const int z = blockIdx.y, it = blockIdx.x;
    const int tid = threadIdx.x, warp = tid>>5, lane = tid&31;
    const int gq = lane>>2, tq = lane&3;

    size_t qoff, kvoff, ooff;
    int ld;
    if (mode == 0){
        qoff = (size_t)z*Nn*HDd; kvoff = qoff;
        ooff = (size_t)(z>>2)*Nn*Dd + (size_t)(z&3)*HDd;
        ld = HDd;
    } else {
        int h = z>>4, zz = z&15;
        size_t f = (size_t)(zz>>2)*Nn*512 + (size_t)(zz&3)*HDd;
        qoff  = (size_t)h*((size_t)Bb*Nn*512) + f;
        kvoff = (size_t)(1-h)*((size_t)Bb*Nn*512) + f;
        ooff  = (size_t)h*BND + (size_t)(zz>>2)*Nn*Dd + (size_t)(zz&3)*HDd;
        ld = 512;
    }

    const float* Q = Qb + qoff + (size_t)it*128*ld;
    const float* K = Kb + kvoff;
    const float* V = Vb + kvoff;
    float* O = Ob + ooff + (size_t)it*128*Dd;

    const int kr = tid>>4, kc = (tid&15)*4;
    auto load_kv = [&](int buf, int j0){
        #pragma unroll
        for (int itr=0; itr<4; itr++){
            int row = kr + itr*16;
            cpa16(Ks + ((size_t)buf*64 + row)*KV_LD + kc, K + (size_t)(j0+row)*ld + kc);
        }
        #pragma unroll
        for (int itr=0; itr<4; itr++){
            int row = kr + itr*16;
            cpa16(Vs + ((size_t)buf*64 + row)*KV_LD + kc, V + (size_t)(j0+row)*ld + kc);
        }
        cpa_commit();
    };

    load_kv(0, 0);

    // stage Q (inputs pre-rounded; *0.125 is exact)
    #pragma unroll
    for (int r=0;r<8;r++){
        int idx = tid + r*256;
        int row = idx>>4, c4 = idx&15;
        float4 qv = *reinterpret_cast<const float4*>(Q + (size_t)row*ld + c4*4);
        QP[row*QP_LD + c4*4+0] = qv.x*0.125f;
        QP[row*QP_LD + c4*4+1] = qv.y*0.125f;
        QP[row*QP_LD + c4*4+2] = qv.z*0.125f;
        QP[row*QP_LD + c4*4+3] = qv.w*0.125f;
    }
    __syncthreads();

    float aq[8][4];
    const int r0 = warp*16 + gq;
    #pragma unroll
    for (int kk=0;kk<8;kk++){
        aq[kk][0] = QP[ r0   *QP_LD + kk*8 + tq];
        aq[kk][1] = QP[(r0+8)*QP_LD + kk*8 + tq];
        aq[kk][2] = QP[ r0   *QP_LD + kk*8 + tq + 4];
        aq[kk][3] = QP[(r0+8)*QP_LD + kk*8 + tq + 4];
    }

    float o[8][4];
    #pragma unroll
    for (int i=0;i<8;i++){ o[i][0]=0.f;o[i][1]=0.f;o[i][2]=0.f;o[i][3]=0.f; }
    float m0=-1e30f, m1=-1e30f, l0=0.f, l1=0.f;

    const int NT = Nn/64;
    for (int j=0;j<NT;j++){
        const int buf = j&1;
        if (j+1 < NT){ load_kv(buf^1, (j+1)*64); cpa_wait<1>(); }
        else         { cpa_wait<0>(); }
        __syncthreads();

        const float* Kb_ = Ks + (size_t)buf*64*KV_LD;
        const float* Vb_ = Vs + (size_t)buf*64*KV_LD;

        float c[8][4];
        #pragma unroll
        for (int nf=0;nf<8;nf++){
            c[nf][0]=0.f;c[nf][1]=0.f;c[nf][2]=0.f;c[nf][3]=0.f;
            #pragma unroll
            for (int kk=0;kk<8;kk++){
                float b[2];
                b[0] = Kb_[(nf*8+gq)*KV_LD + kk*8 + tq];
                b[1] = Kb_[(nf*8+gq)*KV_LD + kk*8 + tq + 4];
                mma_tf32(c[nf], aq[kk], b);
            }
        }
        float mx0=-1e30f, mx1=-1e30f;
        #pragma unroll
        for (int nf=0;nf<8;nf++){
            mx0 = fmaxf(mx0, fmaxf(c[nf][0], c[nf][1]));
            mx1 = fmaxf(mx1, fmaxf(c[nf][2], c[nf][3]));
        }
        mx0 = fmaxf(mx0, __shfl_xor_sync(0xffffffffu, mx0, 1));
        mx0 = fmaxf(mx0, __shfl_xor_sync(0xffffffffu, mx0, 2));
        mx1 = fmaxf(mx1, __shfl_xor_sync(0xffffffffu, mx1, 1));
        mx1 = fmaxf(mx1, __shfl_xor_sync(0xffffffffu, mx1, 2));
        float nm0 = fmaxf(m0, mx0), nm1 = fmaxf(m1, mx1);
        float al0 = __expf(m0-nm0), al1 = __expf(m1-nm1);
        float s0=0.f, s1=0.f;
        #pragma unroll
        for (int nf=0;nf<8;nf++){
            c[nf][0]=__expf(c[nf][0]-nm0); c[nf][1]=__expf(c[nf][1]-nm0);
            c[nf][2]=__expf(c[nf][2]-nm1); c[nf][3]=__expf(c[nf][3]-nm1);
            s0 += c[nf][0]+c[nf][1]; s1 += c[nf][2]+c[nf][3];
        }
        s0 += __shfl_xor_sync(0xffffffffu, s0, 1);
        s0 += __shfl_xor_sync(0xffffffffu, s0, 2);
        s1 += __shfl_xor_sync(0xffffffffu, s1, 1);
        s1 += __shfl_xor_sync(0xffffffffu, s1, 2);
        l0 = l0*al0 + s0; l1 = l1*al1 + s1;
        m0 = nm0; m1 = nm1;
        #pragma unroll
        for (int nd=0;nd<8;nd++){
            o[nd][0]*=al0; o[nd][1]*=al0; o[nd][2]*=al1; o[nd][3]*=al1;
        }
        // P -> smem (HW truncates to tf32 in the mma)
        #pragma unroll
        for (int nf=0;nf<8;nf++){
            QP[ r0   *QP_LD + nf*8 + 2*tq  ] = c[nf][0];
            QP[ r0   *QP_LD + nf*8 + 2*tq+1] = c[nf][1];
            QP[(r0+8)*QP_LD + nf*8 + 2*tq  ] = c[nf][2];
            QP[(r0+8)*QP_LD + nf*8 + 2*tq+1] = c[nf][3];
        }
        __syncwarp();
        #pragma unroll
        for (int kk=0;kk<8;kk++){
            float ap[4];
            ap[0] = QP[ r0   *QP_LD + kk*8 + tq];
            ap[1] = QP[(r0+8)*QP_LD + kk*8 + tq];
            ap[2] = QP[ r0   *QP_LD + kk*8 + tq + 4];
            ap[3] = QP[(r0+8)*QP_LD + kk*8 + tq + 4];
            #pragma unroll
            for (int nd=0;nd<8;nd++){
                float b[2];
                b[0] = Vb_[(kk*8+tq  )*KV_LD + nd*8 + gq];
                b[1] = Vb_[(kk*8+tq+4)*KV_LD + nd*8 + gq];
                mma_tf32(o[nd], ap, b);
            }
        }
        __syncthreads();
    }

    const float inv0 = 1.f/l0, inv1 = 1.f/l1;
    #pragma unroll
    for (int nd=0;nd<8;nd++){
        float2 w0; w0.x = tf32f(o[nd][0]*inv0); w0.y = tf32f(o[nd][1]*inv0);
        float2 w1; w1.x = tf32f(o[nd][2]*inv1); w1.y = tf32f(o[nd][3]*inv1);
        *reinterpret_cast<float2*>(O + (size_t) r0   *Dd + nd*8 + 2*tq) = w0;
        *reinterpret_cast<float2*>(O + (size_t)(r0+8)*Dd + nd*8 + 2*tq) = w1;
    }
}

// ---------------- small kernels ----------------
__global__ void round_copy_k(const float* __restrict__ s, float* __restrict__ d, int n){
    int i = blockIdx.x*blockDim.x + threadIdx.x;
    if (i < n) d[i] = tf32f(s[i]);
}

__global__ void init_x_k(const float* __restrict__ d0, const float* __restrict__ d1,
                         float* __restrict__ x, float* __restrict__ xr){
    int i = blockIdx.x*blockDim.x + threadIdx.x;
    if (i >= 2*(int)BND) return;
    float v = (i < (int)BND) ? d0[i] : d1[i-(int)BND];
    x[i] = v; xr[i] = tf32f(v);
}

__global__ void qkv_rope_k(const float* __restrict__ qkv,
                           const float* __restrict__ enc0,
                           const float* __restrict__ enc1,
                           float* __restrict__ Q, float* __restrict__ K,
                           float* __restrict__ V)
{
    int idx = blockIdx.x*blockDim.x + threadIdx.x;
    const int total = 2*Bb*Hh*Nn*(HDd/2);
    if (idx >= total) return;
    int p = idx % (HDd/2); int t = idx / (HDd/2);
    int n = t % Nn; t /= Nn;
    int h = t % Hh; t /= Hh;
    int b = t % Bb; int s = t / Bb;
    size_t r = (size_t)(s*Bb + b)*Nn + n;
    const float* row = qkv + r*(3*Dd);
    int d0 = 2*p, d1 = 2*p+1;
    float q0 = row[h*192 + d0*3 + 0], q1 = row[h*192 + d1*3 + 0];
    float k0 = row[h*192 + d0*3 + 1], k1 = row[h*192 + d1*3 + 1];
    float v0 = row[h*192 + d0*3 + 2], v1 = row[h*192 + d1*3 + 2];
    const float* enc = s ? enc1 : enc0;
    size_t eoff = ((size_t)b*Nn + n)*HDd;
    float c = enc[eoff + d0];
    float si = enc[(size_t)Bb*Nn*HDd + eoff + d0];
    float qo0 = q0*c - q1*si, qo1 = q1*c + q0*si;
    float ko0 = k0*c - k1*si, ko1 = k1*c + k0*si;
    size_t bh = (size_t)(s*Bb + b)*Hh + h;
    size_t o = (bh*Nn + n)*HDd;
    Q[o+d0]=tf32f(qo0); Q[o+d1]=tf32f(qo1);
    K[o+d0]=tf32f(ko0); K[o+d1]=tf32f(ko1);
    V[o+d0]=tf32f(v0);  V[o+d1]=tf32f(v1);
}

__global__ void copy_left_k(const float* __restrict__ x, float* __restrict__ cat)
{
    int idx = blockIdx.x*blockDim.x + threadIdx.x;
    const int total = M2*(Dd/4);
    if (idx >= total) return;
    int c = idx % (Dd/4); int r = idx / (Dd/4);
    float4 v = reinterpret_cast<const float4*>(x)[idx];
    v.x = tf32f(v.x); v.y = tf32f(v.y); v.z = tf32f(v.z); v.w = tf32f(v.w);
    reinterpret_cast<float4*>(cat)[(size_t)r*(2*Dd/4) + c] = v;
}

__global__ void ln_gelu_k(float* __restrict__ X, const float* __restrict__ g,
                          const float* __restrict__ be)
{
    float* p = X + (size_t)blockIdx.x * 512;
    int tid = threadIdx.x;
    float a = p[tid], b = p[tid+256];
    float s = a + b;
    float sq = a*a + b*b;
    #pragma unroll
    for (int o=16;o;o>>=1){ s += __shfl_xor_sync(0xffffffffu,s,o);
                            sq += __shfl_xor_sync(0xffffffffu,sq,o); }
    __shared__ float ss[8], sqs[8];
    if ((tid&31)==0){ ss[tid>>5]=s; sqs[tid>>5]=sq; }
    __syncthreads();
    s = 0.f; sq = 0.f;
    #pragma unroll
    for (int t=0;t<8;t++){ s+=ss[t]; sq+=sqs[t]; }
    float mean = s * (1.0f/512.0f);
    float var  = sq * (1.0f/512.0f) - mean*mean;
    float inv = rsqrtf(var + 1e-5f);
    float y0 = (a-mean)*inv*g[tid]     + be[tid];
    float y1 = (b-mean)*inv*g[tid+256] + be[tid+256];
    p[tid]     = tf32f(0.5f*y0*(1.0f+erff(y0*0.70710678118f)));
    p[tid+256] = tf32f(0.5f*y1*(1.0f+erff(y1*0.70710678118f)));
}

// bias add for merged qk|v projection (keeps values tf32-rounded)
__global__ void bias2_k(float* __restrict__ hb, const float* __restrict__ bqk,
                        const float* __restrict__ bv)
{
    int i = blockIdx.x*blockDim.x + threadIdx.x;
    if (i >= M2*512) return;
    int c = i & 511;
    float b = (c < 256) ? bqk[c] : bv[c-256];
    if (b != 0.0f){
        hb[i] = tf32f(hb[i] + b);
    }
}

// ================= host orchestration =================
extern "C" void kernel_launch(void* const* d_in, const int* in_sizes, int n_in,
                              void* d_out, int out_size)
{
    const float* desc0  = (const float*)d_in[0];
    const float* desc1  = (const float*)d_in[1];
    const float* enc0   = (const float*)d_in[2];
    const float* enc1   = (const float*)d_in[3];
    const float* s_Wqkv = (const float*)d_in[4];
    const float* s_bqkv = (const float*)d_in[5];
    const float* s_Wout = (const float*)d_in[6];
    const float* s_bout = (const float*)d_in[7];
    const float* s_W1   = (const float*)d_in[8];
    const float* s_b1   = (const float*)d_in[9];
    const float* s_g    = (const float*)d_in[10];
    const float* s_be   = (const float*)d_in[11];
    const float* s_W2   = (const float*)d_in[12];
    const float* s_b2   = (const float*)d_in[13];
    const float* c_Wqk  = (const float*)d_in[14];
    const float* c_bqk  = (const float*)d_in[15];
    const float* c_Wv   = (const float*)d_in[16];
    const float* c_bv   = (const float*)d_in[17];
    const float* c_Wo   = (const float*)d_in[18];
    const float* c_bo   = (const float*)d_in[19];
    const float* c_W1   = (const float*)d_in[20];
    const float* c_b1   = (const float*)d_in[21];
    const float* c_g    = (const float*)d_in[22];
    const float* c_be   = (const float*)d_in[23];
    const float* c_W2   = (const float*)d_in[24];
    const float* c_b2   = (const float*)d_in[25];
    float* out = (float*)d_out;

    float *x,*xr,*qkv,*q,*k,*v,*tmp,*cat,*hb;
    float *wqkv,*wout,*ws1,*ws2,*wcqkv,*wco,*wc1,*wc2;
    cudaGetSymbolAddress((void**)&x,   g_x);
    cudaGetSymbolAddress((void**)&xr,  g_xr);
    cudaGetSymbolAddress((void**)&qkv, g_qkv);
    cudaGetSymbolAddress((void**)&q,   g_q);
    cudaGetSymbolAddress((void**)&k,   g_k);
    cudaGetSymbolAddress((void**)&v,   g_v);
    cudaGetSymbolAddress((void**)&tmp, g_tmp);
    cudaGetSymbolAddress((void**)&cat, g_cat);
    cudaGetSymbolAddress((void**)&hb,  g_h);
    cudaGetSymbolAddress((void**)&wqkv, w_qkv);
    cudaGetSymbolAddress((void**)&wout, w_out);
    cudaGetSymbolAddress((void**)&ws1,  w_s1);
    cudaGetSymbolAddress((void**)&ws2,  w_s2);
    cudaGetSymbolAddress((void**)&wcqkv,w_cqkv);
    cudaGetSymbolAddress((void**)&wco,  w_co);
    cudaGetSymbolAddress((void**)&wc1,  w_c1);
    cudaGetSymbolAddress((void**)&wc2,  w_c2);

    cudaFuncSetAttribute(flash_k,  cudaFuncAttributeMaxDynamicSharedMemorySize, FA_SMEM);
    cudaFuncSetAttribute(tgemm_nt, cudaFuncAttributeMaxDynamicSharedMemorySize, TG_SMEM);

    auto RC = [&](const float* s, float* d, int n){
        round_copy_k<<<(n+255)/256,256>>>(s,d,n);
    };
    auto NT = [&](const float* A,int lda,const float* W,int ldb,
                  float* C,int ldc,const float* bias,const float* Res,int ldr,
                  int M,int Nc,int K,int round_out,float* Cr){
        dim3 gr(Nc/128, M/128);
        tgemm_nt<<<gr,256,TG_SMEM>>>(A,lda,W,ldb,C,ldc,bias,Res,ldr,K,round_out,Cr);
    };

    // ---- weight prep (rounded copies; c_Wqk|c_Wv packed) ----
    RC(s_Wqkv, wqkv, 768*256);
    RC(s_Wout, wout, 256*256);
    RC(s_W1,   ws1,  512*512);
    RC(s_W2,   ws2,  256*512);
    RC(c_Wqk,  wcqkv,         256*256);
    RC(c_Wv,   wcqkv+256*256, 256*256);
    RC(c_Wo,   wco,  256*256);
    RC(c_W1,   wc1,  512*512);
    RC(c_W2,   wc2,  256*512);

    // ======== SELF blocks ========
    init_x_k<<<(2*(int)BND+255)/256,256>>>(desc0, desc1, x, xr);

    NT(xr,Dd, wqkv,Dd, qkv,3*Dd, s_bqkv,nullptr,0, M2,3*Dd,Dd, 0,nullptr);
    {
        int total = 2*Bb*Hh*Nn*(HDd/2);
        qkv_rope_k<<<(total+255)/256,256>>>(qkv, enc0, enc1, q, k, v);
    }
    {
        dim3 gr(Nn/128, 2*Bb*Hh);
        flash_k<<<gr,256,FA_SMEM>>>(q, k, v, tmp, 0);
    }
    NT(tmp,Dd, wout,Dd, cat+Dd,2*Dd, s_bout,nullptr,0, M2,Dd,Dd, 1,nullptr);
    copy_left_k<<<(M2*(Dd/4)+255)/256,256>>>(x, cat);
    NT(cat,2*Dd, ws1,2*Dd, hb,2*Dd, s_b1,nullptr,0, M2,2*Dd,2*Dd, 0,nullptr);
    ln_gelu_k<<<M2,256>>>(hb, s_g, s_be);
    NT(hb,2*Dd, ws2,2*Dd, x,Dd, s_b2, x,Dd, M2,Dd,2*Dd, 0,xr);   // x = x+ffn; xr = round(x)

    // ======== CROSS block ========
    // merged qk|v projection: hb[M2][512] = [qk | v], rounded
    NT(xr,Dd, wcqkv,Dd, hb,512, nullptr,nullptr,0, M2,512,Dd, 1,nullptr);
    bias2_k<<<(M2*512+255)/256,256>>>(hb, c_bqk, c_bv);
    {
        dim3 gr(Nn/128, 2*Bb*Hh);
        flash_k<<<gr,256,FA_SMEM>>>(hb, hb, hb+256, qkv, 1);
    }
    NT(qkv,Dd, wco,Dd, cat+Dd,2*Dd, c_bo,nullptr,0, M2,Dd,Dd, 1,nullptr);
    copy_left_k<<<(M2*(Dd/4)+255)/256,256>>>(x, cat);
    NT(cat,2*Dd, wc1,2*Dd, hb,2*Dd, c_b1,nullptr,0, M2,2*Dd,2*Dd, 0,nullptr);
    ln_gelu_k<<<M2,256>>>(hb, c_g, c_be);
    NT(hb,2*Dd, wc2,2*Dd, out,Dd, c_b2, x,Dd, M2,Dd,2*Dd, 0,nullptr);
}

// round 8
// speedup vs baseline: 3.7116x; 1.3166x over previous
#include <cuda_runtime.h>
#include <math.h>
#include <stdint.h>

#define Bb 4
#define Nn 2048
#define Dd 256
#define Hh 4
#define HDd 64
#define M2 (2*Bb*Nn)
#define BND ((size_t)Bb*Nn*Dd)

// ---------------- static scratch ----------------
__device__ float g_x  [(size_t)M2*Dd];
__device__ float g_xr [(size_t)M2*Dd];
__device__ float g_qkv[(size_t)M2*3*Dd];   // qkv; later: msgR (self), ctx (cross)
__device__ float g_q  [(size_t)2*Bb*Hh*Nn*HDd];
__device__ float g_k  [(size_t)2*Bb*Hh*Nn*HDd];
__device__ float g_v  [(size_t)2*Bb*Hh*Nn*HDd];
__device__ float g_tmp[(size_t)M2*Dd];
__device__ float g_h  [(size_t)M2*2*Dd];
// pre-rounded weights
__device__ float w_qkv [768*256];
__device__ float w_out [256*256];
__device__ float w_s1  [512*512];
__device__ float w_s2  [256*512];
__device__ float w_cqkv[512*256];
__device__ float w_co  [256*256];
__device__ float w_c1  [512*512];
__device__ float w_c2  [256*512];

__device__ __forceinline__ float tf32f(float x){
    float y; asm("cvt.rna.tf32.f32 %0, %1;" : "=f"(y) : "f"(x)); return y;
}

// ---------------- cp.async helpers ----------------
__device__ __forceinline__ void cpa16(uint32_t s, const void* g){
    asm volatile("cp.async.cg.shared.global [%0], [%1], 16;\n" :: "r"(s), "l"(g));
}
__device__ __forceinline__ void cpa_commit(){ asm volatile("cp.async.commit_group;\n"); }
template<int N> __device__ __forceinline__ void cpa_wait(){
    asm volatile("cp.async.wait_group %0;\n" :: "n"(N));
}
__device__ __forceinline__ uint32_t smem_u32(const void* p){
    uint32_t a;
    asm("{ .reg .u64 t; cvta.to.shared.u64 t, %1; cvt.u32.u64 %0, t; }" : "=r"(a) : "l"(p));
    return a;
}

// ---------------- mma.sync m16n8k8 tf32 ----------------
__device__ __forceinline__ void mma_tf32(float* c, const float* a, const float* b){
    asm volatile(
      "mma.sync.aligned.m16n8k8.row.col.f32.tf32.tf32.f32 "
      "{%0,%1,%2,%3},{%4,%5,%6,%7},{%8,%9},{%0,%1,%2,%3};\n"
      : "+f"(c[0]),"+f"(c[1]),"+f"(c[2]),"+f"(c[3])
      : "r"(__float_as_uint(a[0])),"r"(__float_as_uint(a[1])),
        "r"(__float_as_uint(a[2])),"r"(__float_as_uint(a[3])),
        "r"(__float_as_uint(b[0])),"r"(__float_as_uint(b[1])));
}

// ---------------- NT tf32 GEMM: 128x128 CTA, 4 warps (64x64 each) ----------------
// C = A@W^T (+bias/bias2)(+Res). Inputs pre-rounded tf32.
// A2 != null: K=512 split — cols 0-255 from A (ld 256), 256-511 from A2 (ld 256).
// bias2 != null: cols >= 256 use bias2[col-256].
#define GLD 20
#define MG_SMEM (3*128*GLD*2*4)
__global__ void __launch_bounds__(128,2)
mgemm(const float* __restrict__ A, const float* __restrict__ A2, int lda,
      const float* __restrict__ W, int ldb,
      float* __restrict__ C, int ldc,
      const float* __restrict__ bias, const float* __restrict__ bias2,
      const float* __restrict__ Res, int ldr,
      int K, int round_out, float* __restrict__ Cr)
{
    extern __shared__ float dsm[];
    float (*As)[128][GLD] = reinterpret_cast<float(*)[128][GLD]>(dsm);
    float (*Bs)[128][GLD] = reinterpret_cast<float(*)[128][GLD]>(dsm + 3*128*GLD);

    const int bm = blockIdx.y*128, bn = blockIdx.x*128;
    const int tid = threadIdx.x, warp = tid>>5, lane = tid&31;
    const int wm = warp>>1, wn = warp&1;
    const int gq = lane>>2, tq = lane&3;

    float acc[4][8][4];
    #pragma unroll
    for (int m=0;m<4;m++)
        #pragma unroll
        for (int n=0;n<8;n++){
            acc[m][n][0]=0.f; acc[m][n][1]=0.f; acc[m][n][2]=0.f; acc[m][n][3]=0.f;
        }

    auto ld_tile = [&](int st, int k0){
        const float* Ab; int ka;
        if (A2 && k0 >= 256){ Ab = A2; ka = k0 - 256; } else { Ab = A; ka = k0; }
        #pragma unroll
        for (int i=0;i<4;i++){
            int id = tid + i*128;
            int row = id>>2, c4 = id&3;
            cpa16(smem_u32(&As[st][row][c4*4]), Ab + (size_t)(bm+row)*((A2)?256:lda) + ka + c4*4);
        }
        #pragma unroll
        for (int i=0;i<4;i++){
            int id = tid + i*128;
            int row = id>>2, c4 = id&3;
            cpa16(smem_u32(&Bs[st][row][c4*4]), W + (size_t)(bn+row)*ldb + k0 + c4*4);
        }
        cpa_commit();
    };

    const int KT = K/16;
    ld_tile(0, 0);
    ld_tile(1, 16);

    for (int kt=0; kt<KT; kt++){
        const int buf = kt%3;
        if (kt+1 < KT) cpa_wait<1>(); else cpa_wait<0>();
        __syncthreads();
        if (kt+2 < KT) ld_tile((kt+2)%3, (kt+2)*16);
        #pragma unroll
        for (int ks=0; ks<16; ks+=8){
            float a[4][4], b[8][2];
            #pragma unroll
            for (int m=0;m<4;m++){
                a[m][0] = As[buf][wm*64 + m*16 + gq    ][ks + tq];
                a[m][1] = As[buf][wm*64 + m*16 + gq + 8][ks + tq];
                a[m][2] = As[buf][wm*64 + m*16 + gq    ][ks + tq + 4];
                a[m][3] = As[buf][wm*64 + m*16 + gq + 8][ks + tq + 4];
            }
            #pragma unroll
            for (int n=0;n<8;n++){
                b[n][0] = Bs[buf][wn*64 + n*8 + gq][ks + tq];
                b[n][1] = Bs[buf][wn*64 + n*8 + gq][ks + tq + 4];
            }
            #pragma unroll
            for (int m=0;m<4;m++)
                #pragma unroll
                for (int n=0;n<8;n++)
                    mma_tf32(acc[m][n], a[m], b[n]);
        }
    }

    // epilogue: direct global stores (float2 pairs)
    #pragma unroll
    for (int m=0;m<4;m++){
        const int r0g = bm + wm*64 + m*16 + gq;
        #pragma unroll
        for (int n=0;n<8;n++){
            const int cg = bn + wn*64 + n*8 + 2*tq;
            float v0=acc[m][n][0], v1=acc[m][n][1], v2=acc[m][n][2], v3=acc[m][n][3];
            if (bias){
                float b0, b1;
                if (bias2 && cg >= 256){ b0 = bias2[cg-256]; b1 = bias2[cg-255]; }
                else                   { b0 = bias[cg];      b1 = bias[cg+1];    }
                v0+=b0; v1+=b1; v2+=b0; v3+=b1;
            }
            if (Res){
                const float* rp0 = Res + (size_t)r0g*ldr + cg;
                const float* rp1 = Res + (size_t)(r0g+8)*ldr + cg;
                v0+=rp0[0]; v1+=rp0[1]; v2+=rp1[0]; v3+=rp1[1];
            }
            float2 w0, w1;
            if (round_out){ w0.x=tf32f(v0); w0.y=tf32f(v1); w1.x=tf32f(v2); w1.y=tf32f(v3); }
            else          { w0.x=v0; w0.y=v1; w1.x=v2; w1.y=v3; }
            *reinterpret_cast<float2*>(C + (size_t)r0g*ldc + cg)     = w0;
            *reinterpret_cast<float2*>(C + (size_t)(r0g+8)*ldc + cg) = w1;
            if (Cr){
                float2 q0, q1;
                q0.x=tf32f(v0); q0.y=tf32f(v1); q1.x=tf32f(v2); q1.y=tf32f(v3);
                *reinterpret_cast<float2*>(Cr + (size_t)r0g*ldc + cg)     = q0;
                *reinterpret_cast<float2*>(Cr + (size_t)(r0g+8)*ldc + cg) = q1;
            }
        }
    }
}

// ---------------- flash attention (unchanged, passing R6 version) ----------------
#define QP_LD 68
#define KV_LD 68
#define FA_SMEM ((128*QP_LD + 2*64*KV_LD + 2*64*KV_LD)*4)

__global__ void __launch_bounds__(256,2)
flash_k(const float* __restrict__ Qb, const float* __restrict__ Kb,
        const float* __restrict__ Vb, float* __restrict__ Ob, int mode)
{
    extern __shared__ float smf[];
    float* QP = smf;
    float* Ks = smf + 128*QP_LD;
    float* Vs = Ks + 2*64*KV_LD;

    const int z = blockIdx.y, it = blockIdx.x;
    const int tid = threadIdx.x, warp = tid>>5, lane = tid&31;
    const int gq = lane>>2, tq = lane&3;

    size_t qoff, kvoff, ooff;
    int ld;
    if (mode == 0){
        qoff = (size_t)z*Nn*HDd; kvoff = qoff;
        ooff = (size_t)(z>>2)*Nn*Dd + (size_t)(z&3)*HDd;
        ld = HDd;
    } else {
        int h = z>>4, zz = z&15;
        size_t f = (size_t)(zz>>2)*Nn*512 + (size_t)(zz&3)*HDd;
        qoff  = (size_t)h*((size_t)Bb*Nn*512) + f;
        kvoff = (size_t)(1-h)*((size_t)Bb*Nn*512) + f;
        ooff  = (size_t)h*BND + (size_t)(zz>>2)*Nn*Dd + (size_t)(zz&3)*HDd;
        ld = 512;
    }

    const float* Q = Qb + qoff + (size_t)it*128*ld;
    const float* K = Kb + kvoff;
    const float* V = Vb + kvoff;
    float* O = Ob + ooff + (size_t)it*128*Dd;

    const int kr = tid>>4, kc = (tid&15)*4;
    auto load_kv = [&](int buf, int j0){
        #pragma unroll
        for (int itr=0; itr<4; itr++){
            int row = kr + itr*16;
            cpa16(smem_u32(Ks + ((size_t)buf*64 + row)*KV_LD + kc), K + (size_t)(j0+row)*ld + kc);
        }
        #pragma unroll
        for (int itr=0; itr<4; itr++){
            int row = kr + itr*16;
            cpa16(smem_u32(Vs + ((size_t)buf*64 + row)*KV_LD + kc), V + (size_t)(j0+row)*ld + kc);
        }
        cpa_commit();
    };

    load_kv(0, 0);

    #pragma unroll
    for (int r=0;r<8;r++){
        int idx = tid + r*256;
        int row = idx>>4, c4 = idx&15;
        float4 qv = *reinterpret_cast<const float4*>(Q + (size_t)row*ld + c4*4);
        QP[row*QP_LD + c4*4+0] = qv.x*0.125f;
        QP[row*QP_LD + c4*4+1] = qv.y*0.125f;
        QP[row*QP_LD + c4*4+2] = qv.z*0.125f;
        QP[row*QP_LD + c4*4+3] = qv.w*0.125f;
    }
    __syncthreads();

    float aq[8][4];
    const int r0 = warp*16 + gq;
    #pragma unroll
    for (int kk=0;kk<8;kk++){
        aq[kk][0] = QP[ r0   *QP_LD + kk*8 + tq];
        aq[kk][1] = QP[(r0+8)*QP_LD + kk*8 + tq];
        aq[kk][2] = QP[ r0   *QP_LD + kk*8 + tq + 4];
        aq[kk][3] = QP[(r0+8)*QP_LD + kk*8 + tq + 4];
    }

    float o[8][4];
    #pragma unroll
    for (int i=0;i<8;i++){ o[i][0]=0.f;o[i][1]=0.f;o[i][2]=0.f;o[i][3]=0.f; }
    float m0=-1e30f, m1=-1e30f, l0=0.f, l1=0.f;

    const int NT = Nn/64;
    for (int j=0;j<NT;j++){
        const int buf = j&1;
        if (j+1 < NT){ load_kv(buf^1, (j+1)*64); cpa_wait<1>(); }
        else         { cpa_wait<0>(); }
        __syncthreads();

        const float* Kb_ = Ks + (size_t)buf*64*KV_LD;
        const float* Vb_ = Vs + (size_t)buf*64*KV_LD;

        float c[8][4];
        #pragma unroll
        for (int nf=0;nf<8;nf++){
            c[nf][0]=0.f;c[nf][1]=0.f;c[nf][2]=0.f;c[nf][3]=0.f;
            #pragma unroll
            for (int kk=0;kk<8;kk++){
                float b[2];
                b[0] = Kb_[(nf*8+gq)*KV_LD + kk*8 + tq];
                b[1] = Kb_[(nf*8+gq)*KV_LD + kk*8 + tq + 4];
                mma_tf32(c[nf], aq[kk], b);
            }
        }
        float mx0=-1e30f, mx1=-1e30f;
        #pragma unroll
        for (int nf=0;nf<8;nf++){
            mx0 = fmaxf(mx0, fmaxf(c[nf][0], c[nf][1]));
            mx1 = fmaxf(mx1, fmaxf(c[nf][2], c[nf][3]));
        }
        mx0 = fmaxf(mx0, __shfl_xor_sync(0xffffffffu, mx0, 1));
        mx0 = fmaxf(mx0, __shfl_xor_sync(0xffffffffu, mx0, 2));
        mx1 = fmaxf(mx1, __shfl_xor_sync(0xffffffffu, mx1, 1));
        mx1 = fmaxf(mx1, __shfl_xor_sync(0xffffffffu, mx1, 2));
        float nm0 = fmaxf(m0, mx0), nm1 = fmaxf(m1, mx1);
        float al0 = __expf(m0-nm0), al1 = __expf(m1-nm1);
        float s0=0.f, s1=0.f;
        #pragma unroll
        for (int nf=0;nf<8;nf++){
            c[nf][0]=__expf(c[nf][0]-nm0); c[nf][1]=__expf(c[nf][1]-nm0);
            c[nf][2]=__expf(c[nf][2]-nm1); c[nf][3]=__expf(c[nf][3]-nm1);
            s0 += c[nf][0]+c[nf][1]; s1 += c[nf][2]+c[nf][3];
        }
        s0 += __shfl_xor_sync(0xffffffffu, s0, 1);
        s0 += __shfl_xor_sync(0xffffffffu, s0, 2);
        s1 += __shfl_xor_sync(0xffffffffu, s1, 1);
        s1 += __shfl_xor_sync(0xffffffffu, s1, 2);
        l0 = l0*al0 + s0; l1 = l1*al1 + s1;
        m0 = nm0; m1 = nm1;
        #pragma unroll
        for (int nd=0;nd<8;nd++){
            o[nd][0]*=al0; o[nd][1]*=al0; o[nd][2]*=al1; o[nd][3]*=al1;
        }
        #pragma unroll
        for (int nf=0;nf<8;nf++){
            QP[ r0   *QP_LD + nf*8 + 2*tq  ] = c[nf][0];
            QP[ r0   *QP_LD + nf*8 + 2*tq+1] = c[nf][1];
            QP[(r0+8)*QP_LD + nf*8 + 2*tq  ] = c[nf][2];
            QP[(r0+8)*QP_LD + nf*8 + 2*tq+1] = c[nf][3];
        }
        __syncwarp();
        #pragma unroll
        for (int kk=0;kk<8;kk++){
            float ap[4];
            ap[0] = QP[ r0   *QP_LD + kk*8 + tq];
            ap[1] = QP[(r0+8)*QP_LD + kk*8 + tq];
            ap[2] = QP[ r0   *QP_LD + kk*8 + tq + 4];
            ap[3] = QP[(r0+8)*QP_LD + kk*8 + tq + 4];
            #pragma unroll
            for (int nd=0;nd<8;nd++){
                float b[2];
                b[0] = Vb_[(kk*8+tq  )*KV_LD + nd*8 + gq];
                b[1] = Vb_[(kk*8+tq+4)*KV_LD + nd*8 + gq];
                mma_tf32(o[nd], ap, b);
            }
        }
        __syncthreads();
    }

    const float inv0 = 1.f/l0, inv1 = 1.f/l1;
    #pragma unroll
    for (int nd=0;nd<8;nd++){
        float2 w0; w0.x = tf32f(o[nd][0]*inv0); w0.y = tf32f(o[nd][1]*inv0);
        float2 w1; w1.x = tf32f(o[nd][2]*inv1); w1.y = tf32f(o[nd][3]*inv1);
        *reinterpret_cast<float2*>(O + (size_t) r0   *Dd + nd*8 + 2*tq) = w0;
        *reinterpret_cast<float2*>(O + (size_t)(r0+8)*Dd + nd*8 + 2*tq) = w1;
    }
}

// ---------------- small kernels ----------------
__global__ void prep_k(const float* a,const float* b,const float* c,const float* d,
                       const float* e,const float* f,const float* g,const float* h,
                       const float* i)
{
    int t = blockIdx.x*blockDim.x + threadIdx.x;
    switch (blockIdx.y){
        case 0: if (t<196608) w_qkv[t]        = tf32f(a[t]); break;
        case 1: if (t<65536)  w_out[t]        = tf32f(b[t]); break;
        case 2: if (t<262144) w_s1[t]         = tf32f(c[t]); break;
        case 3: if (t<131072) w_s2[t]         = tf32f(d[t]); break;
        case 4: if (t<65536)  w_cqkv[t]       = tf32f(e[t]); break;
        case 5: if (t<65536)  w_cqkv[65536+t] = tf32f(f[t]); break;
        case 6: if (t<65536)  w_co[t]         = tf32f(g[t]); break;
        case 7: if (t<262144) w_c1[t]         = tf32f(h[t]); break;
        case 8: if (t<131072) w_c2[t]         = tf32f(i[t]); break;
    }
}

__global__ void init_x_k(const float* __restrict__ d0, const float* __restrict__ d1,
                         float* __restrict__ x, float* __restrict__ xr){
    int i = blockIdx.x*blockDim.x + threadIdx.x;
    if (i >= 2*(int)BND) return;
    float v = (i < (int)BND) ? d0[i] : d1[i-(int)BND];
    x[i] = v; xr[i] = tf32f(v);
}

__global__ void qkv_rope_k(const float* __restrict__ qkv,
                           const float* __restrict__ enc0,
                           const float* __restrict__ enc1,
                           float* __restrict__ Q, float* __restrict__ K,
                           float* __restrict__ V)
{
    int idx = blockIdx.x*blockDim.x + threadIdx.x;
    const int total = 2*Bb*Hh*Nn*(HDd/2);
    if (idx >= total) return;
    int p = idx % (HDd/2); int t = idx / (HDd/2);
    int n = t % Nn; t /= Nn;
    int h = t % Hh; t /= Hh;
    int b = t % Bb; int s = t / Bb;
    size_t r = (size_t)(s*Bb + b)*Nn + n;
    const float* row = qkv + r*(3*Dd);
    int d0 = 2*p, d1 = 2*p+1;
    float q0 = row[h*192 + d0*3 + 0], q1 = row[h*192 + d1*3 + 0];
    float k0 = row[h*192 + d0*3 + 1], k1 = row[h*192 + d1*3 + 1];
    float v0 = row[h*192 + d0*3 + 2], v1 = row[h*192 + d1*3 + 2];
    const float* enc = s ? enc1 : enc0;
    size_t eoff = ((size_t)b*Nn + n)*HDd;
    float c = enc[eoff + d0];
    float si = enc[(size_t)Bb*Nn*HDd + eoff + d0];
    float qo0 = q0*c - q1*si, qo1 = q1*c + q0*si;
    float ko0 = k0*c - k1*si, ko1 = k1*c + k0*si;
    size_t bh = (size_t)(s*Bb + b)*Hh + h;
    size_t o = (bh*Nn + n)*HDd;
    Q[o+d0]=tf32f(qo0); Q[o+d1]=tf32f(qo1);
    K[o+d0]=tf32f(ko0); K[o+d1]=tf32f(ko1);
    V[o+d0]=tf32f(v0);  V[o+d1]=tf32f(v1);
}

__global__ void ln_gelu_k(float* __restrict__ X, const float* __restrict__ g,
                          const float* __restrict__ be)
{
    float* p = X + (size_t)blockIdx.x * 512;
    int tid = threadIdx.x;
    float a = p[tid], b = p[tid+256];
    float s = a + b;
    float sq = a*a + b*b;
    #pragma unroll
    for (int o=16;o;o>>=1){ s += __shfl_xor_sync(0xffffffffu,s,o);
                            sq += __shfl_xor_sync(0xffffffffu,sq,o); }
    __shared__ float ss[8], sqs[8];
    if ((tid&31)==0){ ss[tid>>5]=s; sqs[tid>>5]=sq; }
    __syncthreads();
    s = 0.f; sq = 0.f;
    #pragma unroll
    for (int t=0;t<8;t++){ s+=ss[t]; sq+=sqs[t]; }
    float mean = s * (1.0f/512.0f);
    float var  = sq * (1.0f/512.0f) - mean*mean;
    float inv = rsqrtf(var + 1e-5f);
    float y0 = (a-mean)*inv*g[tid]     + be[tid];
    float y1 = (b-mean)*inv*g[tid+256] + be[tid+256];
    p[tid]     = tf32f(0.5f*y0*(1.0f+erff(y0*0.70710678118f)));
    p[tid+256] = tf32f(0.5f*y1*(1.0f+erff(y1*0.70710678118f)));
}

// ================= host orchestration =================
extern "C" void kernel_launch(void* const* d_in, const int* in_sizes, int n_in,
                              void* d_out, int out_size)
{
    const float* desc0  = (const float*)d_in[0];
    const float* desc1  = (const float*)d_in[1];
    const float* enc0   = (const float*)d_in[2];
    const float* enc1   = (const float*)d_in[3];
    const float* s_Wqkv = (const float*)d_in[4];
    const float* s_bqkv = (const float*)d_in[5];
    const float* s_Wout = (const float*)d_in[6];
    const float* s_bout = (const float*)d_in[7];
    const float* s_W1   = (const float*)d_in[8];
    const float* s_b1   = (const float*)d_in[9];
    const float* s_g    = (const float*)d_in[10];
    const float* s_be   = (const float*)d_in[11];
    const float* s_W2   = (const float*)d_in[12];
    const float* s_b2   = (const float*)d_in[13];
    const float* c_Wqk  = (const float*)d_in[14];
    const float* c_bqk  = (const float*)d_in[15];
    const float* c_Wv   = (const float*)d_in[16];
    const float* c_bv   = (const float*)d_in[17];
    const float* c_Wo   = (const float*)d_in[18];
    const float* c_bo   = (const float*)d_in[19];
    const float* c_W1   = (const float*)d_in[20];
    const float* c_b1   = (const float*)d_in[21];
    const float* c_g    = (const float*)d_in[22];
    const float* c_be   = (const float*)d_in[23];
    const float* c_W2   = (const float*)d_in[24];
    const float* c_b2   = (const float*)d_in[25];
    float* out = (float*)d_out;

    float *x,*xr,*qkv,*q,*k,*v,*tmp,*hb;
    float *wqkv,*wout,*ws1,*ws2,*wcqkv,*wco,*wc1,*wc2;
    cudaGetSymbolAddress((void**)&x,   g_x);
    cudaGetSymbolAddress((void**)&xr,  g_xr);
    cudaGetSymbolAddress((void**)&qkv, g_qkv);
    cudaGetSymbolAddress((void**)&q,   g_q);
    cudaGetSymbolAddress((void**)&k,   g_k);
    cudaGetSymbolAddress((void**)&v,   g_v);
    cudaGetSymbolAddress((void**)&tmp, g_tmp);
    cudaGetSymbolAddress((void**)&hb,  g_h);
    cudaGetSymbolAddress((void**)&wqkv, w_qkv);
    cudaGetSymbolAddress((void**)&wout, w_out);
    cudaGetSymbolAddress((void**)&ws1,  w_s1);
    cudaGetSymbolAddress((void**)&ws2,  w_s2);
    cudaGetSymbolAddress((void**)&wcqkv,w_cqkv);
    cudaGetSymbolAddress((void**)&wco,  w_co);
    cudaGetSymbolAddress((void**)&wc1,  w_c1);
    cudaGetSymbolAddress((void**)&wc2,  w_c2);

    cudaFuncSetAttribute(flash_k, cudaFuncAttributeMaxDynamicSharedMemorySize, FA_SMEM);
    cudaFuncSetAttribute(mgemm,   cudaFuncAttributeMaxDynamicSharedMemorySize, MG_SMEM);

    auto GE = [&](const float* A,const float* A2,int lda,const float* W,int ldb,
                  float* C,int ldc,const float* bias,const float* bias2,
                  const float* Res,int ldr,int M,int Nc,int K,int ro,float* Cr){
        dim3 gr(Nc/128, M/128);
        mgemm<<<gr,128,MG_SMEM>>>(A,A2,lda,W,ldb,C,ldc,bias,bias2,Res,ldr,K,ro,Cr);
    };

    // 1
    {
        dim3 gr(1024, 9);
        prep_k<<<gr,256>>>(s_Wqkv,s_Wout,s_W1,s_W2,c_Wqk,c_Wv,c_Wo,c_W1,c_W2);
    }
    // 2
    init_x_k<<<(2*(int)BND+255)/256,256>>>(desc0, desc1, x, xr);
    // 3: qkv
    GE(xr,nullptr,Dd, wqkv,Dd, qkv,3*Dd, s_bqkv,nullptr, nullptr,0, M2,3*Dd,Dd, 0,nullptr);
    // 4
    {
        int total = 2*Bb*Hh*Nn*(HDd/2);
        qkv_rope_k<<<(total+255)/256,256>>>(qkv, enc0, enc1, q, k, v);
    }
    // 5: flash self -> tmp (flat, rounded)
    {
        dim3 gr(Nn/128, 2*Bb*Hh);
        flash_k<<<gr,256,FA_SMEM>>>(q, k, v, tmp, 0);
    }
    // 6: msg = wout(tmp) -> qkv buffer (ld 256, rounded)   [ncu window]
    GE(tmp,nullptr,Dd, wout,Dd, qkv,Dd, s_bout,nullptr, nullptr,0, M2,Dd,Dd, 1,nullptr);
    // FFN: h = W1 @ [xr | msg]
    GE(xr,qkv,Dd, ws1,2*Dd, hb,2*Dd, s_b1,nullptr, nullptr,0, M2,2*Dd,2*Dd, 0,nullptr);
    ln_gelu_k<<<M2,256>>>(hb, s_g, s_be);
    GE(hb,nullptr,2*Dd, ws2,2*Dd, x,Dd, s_b2,nullptr, x,Dd, M2,Dd,2*Dd, 0,xr);

    // ======== CROSS block ========
    // merged qk|v projection with fused per-half biases, rounded
    GE(xr,nullptr,Dd, wcqkv,Dd, hb,512, c_bqk,c_bv, nullptr,0, M2,512,Dd, 1,nullptr);
    {
        dim3 gr(Nn/128, 2*Bb*Hh);
        flash_k<<<gr,256,FA_SMEM>>>(hb, hb, hb+256, qkv, 1);   // ctx -> qkv
    }
    // msg = Wo(ctx) -> tmp (rounded)
    GE(qkv,nullptr,Dd, wco,Dd, tmp,Dd, c_bo,nullptr, nullptr,0, M2,Dd,Dd, 1,nullptr);
    GE(xr,tmp,Dd, wc1,2*Dd, hb,2*Dd, c_b1,nullptr, nullptr,0, M2,2*Dd,2*Dd, 0,nullptr);
    ln_gelu_k<<<M2,256>>>(hb, c_g, c_be);
    GE(hb,nullptr,2*Dd, wc2,2*Dd, out,Dd, c_b2,nullptr, x,Dd, M2,Dd,2*Dd, 0,nullptr);
}

// round 9
// speedup vs baseline: 3.9543x; 1.0654x over previous
#include <cuda_runtime.h>
#include <math.h>
#include <stdint.h>

#define Bb 4
#define Nn 2048
#define Dd 256
#define Hh 4
#define HDd 64
#define M2 (2*Bb*Nn)
#define BND ((size_t)Bb*Nn*Dd)

// ---------------- static scratch ----------------
__device__ float g_x  [(size_t)M2*Dd];
__device__ float g_xr [(size_t)M2*Dd];
__device__ float g_qkv[(size_t)M2*3*Dd];
__device__ float g_q  [(size_t)2*Bb*Hh*Nn*HDd];
__device__ float g_k  [(size_t)2*Bb*Hh*Nn*HDd];
__device__ float g_v  [(size_t)2*Bb*Hh*Nn*HDd];
__device__ float g_tmp[(size_t)M2*Dd];
__device__ float g_h  [(size_t)M2*2*Dd];
// pre-rounded weights
__device__ float w_qkv [768*256];
__device__ float w_out [256*256];
__device__ float w_s1  [512*512];
__device__ float w_s2  [256*512];
__device__ float w_cqkv[512*256];
__device__ float w_co  [256*256];
__device__ float w_c1  [512*512];
__device__ float w_c2  [256*512];

__device__ __forceinline__ float tf32f(float x){
    float y; asm("cvt.rna.tf32.f32 %0, %1;" : "=f"(y) : "f"(x)); return y;
}

// ---------------- cp.async helpers ----------------
__device__ __forceinline__ void cpa16(uint32_t s, const void* g){
    asm volatile("cp.async.cg.shared.global [%0], [%1], 16;\n" :: "r"(s), "l"(g));
}
__device__ __forceinline__ void cpa_commit(){ asm volatile("cp.async.commit_group;\n"); }
template<int N> __device__ __forceinline__ void cpa_wait(){
    asm volatile("cp.async.wait_group %0;\n" :: "n"(N));
}
__device__ __forceinline__ uint32_t smem_u32(const void* p){
    uint32_t a;
    asm("{ .reg .u64 t; cvta.to.shared.u64 t, %1; cvt.u32.u64 %0, t; }" : "=r"(a) : "l"(p));
    return a;
}

// ---------------- mma.sync m16n8k8 tf32 ----------------
__device__ __forceinline__ void mma_tf32(float* c, const float* a, const float* b){
    asm volatile(
      "mma.sync.aligned.m16n8k8.row.col.f32.tf32.tf32.f32 "
      "{%0,%1,%2,%3},{%4,%5,%6,%7},{%8,%9},{%0,%1,%2,%3};\n"
      : "+f"(c[0]),"+f"(c[1]),"+f"(c[2]),"+f"(c[3])
      : "r"(__float_as_uint(a[0])),"r"(__float_as_uint(a[1])),
        "r"(__float_as_uint(a[2])),"r"(__float_as_uint(a[3])),
        "r"(__float_as_uint(b[0])),"r"(__float_as_uint(b[1])));
}

// ---------------- NT tf32 GEMM (unchanged from R8) ----------------
#define GLD 20
#define MG_SMEM (3*128*GLD*2*4)
__global__ void __launch_bounds__(128,2)
mgemm(const float* __restrict__ A, const float* __restrict__ A2, int lda,
      const float* __restrict__ W, int ldb,
      float* __restrict__ C, int ldc,
      const float* __restrict__ bias, const float* __restrict__ bias2,
      const float* __restrict__ Res, int ldr,
      int K, int round_out, float* __restrict__ Cr)
{
    extern __shared__ float dsm[];
    float (*As)[128][GLD] = reinterpret_cast<float(*)[128][GLD]>(dsm);
    float (*Bs)[128][GLD] = reinterpret_cast<float(*)[128][GLD]>(dsm + 3*128*GLD);

    const int bm = blockIdx.y*128, bn = blockIdx.x*128;
    const int tid = threadIdx.x, warp = tid>>5, lane = tid&31;
    const int wm = warp>>1, wn = warp&1;
    const int gq = lane>>2, tq = lane&3;

    float acc[4][8][4];
    #pragma unroll
    for (int m=0;m<4;m++)
        #pragma unroll
        for (int n=0;n<8;n++){
            acc[m][n][0]=0.f; acc[m][n][1]=0.f; acc[m][n][2]=0.f; acc[m][n][3]=0.f;
        }

    auto ld_tile = [&](int st, int k0){
        const float* Ab; int ka;
        if (A2 && k0 >= 256){ Ab = A2; ka = k0 - 256; } else { Ab = A; ka = k0; }
        #pragma unroll
        for (int i=0;i<4;i++){
            int id = tid + i*128;
            int row = id>>2, c4 = id&3;
            cpa16(smem_u32(&As[st][row][c4*4]), Ab + (size_t)(bm+row)*((A2)?256:lda) + ka + c4*4);
        }
        #pragma unroll
        for (int i=0;i<4;i++){
            int id = tid + i*128;
            int row = id>>2, c4 = id&3;
            cpa16(smem_u32(&Bs[st][row][c4*4]), W + (size_t)(bn+row)*ldb + k0 + c4*4);
        }
        cpa_commit();
    };

    const int KT = K/16;
    ld_tile(0, 0);
    ld_tile(1, 16);

    for (int kt=0; kt<KT; kt++){
        const int buf = kt%3;
        if (kt+1 < KT) cpa_wait<1>(); else cpa_wait<0>();
        __syncthreads();
        if (kt+2 < KT) ld_tile((kt+2)%3, (kt+2)*16);
        #pragma unroll
        for (int ks=0; ks<16; ks+=8){
            float a[4][4], b[8][2];
            #pragma unroll
            for (int m=0;m<4;m++){
                a[m][0] = As[buf][wm*64 + m*16 + gq    ][ks + tq];
                a[m][1] = As[buf][wm*64 + m*16 + gq + 8][ks + tq];
                a[m][2] = As[buf][wm*64 + m*16 + gq    ][ks + tq + 4];
                a[m][3] = As[buf][wm*64 + m*16 + gq + 8][ks + tq + 4];
            }
            #pragma unroll
            for (int n=0;n<8;n++){
                b[n][0] = Bs[buf][wn*64 + n*8 + gq][ks + tq];
                b[n][1] = Bs[buf][wn*64 + n*8 + gq][ks + tq + 4];
            }
            #pragma unroll
            for (int m=0;m<4;m++)
                #pragma unroll
                for (int n=0;n<8;n++)
                    mma_tf32(acc[m][n], a[m], b[n]);
        }
    }

    #pragma unroll
    for (int m=0;m<4;m++){
        const int r0g = bm + wm*64 + m*16 + gq;
        #pragma unroll
        for (int n=0;n<8;n++){
            const int cg = bn + wn*64 + n*8 + 2*tq;
            float v0=acc[m][n][0], v1=acc[m][n][1], v2=acc[m][n][2], v3=acc[m][n][3];
            if (bias){
                float b0, b1;
                if (bias2 && cg >= 256){ b0 = bias2[cg-256]; b1 = bias2[cg-255]; }
                else                   { b0 = bias[cg];      b1 = bias[cg+1];    }
                v0+=b0; v1+=b1; v2+=b0; v3+=b1;
            }
            if (Res){
                const float* rp0 = Res + (size_t)r0g*ldr + cg;
                const float* rp1 = Res + (size_t)(r0g+8)*ldr + cg;
                v0+=rp0[0]; v1+=rp0[1]; v2+=rp1[0]; v3+=rp1[1];
            }
            float2 w0, w1;
            if (round_out){ w0.x=tf32f(v0); w0.y=tf32f(v1); w1.x=tf32f(v2); w1.y=tf32f(v3); }
            else          { w0.x=v0; w0.y=v1; w1.x=v2; w1.y=v3; }
            *reinterpret_cast<float2*>(C + (size_t)r0g*ldc + cg)     = w0;
            *reinterpret_cast<float2*>(C + (size_t)(r0g+8)*ldc + cg) = w1;
            if (Cr){
                float2 q0, q1;
                q0.x=tf32f(v0); q0.y=tf32f(v1); q1.x=tf32f(v2); q1.y=tf32f(v3);
                *reinterpret_cast<float2*>(Cr + (size_t)r0g*ldc + cg)     = q0;
                *reinterpret_cast<float2*>(Cr + (size_t)(r0g+8)*ldc + cg) = q1;
            }
        }
    }
}

// ---------------- flash attention v2: 4 warps x 32 q-rows ----------------
// Each warp owns 32 q-rows (two m16 groups), so K/V b-fragments are reused
// across both groups — ~45% less LDS per FLOP than R8.
#define QP_LD 68
#define KV_LD 68
#define FA_SMEM ((128*QP_LD + 2*64*KV_LD + 2*64*KV_LD)*4)

__global__ void __launch_bounds__(128,2)
flash_k(const float* __restrict__ Qb, const float* __restrict__ Kb,
        const float* __restrict__ Vb, float* __restrict__ Ob, int mode)
{
    extern __shared__ float smf[];
    float* QP = smf;
    float* Ks = smf + 128*QP_LD;
    float* Vs = Ks + 2*64*KV_LD;

    const int z = blockIdx.y, it = blockIdx.x;
    const int tid = threadIdx.x, warp = tid>>5, lane = tid&31;
    const int gq = lane>>2, tq = lane&3;

    size_t qoff, kvoff, ooff;
    int ld;
    if (mode == 0){
        qoff = (size_t)z*Nn*HDd; kvoff = qoff;
        ooff = (size_t)(z>>2)*Nn*Dd + (size_t)(z&3)*HDd;
        ld = HDd;
    } else {
        int h = z>>4, zz = z&15;
        size_t f = (size_t)(zz>>2)*Nn*512 + (size_t)(zz&3)*HDd;
        qoff  = (size_t)h*((size_t)Bb*Nn*512) + f;
        kvoff = (size_t)(1-h)*((size_t)Bb*Nn*512) + f;
        ooff  = (size_t)h*BND + (size_t)(zz>>2)*Nn*Dd + (size_t)(zz&3)*HDd;
        ld = 512;
    }

    const float* Q = Qb + qoff + (size_t)it*128*ld;
    const float* K = Kb + kvoff;
    const float* V = Vb + kvoff;
    float* O = Ob + ooff + (size_t)it*128*Dd;

    // K/V loader for 128 threads: 64 rows x 64 floats each
    const int kr = tid>>4, kc = (tid&15)*4;
    auto load_kv = [&](int buf, int j0){
        #pragma unroll
        for (int itr=0; itr<8; itr++){
            int row = kr + itr*8;
            cpa16(smem_u32(Ks + ((size_t)buf*64 + row)*KV_LD + kc), K + (size_t)(j0+row)*ld + kc);
        }
        #pragma unroll
        for (int itr=0; itr<8; itr++){
            int row = kr + itr*8;
            cpa16(smem_u32(Vs + ((size_t)buf*64 + row)*KV_LD + kc), V + (size_t)(j0+row)*ld + kc);
        }
        cpa_commit();
    };

    load_kv(0, 0);

    // stage Q (pre-rounded inputs; *0.125 exact)
    #pragma unroll
    for (int r=0;r<16;r++){
        int idx = tid + r*128;
        int row = idx>>4, c4 = idx&15;
        float4 qv = *reinterpret_cast<const float4*>(Q + (size_t)row*ld + c4*4);
        QP[row*QP_LD + c4*4+0] = qv.x*0.125f;
        QP[row*QP_LD + c4*4+1] = qv.y*0.125f;
        QP[row*QP_LD + c4*4+2] = qv.z*0.125f;
        QP[row*QP_LD + c4*4+3] = qv.w*0.125f;
    }
    __syncthreads();

    // Q a-fragments for 2 row-groups, kept in registers the whole loop
    const int r0 = warp*32 + gq;      // group 0: rows r0, r0+8 ; group 1: +16
    float aq[2][8][4];
    #pragma unroll
    for (int g=0; g<2; g++){
        int rg = r0 + g*16;
        #pragma unroll
        for (int kk=0;kk<8;kk++){
            aq[g][kk][0] = QP[ rg    *QP_LD + kk*8 + tq];
            aq[g][kk][1] = QP[(rg+8)*QP_LD + kk*8 + tq];
            aq[g][kk][2] = QP[ rg    *QP_LD + kk*8 + tq + 4];
            aq[g][kk][3] = QP[(rg+8)*QP_LD + kk*8 + tq + 4];
        }
    }

    float o[2][8][4];
    #pragma unroll
    for (int g=0;g<2;g++)
        #pragma unroll
        for (int i=0;i<8;i++){ o[g][i][0]=0.f;o[g][i][1]=0.f;o[g][i][2]=0.f;o[g][i][3]=0.f; }
    float mrow[4] = {-1e30f,-1e30f,-1e30f,-1e30f};
    float lrow[4] = {0.f,0.f,0.f,0.f};

    const int NT = Nn/64;
    for (int j=0;j<NT;j++){
        const int buf = j&1;
        cpa_wait<0>();          // only tile j in flight
        __syncthreads();        // all warps done with previous tile + data visible
        if (j+1 < NT) load_kv(buf^1, (j+1)*64);   // safe: everyone past prev tile

        const float* Kb_ = Ks + (size_t)buf*64*KV_LD;
        const float* Vb_ = Vs + (size_t)buf*64*KV_LD;

        // S = (Q*scale) K^T for both row groups; K b-frags loaded once
        float c[2][8][4];
        #pragma unroll
        for (int nf=0;nf<8;nf++){
            #pragma unroll
            for (int g=0;g<2;g++){ c[g][nf][0]=0.f;c[g][nf][1]=0.f;c[g][nf][2]=0.f;c[g][nf][3]=0.f; }
            #pragma unroll
            for (int kk=0;kk<8;kk++){
                float b[2];
                b[0] = Kb_[(nf*8+gq)*KV_LD + kk*8 + tq];
                b[1] = Kb_[(nf*8+gq)*KV_LD + kk*8 + tq + 4];
                mma_tf32(c[0][nf], aq[0][kk], b);
                mma_tf32(c[1][nf], aq[1][kk], b);
            }
        }

        // online softmax per row group
        #pragma unroll
        for (int g=0;g<2;g++){
            float mx0=-1e30f, mx1=-1e30f;
            #pragma unroll
            for (int nf=0;nf<8;nf++){
                mx0 = fmaxf(mx0, fmaxf(c[g][nf][0], c[g][nf][1]));
                mx1 = fmaxf(mx1, fmaxf(c[g][nf][2], c[g][nf][3]));
            }
            mx0 = fmaxf(mx0, __shfl_xor_sync(0xffffffffu, mx0, 1));
            mx0 = fmaxf(mx0, __shfl_xor_sync(0xffffffffu, mx0, 2));
            mx1 = fmaxf(mx1, __shfl_xor_sync(0xffffffffu, mx1, 1));
            mx1 = fmaxf(mx1, __shfl_xor_sync(0xffffffffu, mx1, 2));
            float nm0 = fmaxf(mrow[g*2],   mx0);
            float nm1 = fmaxf(mrow[g*2+1], mx1);
            float al0 = __expf(mrow[g*2]  -nm0);
            float al1 = __expf(mrow[g*2+1]-nm1);
            float s0=0.f, s1=0.f;
            #pragma unroll
            for (int nf=0;nf<8;nf++){
                c[g][nf][0]=__expf(c[g][nf][0]-nm0); c[g][nf][1]=__expf(c[g][nf][1]-nm0);
                c[g][nf][2]=__expf(c[g][nf][2]-nm1); c[g][nf][3]=__expf(c[g][nf][3]-nm1);
                s0 += c[g][nf][0]+c[g][nf][1]; s1 += c[g][nf][2]+c[g][nf][3];
            }
            s0 += __shfl_xor_sync(0xffffffffu, s0, 1);
            s0 += __shfl_xor_sync(0xffffffffu, s0, 2);
            s1 += __shfl_xor_sync(0xffffffffu, s1, 1);
            s1 += __shfl_xor_sync(0xffffffffu, s1, 2);
            lrow[g*2]   = lrow[g*2]*al0   + s0;
            lrow[g*2+1] = lrow[g*2+1]*al1 + s1;
            mrow[g*2] = nm0; mrow[g*2+1] = nm1;
            #pragma unroll
            for (int nd=0;nd<8;nd++){
                o[g][nd][0]*=al0; o[g][nd][1]*=al0; o[g][nd][2]*=al1; o[g][nd][3]*=al1;
            }
            // P -> smem (warp-local rows), paired STS.64
            int rg = r0 + g*16;
            #pragma unroll
            for (int nf=0;nf<8;nf++){
                float2 p0; p0.x = c[g][nf][0]; p0.y = c[g][nf][1];
                float2 p1; p1.x = c[g][nf][2]; p1.y = c[g][nf][3];
                *reinterpret_cast<float2*>(&QP[ rg    *QP_LD + nf*8 + 2*tq]) = p0;
                *reinterpret_cast<float2*>(&QP[(rg+8)*QP_LD + nf*8 + 2*tq]) = p1;
            }
        }
        __syncwarp();

        // O += P V ; V b-frags loaded once, reused across both groups
        #pragma unroll
        for (int kk=0;kk<8;kk++){
            float ap[2][4];
            #pragma unroll
            for (int g=0;g<2;g++){
                int rg = r0 + g*16;
                ap[g][0] = QP[ rg    *QP_LD + kk*8 + tq];
                ap[g][1] = QP[(rg+8)*QP_LD + kk*8 + tq];
                ap[g][2] = QP[ rg    *QP_LD + kk*8 + tq + 4];
                ap[g][3] = QP[(rg+8)*QP_LD + kk*8 + tq + 4];
            }
            #pragma unroll
            for (int nd=0;nd<8;nd++){
                float b[2];
                b[0] = Vb_[(kk*8+tq  )*KV_LD + nd*8 + gq];
                b[1] = Vb_[(kk*8+tq+4)*KV_LD + nd*8 + gq];
                mma_tf32(o[0][nd], ap[0], b);
                mma_tf32(o[1][nd], ap[1], b);
            }
        }
        __syncthreads();   // all warps done reading buf before it's overwritten next iter
    }

    #pragma unroll
    for (int g=0;g<2;g++){
        int rg = r0 + g*16;
        const float inv0 = 1.f/lrow[g*2], inv1 = 1.f/lrow[g*2+1];
        #pragma unroll
        for (int nd=0;nd<8;nd++){
            float2 w0; w0.x = tf32f(o[g][nd][0]*inv0); w0.y = tf32f(o[g][nd][1]*inv0);
            float2 w1; w1.x = tf32f(o[g][nd][2]*inv1); w1.y = tf32f(o[g][nd][3]*inv1);
            *reinterpret_cast<float2*>(O + (size_t) rg   *Dd + nd*8 + 2*tq) = w0;
            *reinterpret_cast<float2*>(O + (size_t)(rg+8)*Dd + nd*8 + 2*tq) = w1;
        }
    }
}

// ---------------- prep: weights round + init x/xr (one launch) ----------------
__global__ void prep_k(const float* a,const float* b,const float* c,const float* d,
                       const float* e,const float* f,const float* g,const float* h,
                       const float* i, const float* d0, const float* d1)
{
    int t = blockIdx.x*blockDim.x + threadIdx.x;
    switch (blockIdx.y){
        case 0: if (t<196608) w_qkv[t]        = tf32f(a[t]); break;
        case 1: if (t<65536)  w_out[t]        = tf32f(b[t]); break;
        case 2: if (t<262144) w_s1[t]         = tf32f(c[t]); break;
        case 3: if (t<131072) w_s2[t]         = tf32f(d[t]); break;
        case 4: if (t<65536)  w_cqkv[t]       = tf32f(e[t]); break;
        case 5: if (t<65536)  w_cqkv[65536+t] = tf32f(f[t]); break;
        case 6: if (t<65536)  w_co[t]         = tf32f(g[t]); break;
        case 7: if (t<262144) w_c1[t]         = tf32f(h[t]); break;
        case 8: if (t<131072) w_c2[t]         = tf32f(i[t]); break;
        case 9:
            if (t < 2*(int)BND){
                float v = (t < (int)BND) ? d0[t] : d1[t-(int)BND];
                g_x[t] = v; g_xr[t] = tf32f(v);
            }
            break;
    }
}

__global__ void qkv_rope_k(const float* __restrict__ qkv,
                           const float* __restrict__ enc0,
                           const float* __restrict__ enc1,
                           float* __restrict__ Q, float* __restrict__ K,
                           float* __restrict__ V)
{
    int idx = blockIdx.x*blockDim.x + threadIdx.x;
    const int total = 2*Bb*Hh*Nn*(HDd/2);
    if (idx >= total) return;
    int p = idx % (HDd/2); int t = idx / (HDd/2);
    int n = t % Nn; t /= Nn;
    int h = t % Hh; t /= Hh;
    int b = t % Bb; int s = t / Bb;
    size_t r = (size_t)(s*Bb + b)*Nn + n;
    const float* row = qkv + r*(3*Dd);
    int d0 = 2*p, d1 = 2*p+1;
    float q0 = row[h*192 + d0*3 + 0], q1 = row[h*192 + d1*3 + 0];
    float k0 = row[h*192 + d0*3 + 1], k1 = row[h*192 + d1*3 + 1];
    float v0 = row[h*192 + d0*3 + 2], v1 = row[h*192 + d1*3 + 2];
    const float* enc = s ? enc1 : enc0;
    size_t eoff = ((size_t)b*Nn + n)*HDd;
    float c = enc[eoff + d0];
    float si = enc[(size_t)Bb*Nn*HDd + eoff + d0];
    float qo0 = q0*c - q1*si, qo1 = q1*c + q0*si;
    float ko0 = k0*c - k1*si, ko1 = k1*c + k0*si;
    size_t bh = (size_t)(s*Bb + b)*Hh + h;
    size_t o = (bh*Nn + n)*HDd;
    Q[o+d0]=tf32f(qo0); Q[o+d1]=tf32f(qo1);
    K[o+d0]=tf32f(ko0); K[o+d1]=tf32f(ko1);
    V[o+d0]=tf32f(v0);  V[o+d1]=tf32f(v1);
}

__global__ void ln_gelu_k(float* __restrict__ X, const float* __restrict__ g,
                          const float* __restrict__ be)
{
    float* p = X + (size_t)blockIdx.x * 512;
    int tid = threadIdx.x;
    float a = p[tid], b = p[tid+256];
    float s = a + b;
    float sq = a*a + b*b;
    #pragma unroll
    for (int o=16;o;o>>=1){ s += __shfl_xor_sync(0xffffffffu,s,o);
                            sq += __shfl_xor_sync(0xffffffffu,sq,o); }
    __shared__ float ss[8], sqs[8];
    if ((tid&31)==0){ ss[tid>>5]=s; sqs[tid>>5]=sq; }
    __syncthreads();
    s = 0.f; sq = 0.f;
    #pragma unroll
    for (int t=0;t<8;t++){ s+=ss[t]; sq+=sqs[t]; }
    float mean = s * (1.0f/512.0f);
    float var  = sq * (1.0f/512.0f) - mean*mean;
    float inv = rsqrtf(var + 1e-5f);
    float y0 = (a-mean)*inv*g[tid]     + be[tid];
    float y1 = (b-mean)*inv*g[tid+256] + be[tid+256];
    p[tid]     = tf32f(0.5f*y0*(1.0f+erff(y0*0.70710678118f)));
    p[tid+256] = tf32f(0.5f*y1*(1.0f+erff(y1*0.70710678118f)));
}

// ================= host orchestration =================
extern "C" void kernel_launch(void* const* d_in, const int* in_sizes, int n_in,
                              void* d_out, int out_size)
{
    const float* desc0  = (const float*)d_in[0];
    const float* desc1  = (const float*)d_in[1];
    const float* enc0   = (const float*)d_in[2];
    const float* enc1   = (const float*)d_in[3];
    const float* s_Wqkv = (const float*)d_in[4];
    const float* s_bqkv = (const float*)d_in[5];
    const float* s_Wout = (const float*)d_in[6];
    const float* s_bout = (const float*)d_in[7];
    const float* s_W1   = (const float*)d_in[8];
    const float* s_b1   = (const float*)d_in[9];
    const float* s_g    = (const float*)d_in[10];
    const float* s_be   = (const float*)d_in[11];
    const float* s_W2   = (const float*)d_in[12];
    const float* s_b2   = (const float*)d_in[13];
    const float* c_Wqk  = (const float*)d_in[14];
    const float* c_bqk  = (const float*)d_in[15];
    const float* c_Wv   = (const float*)d_in[16];
    const float* c_bv   = (const float*)d_in[17];
    const float* c_Wo   = (const float*)d_in[18];
    const float* c_bo   = (const float*)d_in[19];
    const float* c_W1   = (const float*)d_in[20];
    const float* c_b1   = (const float*)d_in[21];
    const float* c_g    = (const float*)d_in[22];
    const float* c_be   = (const float*)d_in[23];
    const float* c_W2   = (const float*)d_in[24];
    const float* c_b2   = (const float*)d_in[25];
    float* out = (float*)d_out;

    float *x,*xr,*qkv,*q,*k,*v,*tmp,*hb;
    float *wqkv,*wout,*ws1,*ws2,*wcqkv,*wco,*wc1,*wc2;
    cudaGetSymbolAddress((void**)&x,   g_x);
    cudaGetSymbolAddress((void**)&xr,  g_xr);
    cudaGetSymbolAddress((void**)&qkv, g_qkv);
    cudaGetSymbolAddress((void**)&q,   g_q);
    cudaGetSymbolAddress((void**)&k,   g_k);
    cudaGetSymbolAddress((void**)&v,   g_v);
    cudaGetSymbolAddress((void**)&tmp, g_tmp);
    cudaGetSymbolAddress((void**)&hb,  g_h);
    cudaGetSymbolAddress((void**)&wqkv, w_qkv);
    cudaGetSymbolAddress((void**)&wout, w_out);
    cudaGetSymbolAddress((void**)&ws1,  w_s1);
    cudaGetSymbolAddress((void**)&ws2,  w_s2);
    cudaGetSymbolAddress((void**)&wcqkv,w_cqkv);
    cudaGetSymbolAddress((void**)&wco,  w_co);
    cudaGetSymbolAddress((void**)&wc1,  w_c1);
    cudaGetSymbolAddress((void**)&wc2,  w_c2);

    cudaFuncSetAttribute(flash_k, cudaFuncAttributeMaxDynamicSharedMemorySize, FA_SMEM);
    cudaFuncSetAttribute(mgemm,   cudaFuncAttributeMaxDynamicSharedMemorySize, MG_SMEM);

    auto GE = [&](const float* A,const float* A2,int lda,const float* W,int ldb,
                  float* C,int ldc,const float* bias,const float* bias2,
                  const float* Res,int ldr,int M,int Nc,int K,int ro,float* Cr){
        dim3 gr(Nc/128, M/128);
        mgemm<<<gr,128,MG_SMEM>>>(A,A2,lda,W,ldb,C,ldc,bias,bias2,Res,ldr,K,ro,Cr);
    };

    // 1: prep (weights + x/xr init, one launch)
    {
        dim3 gr((2*(int)BND+255)/256, 10);
        prep_k<<<gr,256>>>(s_Wqkv,s_Wout,s_W1,s_W2,c_Wqk,c_Wv,c_Wo,c_W1,c_W2,desc0,desc1);
    }
    // 2: qkv
    GE(xr,nullptr,Dd, wqkv,Dd, qkv,3*Dd, s_bqkv,nullptr, nullptr,0, M2,3*Dd,Dd, 0,nullptr);
    // 3: rope
    {
        int total = 2*Bb*Hh*Nn*(HDd/2);
        qkv_rope_k<<<(total+255)/256,256>>>(qkv, enc0, enc1, q, k, v);
    }
    // 4: flash self -> tmp   [ncu window]
    {
        dim3 gr(Nn/128, 2*Bb*Hh);
        flash_k<<<gr,128,FA_SMEM>>>(q, k, v, tmp, 0);
    }
    // 5: msg = wout(tmp) -> qkv buffer (rounded)
    GE(tmp,nullptr,Dd, wout,Dd, qkv,Dd, s_bout,nullptr, nullptr,0, M2,Dd,Dd, 1,nullptr);
    // FFN: h = W1 @ [xr | msg]
    GE(xr,qkv,Dd, ws1,2*Dd, hb,2*Dd, s_b1,nullptr, nullptr,0, M2,2*Dd,2*Dd, 0,nullptr);
    ln_gelu_k<<<M2,256>>>(hb, s_g, s_be);
    GE(hb,nullptr,2*Dd, ws2,2*Dd, x,Dd, s_b2,nullptr, x,Dd, M2,Dd,2*Dd, 0,xr);

    // ======== CROSS block ========
    GE(xr,nullptr,Dd, wcqkv,Dd, hb,512, c_bqk,c_bv, nullptr,0, M2,512,Dd, 1,nullptr);
    {
        dim3 gr(Nn/128, 2*Bb*Hh);
        flash_k<<<gr,128,FA_SMEM>>>(hb, hb, hb+256, qkv, 1);
    }
    GE(qkv,nullptr,Dd, wco,Dd, tmp,Dd, c_bo,nullptr, nullptr,0, M2,Dd,Dd, 1,nullptr);
    GE(xr,tmp,Dd, wc1,2*Dd, hb,2*Dd, c_b1,nullptr, nullptr,0, M2,2*Dd,2*Dd, 0,nullptr);
    ln_gelu_k<<<M2,256>>>(hb, c_g, c_be);
    GE(hb,nullptr,2*Dd, wc2,2*Dd, out,Dd, c_b2,nullptr, x,Dd, M2,Dd,2*Dd, 0,nullptr);
}

// round 10
// speedup vs baseline: 4.0898x; 1.0343x over previous
#include <cuda_runtime.h>
#include <math.h>
#include <stdint.h>

#define Bb 4
#define Nn 2048
#define Dd 256
#define Hh 4
#define HDd 64
#define M2 (2*Bb*Nn)
#define BND ((size_t)Bb*Nn*Dd)

// ---------------- static scratch ----------------
__device__ float g_x  [(size_t)M2*Dd];
__device__ float g_xr [(size_t)M2*Dd];
__device__ float g_qkv[(size_t)M2*3*Dd];
__device__ float g_q  [(size_t)2*Bb*Hh*Nn*HDd];
__device__ float g_k  [(size_t)2*Bb*Hh*Nn*HDd];
__device__ float g_v  [(size_t)2*Bb*Hh*Nn*HDd];
__device__ float g_tmp[(size_t)M2*Dd];
__device__ float g_h  [(size_t)M2*2*Dd];
// pre-rounded weights
__device__ float w_qkv [768*256];
__device__ float w_out [256*256];
__device__ float w_s1  [512*512];
__device__ float w_s2  [256*512];
__device__ float w_cqkv[512*256];
__device__ float w_co  [256*256];
__device__ float w_c1  [512*512];
__device__ float w_c2  [256*512];

__device__ __forceinline__ float tf32f(float x){
    float y; asm("cvt.rna.tf32.f32 %0, %1;" : "=f"(y) : "f"(x)); return y;
}

// ---------------- cp.async helpers ----------------
__device__ __forceinline__ void cpa16(uint32_t s, const void* g){
    asm volatile("cp.async.cg.shared.global [%0], [%1], 16;\n" :: "r"(s), "l"(g));
}
__device__ __forceinline__ void cpa_commit(){ asm volatile("cp.async.commit_group;\n"); }
template<int N> __device__ __forceinline__ void cpa_wait(){
    asm volatile("cp.async.wait_group %0;\n" :: "n"(N));
}
__device__ __forceinline__ uint32_t smem_u32(const void* p){
    uint32_t a;
    asm("{ .reg .u64 t; cvta.to.shared.u64 t, %1; cvt.u32.u64 %0, t; }" : "=r"(a) : "l"(p));
    return a;
}

// ---------------- mma.sync m16n8k8 tf32 ----------------
__device__ __forceinline__ void mma_tf32(float* c, const float* a, const float* b){
    asm volatile(
      "mma.sync.aligned.m16n8k8.row.col.f32.tf32.tf32.f32 "
      "{%0,%1,%2,%3},{%4,%5,%6,%7},{%8,%9},{%0,%1,%2,%3};\n"
      : "+f"(c[0]),"+f"(c[1]),"+f"(c[2]),"+f"(c[3])
      : "r"(__float_as_uint(a[0])),"r"(__float_as_uint(a[1])),
        "r"(__float_as_uint(a[2])),"r"(__float_as_uint(a[3])),
        "r"(__float_as_uint(b[0])),"r"(__float_as_uint(b[1])));
}

// ---------------- NT tf32 GEMM: 128x128 CTA, 4 warps (64x64 each) ----------------
// k-lane remap: lane tq <-> col 2tq, lane tq+4 <-> col 2tq+1  (same 8-col set
// per k-block; bitwise-identical result) so a/b fragment loads are LDS.64.
#define GLD 24
#define MG_SMEM (3*128*GLD*2*4)
__global__ void __launch_bounds__(128,2)
mgemm(const float* __restrict__ A, const float* __restrict__ A2, int lda,
      const float* __restrict__ W, int ldb,
      float* __restrict__ C, int ldc,
      const float* __restrict__ bias, const float* __restrict__ bias2,
      const float* __restrict__ Res, int ldr,
      int K, int round_out, float* __restrict__ Cr)
{
    extern __shared__ float dsm[];
    float (*As)[128][GLD] = reinterpret_cast<float(*)[128][GLD]>(dsm);
    float (*Bs)[128][GLD] = reinterpret_cast<float(*)[128][GLD]>(dsm + 3*128*GLD);

    const int bm = blockIdx.y*128, bn = blockIdx.x*128;
    const int tid = threadIdx.x, warp = tid>>5, lane = tid&31;
    const int wm = warp>>1, wn = warp&1;
    const int gq = lane>>2, tq = lane&3;

    float acc[4][8][4];
    #pragma unroll
    for (int m=0;m<4;m++)
        #pragma unroll
        for (int n=0;n<8;n++){
            acc[m][n][0]=0.f; acc[m][n][1]=0.f; acc[m][n][2]=0.f; acc[m][n][3]=0.f;
        }

    auto ld_tile = [&](int st, int k0){
        const float* Ab; int ka;
        if (A2 && k0 >= 256){ Ab = A2; ka = k0 - 256; } else { Ab = A; ka = k0; }
        #pragma unroll
        for (int i=0;i<4;i++){
            int id = tid + i*128;
            int row = id>>2, c4 = id&3;
            cpa16(smem_u32(&As[st][row][c4*4]), Ab + (size_t)(bm+row)*((A2)?256:lda) + ka + c4*4);
        }
        #pragma unroll
        for (int i=0;i<4;i++){
            int id = tid + i*128;
            int row = id>>2, c4 = id&3;
            cpa16(smem_u32(&Bs[st][row][c4*4]), W + (size_t)(bn+row)*ldb + k0 + c4*4);
        }
        cpa_commit();
    };

    const int KT = K/16;
    ld_tile(0, 0);
    ld_tile(1, 16);

    for (int kt=0; kt<KT; kt++){
        const int buf = kt%3;
        if (kt+1 < KT) cpa_wait<1>(); else cpa_wait<0>();
        __syncthreads();
        if (kt+2 < KT) ld_tile((kt+2)%3, (kt+2)*16);
        #pragma unroll
        for (int ks=0; ks<16; ks+=8){
            float a[4][4], b[8][2];
            #pragma unroll
            for (int m=0;m<4;m++){
                float2 a02 = *reinterpret_cast<const float2*>(&As[buf][wm*64 + m*16 + gq    ][ks + 2*tq]);
                float2 a13 = *reinterpret_cast<const float2*>(&As[buf][wm*64 + m*16 + gq + 8][ks + 2*tq]);
                a[m][0]=a02.x; a[m][2]=a02.y; a[m][1]=a13.x; a[m][3]=a13.y;
            }
            #pragma unroll
            for (int n=0;n<8;n++){
                float2 bb = *reinterpret_cast<const float2*>(&Bs[buf][wn*64 + n*8 + gq][ks + 2*tq]);
                b[n][0]=bb.x; b[n][1]=bb.y;
            }
            #pragma unroll
            for (int m=0;m<4;m++)
                #pragma unroll
                for (int n=0;n<8;n++)
                    mma_tf32(acc[m][n], a[m], b[n]);
        }
    }

    #pragma unroll
    for (int m=0;m<4;m++){
        const int r0g = bm + wm*64 + m*16 + gq;
        #pragma unroll
        for (int n=0;n<8;n++){
            const int cg = bn + wn*64 + n*8 + 2*tq;
            float v0=acc[m][n][0], v1=acc[m][n][1], v2=acc[m][n][2], v3=acc[m][n][3];
            if (bias){
                float b0, b1;
                if (bias2 && cg >= 256){ b0 = bias2[cg-256]; b1 = bias2[cg-255]; }
                else                   { b0 = bias[cg];      b1 = bias[cg+1];    }
                v0+=b0; v1+=b1; v2+=b0; v3+=b1;
            }
            if (Res){
                const float* rp0 = Res + (size_t)r0g*ldr + cg;
                const float* rp1 = Res + (size_t)(r0g+8)*ldr + cg;
                v0+=rp0[0]; v1+=rp0[1]; v2+=rp1[0]; v3+=rp1[1];
            }
            float2 w0, w1;
            if (round_out){ w0.x=tf32f(v0); w0.y=tf32f(v1); w1.x=tf32f(v2); w1.y=tf32f(v3); }
            else          { w0.x=v0; w0.y=v1; w1.x=v2; w1.y=v3; }
            *reinterpret_cast<float2*>(C + (size_t)r0g*ldc + cg)     = w0;
            *reinterpret_cast<float2*>(C + (size_t)(r0g+8)*ldc + cg) = w1;
            if (Cr){
                float2 q0, q1;
                q0.x=tf32f(v0); q0.y=tf32f(v1); q1.x=tf32f(v2); q1.y=tf32f(v3);
                *reinterpret_cast<float2*>(Cr + (size_t)r0g*ldc + cg)     = q0;
                *reinterpret_cast<float2*>(Cr + (size_t)(r0g+8)*ldc + cg) = q1;
            }
        }
    }
}

// ---------------- flash attention: 4 warps x 32 q-rows, k-lane remap ----------------
#define QP_LD 72
#define KV_LD 72
#define FA_SMEM ((128*QP_LD + 2*64*KV_LD + 2*64*KV_LD)*4)

__global__ void __launch_bounds__(128,2)
flash_k(const float* __restrict__ Qb, const float* __restrict__ Kb,
        const float* __restrict__ Vb, float* __restrict__ Ob, int mode)
{
    extern __shared__ float smf[];
    float* QP = smf;
    float* Ks = smf + 128*QP_LD;
    float* Vs = Ks + 2*64*KV_LD;

    const int z = blockIdx.y, it = blockIdx.x;
    const int tid = threadIdx.x, warp = tid>>5, lane = tid&31;
    const int gq = lane>>2, tq = lane&3;

    size_t qoff, kvoff, ooff;
    int ld;
    if (mode == 0){
        qoff = (size_t)z*Nn*HDd; kvoff = qoff;
        ooff = (size_t)(z>>2)*Nn*Dd + (size_t)(z&3)*HDd;
        ld = HDd;
    } else {
        int h = z>>4, zz = z&15;
        size_t f = (size_t)(zz>>2)*Nn*512 + (size_t)(zz&3)*HDd;
        qoff  = (size_t)h*((size_t)Bb*Nn*512) + f;
        kvoff = (size_t)(1-h)*((size_t)Bb*Nn*512) + f;
        ooff  = (size_t)h*BND + (size_t)(zz>>2)*Nn*Dd + (size_t)(zz&3)*HDd;
        ld = 512;
    }

    const float* Q = Qb + qoff + (size_t)it*128*ld;
    const float* K = Kb + kvoff;
    const float* V = Vb + kvoff;
    float* O = Ob + ooff + (size_t)it*128*Dd;

    const int kr = tid>>4, kc = (tid&15)*4;
    auto load_kv = [&](int buf, int j0){
        #pragma unroll
        for (int itr=0; itr<8; itr++){
            int row = kr + itr*8;
            cpa16(smem_u32(Ks + ((size_t)buf*64 + row)*KV_LD + kc), K + (size_t)(j0+row)*ld + kc);
        }
        #pragma unroll
        for (int itr=0; itr<8; itr++){
            int row = kr + itr*8;
            cpa16(smem_u32(Vs + ((size_t)buf*64 + row)*KV_LD + kc), V + (size_t)(j0+row)*ld + kc);
        }
        cpa_commit();
    };

    load_kv(0, 0);

    #pragma unroll
    for (int r=0;r<16;r++){
        int idx = tid + r*128;
        int row = idx>>4, c4 = idx&15;
        float4 qv = *reinterpret_cast<const float4*>(Q + (size_t)row*ld + c4*4);
        QP[row*QP_LD + c4*4+0] = qv.x*0.125f;
        QP[row*QP_LD + c4*4+1] = qv.y*0.125f;
        QP[row*QP_LD + c4*4+2] = qv.z*0.125f;
        QP[row*QP_LD + c4*4+3] = qv.w*0.125f;
    }
    __syncthreads();

    // Q a-fragments with k-lane remap: lane tq -> col 2tq, lane tq+4 -> col 2tq+1
    const int r0 = warp*32 + gq;
    float aq[2][8][4];
    #pragma unroll
    for (int g=0; g<2; g++){
        int rg = r0 + g*16;
        #pragma unroll
        for (int kk=0;kk<8;kk++){
            float2 q02 = *reinterpret_cast<const float2*>(&QP[ rg    *QP_LD + kk*8 + 2*tq]);
            float2 q13 = *reinterpret_cast<const float2*>(&QP[(rg+8)*QP_LD + kk*8 + 2*tq]);
            aq[g][kk][0]=q02.x; aq[g][kk][2]=q02.y;
            aq[g][kk][1]=q13.x; aq[g][kk][3]=q13.y;
        }
    }

    float o[2][8][4];
    #pragma unroll
    for (int g=0;g<2;g++)
        #pragma unroll
        for (int i=0;i<8;i++){ o[g][i][0]=0.f;o[g][i][1]=0.f;o[g][i][2]=0.f;o[g][i][3]=0.f; }
    float mrow[4] = {-1e30f,-1e30f,-1e30f,-1e30f};
    float lrow[4] = {0.f,0.f,0.f,0.f};

    const int NT = Nn/64;
    for (int j=0;j<NT;j++){
        const int buf = j&1;
        cpa_wait<0>();
        __syncthreads();
        if (j+1 < NT) load_kv(buf^1, (j+1)*64);

        const float* Kb_ = Ks + (size_t)buf*64*KV_LD;
        const float* Vb_ = Vs + (size_t)buf*64*KV_LD;

        // S = (Q*scale) K^T ; K b-frags as LDS.64 via remap
        float c[2][8][4];
        #pragma unroll
        for (int nf=0;nf<8;nf++){
            #pragma unroll
            for (int g=0;g<2;g++){ c[g][nf][0]=0.f;c[g][nf][1]=0.f;c[g][nf][2]=0.f;c[g][nf][3]=0.f; }
            #pragma unroll
            for (int kk=0;kk<8;kk++){
                float2 bb = *reinterpret_cast<const float2*>(&Kb_[(nf*8+gq)*KV_LD + kk*8 + 2*tq]);
                float b[2] = {bb.x, bb.y};
                mma_tf32(c[0][nf], aq[0][kk], b);
                mma_tf32(c[1][nf], aq[1][kk], b);
            }
        }

        #pragma unroll
        for (int g=0;g<2;g++){
            float mx0=-1e30f, mx1=-1e30f;
            #pragma unroll
            for (int nf=0;nf<8;nf++){
                mx0 = fmaxf(mx0, fmaxf(c[g][nf][0], c[g][nf][1]));
                mx1 = fmaxf(mx1, fmaxf(c[g][nf][2], c[g][nf][3]));
            }
            mx0 = fmaxf(mx0, __shfl_xor_sync(0xffffffffu, mx0, 1));
            mx0 = fmaxf(mx0, __shfl_xor_sync(0xffffffffu, mx0, 2));
            mx1 = fmaxf(mx1, __shfl_xor_sync(0xffffffffu, mx1, 1));
            mx1 = fmaxf(mx1, __shfl_xor_sync(0xffffffffu, mx1, 2));
            float nm0 = fmaxf(mrow[g*2],   mx0);
            float nm1 = fmaxf(mrow[g*2+1], mx1);
            float al0 = __expf(mrow[g*2]  -nm0);
            float al1 = __expf(mrow[g*2+1]-nm1);
            float s0=0.f, s1=0.f;
            #pragma unroll
            for (int nf=0;nf<8;nf++){
                c[g][nf][0]=__expf(c[g][nf][0]-nm0); c[g][nf][1]=__expf(c[g][nf][1]-nm0);
                c[g][nf][2]=__expf(c[g][nf][2]-nm1); c[g][nf][3]=__expf(c[g][nf][3]-nm1);
                s0 += c[g][nf][0]+c[g][nf][1]; s1 += c[g][nf][2]+c[g][nf][3];
            }
            s0 += __shfl_xor_sync(0xffffffffu, s0, 1);
            s0 += __shfl_xor_sync(0xffffffffu, s0, 2);
            s1 += __shfl_xor_sync(0xffffffffu, s1, 1);
            s1 += __shfl_xor_sync(0xffffffffu, s1, 2);
            lrow[g*2]   = lrow[g*2]*al0   + s0;
            lrow[g*2+1] = lrow[g*2+1]*al1 + s1;
            mrow[g*2] = nm0; mrow[g*2+1] = nm1;
            #pragma unroll
            for (int nd=0;nd<8;nd++){
                o[g][nd][0]*=al0; o[g][nd][1]*=al0; o[g][nd][2]*=al1; o[g][nd][3]*=al1;
            }
            int rg = r0 + g*16;
            #pragma unroll
            for (int nf=0;nf<8;nf++){
                float2 p0; p0.x = c[g][nf][0]; p0.y = c[g][nf][1];
                float2 p1; p1.x = c[g][nf][2]; p1.y = c[g][nf][3];
                *reinterpret_cast<float2*>(&QP[ rg    *QP_LD + nf*8 + 2*tq]) = p0;
                *reinterpret_cast<float2*>(&QP[(rg+8)*QP_LD + nf*8 + 2*tq]) = p1;
            }
        }
        __syncwarp();

        // O += P V ; k-lane remap: lane tq -> P col/V row kk*8+2tq, lane tq+4 -> +1
        #pragma unroll
        for (int kk=0;kk<8;kk++){
            float ap[2][4];
            #pragma unroll
            for (int g=0;g<2;g++){
                int rg = r0 + g*16;
                float2 p02 = *reinterpret_cast<const float2*>(&QP[ rg    *QP_LD + kk*8 + 2*tq]);
                float2 p13 = *reinterpret_cast<const float2*>(&QP[(rg+8)*QP_LD + kk*8 + 2*tq]);
                ap[g][0]=p02.x; ap[g][2]=p02.y; ap[g][1]=p13.x; ap[g][3]=p13.y;
            }
            #pragma unroll
            for (int nd=0;nd<8;nd++){
                float b[2];
                b[0] = Vb_[(kk*8+2*tq  )*KV_LD + nd*8 + gq];
                b[1] = Vb_[(kk*8+2*tq+1)*KV_LD + nd*8 + gq];
                mma_tf32(o[0][nd], ap[0], b);
                mma_tf32(o[1][nd], ap[1], b);
            }
        }
        __syncthreads();
    }

    #pragma unroll
    for (int g=0;g<2;g++){
        int rg = r0 + g*16;
        const float inv0 = 1.f/lrow[g*2], inv1 = 1.f/lrow[g*2+1];
        #pragma unroll
        for (int nd=0;nd<8;nd++){
            float2 w0; w0.x = tf32f(o[g][nd][0]*inv0); w0.y = tf32f(o[g][nd][1]*inv0);
            float2 w1; w1.x = tf32f(o[g][nd][2]*inv1); w1.y = tf32f(o[g][nd][3]*inv1);
            *reinterpret_cast<float2*>(O + (size_t) rg   *Dd + nd*8 + 2*tq) = w0;
            *reinterpret_cast<float2*>(O + (size_t)(rg+8)*Dd + nd*8 + 2*tq) = w1;
        }
    }
}

// ---------------- prep: weights round + init x/xr (one launch) ----------------
__global__ void prep_k(const float* a,const float* b,const float* c,const float* d,
                       const float* e,const float* f,const float* g,const float* h,
                       const float* i, const float* d0, const float* d1)
{
    int t = blockIdx.x*blockDim.x + threadIdx.x;
    switch (blockIdx.y){
        case 0: if (t<196608) w_qkv[t]        = tf32f(a[t]); break;
        case 1: if (t<65536)  w_out[t]        = tf32f(b[t]); break;
        case 2: if (t<262144) w_s1[t]         = tf32f(c[t]); break;
        case 3: if (t<131072) w_s2[t]         = tf32f(d[t]); break;
        case 4: if (t<65536)  w_cqkv[t]       = tf32f(e[t]); break;
        case 5: if (t<65536)  w_cqkv[65536+t] = tf32f(f[t]); break;
        case 6: if (t<65536)  w_co[t]         = tf32f(g[t]); break;
        case 7: if (t<262144) w_c1[t]         = tf32f(h[t]); break;
        case 8: if (t<131072) w_c2[t]         = tf32f(i[t]); break;
        case 9:
            if (t < 2*(int)BND){
                float v = (t < (int)BND) ? d0[t] : d1[t-(int)BND];
                g_x[t] = v; g_xr[t] = tf32f(v);
            }
            break;
    }
}

__global__ void qkv_rope_k(const float* __restrict__ qkv,
                           const float* __restrict__ enc0,
                           const float* __restrict__ enc1,
                           float* __restrict__ Q, float* __restrict__ K,
                           float* __restrict__ V)
{
    int idx = blockIdx.x*blockDim.x + threadIdx.x;
    const int total = 2*Bb*Hh*Nn*(HDd/2);
    if (idx >= total) return;
    int p = idx % (HDd/2); int t = idx / (HDd/2);
    int n = t % Nn; t /= Nn;
    int h = t % Hh; t /= Hh;
    int b = t % Bb; int s = t / Bb;
    size_t r = (size_t)(s*Bb + b)*Nn + n;
    const float* row = qkv + r*(3*Dd);
    int d0 = 2*p, d1 = 2*p+1;
    float q0 = row[h*192 + d0*3 + 0], q1 = row[h*192 + d1*3 + 0];
    float k0 = row[h*192 + d0*3 + 1], k1 = row[h*192 + d1*3 + 1];
    float v0 = row[h*192 + d0*3 + 2], v1 = row[h*192 + d1*3 + 2];
    const float* enc = s ? enc1 : enc0;
    size_t eoff = ((size_t)b*Nn + n)*HDd;
    float c = enc[eoff + d0];
    float si = enc[(size_t)Bb*Nn*HDd + eoff + d0];
    float qo0 = q0*c - q1*si, qo1 = q1*c + q0*si;
    float ko0 = k0*c - k1*si, ko1 = k1*c + k0*si;
    size_t bh = (size_t)(s*Bb + b)*Hh + h;
    size_t o = (bh*Nn + n)*HDd;
    Q[o+d0]=tf32f(qo0); Q[o+d1]=tf32f(qo1);
    K[o+d0]=tf32f(ko0); K[o+d1]=tf32f(ko1);
    V[o+d0]=tf32f(v0);  V[o+d1]=tf32f(v1);
}

__global__ void ln_gelu_k(float* __restrict__ X, const float* __restrict__ g,
                          const float* __restrict__ be)
{
    float* p = X + (size_t)blockIdx.x * 512;
    int tid = threadIdx.x;
    float a = p[tid], b = p[tid+256];
    float s = a + b;
    float sq = a*a + b*b;
    #pragma unroll
    for (int o=16;o;o>>=1){ s += __shfl_xor_sync(0xffffffffu,s,o);
                            sq += __shfl_xor_sync(0xffffffffu,sq,o); }
    __shared__ float ss[8], sqs[8];
    if ((tid&31)==0){ ss[tid>>5]=s; sqs[tid>>5]=sq; }
    __syncthreads();
    s = 0.f; sq = 0.f;
    #pragma unroll
    for (int t=0;t<8;t++){ s+=ss[t]; sq+=sqs[t]; }
    float mean = s * (1.0f/512.0f);
    float var  = sq * (1.0f/512.0f) - mean*mean;
    float inv = rsqrtf(var + 1e-5f);
    float y0 = (a-mean)*inv*g[tid]     + be[tid];
    float y1 = (b-mean)*inv*g[tid+256] + be[tid+256];
    p[tid]     = tf32f(0.5f*y0*(1.0f+erff(y0*0.70710678118f)));
    p[tid+256] = tf32f(0.5f*y1*(1.0f+erff(y1*0.70710678118f)));
}

// ================= host orchestration =================
extern "C" void kernel_launch(void* const* d_in, const int* in_sizes, int n_in,
                              void* d_out, int out_size)
{
    const float* desc0  = (const float*)d_in[0];
    const float* desc1  = (const float*)d_in[1];
    const float* enc0   = (const float*)d_in[2];
    const float* enc1   = (const float*)d_in[3];
    const float* s_Wqkv = (const float*)d_in[4];
    const float* s_bqkv = (const float*)d_in[5];
    const float* s_Wout = (const float*)d_in[6];
    const float* s_bout = (const float*)d_in[7];
    const float* s_W1   = (const float*)d_in[8];
    const float* s_b1   = (const float*)d_in[9];
    const float* s_g    = (const float*)d_in[10];
    const float* s_be   = (const float*)d_in[11];
    const float* s_W2   = (const float*)d_in[12];
    const float* s_b2   = (const float*)d_in[13];
    const float* c_Wqk  = (const float*)d_in[14];
    const float* c_bqk  = (const float*)d_in[15];
    const float* c_Wv   = (const float*)d_in[16];
    const float* c_bv   = (const float*)d_in[17];
    const float* c_Wo   = (const float*)d_in[18];
    const float* c_bo   = (const float*)d_in[19];
    const float* c_W1   = (const float*)d_in[20];
    const float* c_b1   = (const float*)d_in[21];
    const float* c_g    = (const float*)d_in[22];
    const float* c_be   = (const float*)d_in[23];
    const float* c_W2   = (const float*)d_in[24];
    const float* c_b2   = (const float*)d_in[25];
    float* out = (float*)d_out;

    float *x,*xr,*qkv,*q,*k,*v,*tmp,*hb;
    float *wqkv,*wout,*ws1,*ws2,*wcqkv,*wco,*wc1,*wc2;
    cudaGetSymbolAddress((void**)&x,   g_x);
    cudaGetSymbolAddress((void**)&xr,  g_xr);
    cudaGetSymbolAddress((void**)&qkv, g_qkv);
    cudaGetSymbolAddress((void**)&q,   g_q);
    cudaGetSymbolAddress((void**)&k,   g_k);
    cudaGetSymbolAddress((void**)&v,   g_v);
    cudaGetSymbolAddress((void**)&tmp, g_tmp);
    cudaGetSymbolAddress((void**)&hb,  g_h);
    cudaGetSymbolAddress((void**)&wqkv, w_qkv);
    cudaGetSymbolAddress((void**)&wout, w_out);
    cudaGetSymbolAddress((void**)&ws1,  w_s1);
    cudaGetSymbolAddress((void**)&ws2,  w_s2);
    cudaGetSymbolAddress((void**)&wcqkv,w_cqkv);
    cudaGetSymbolAddress((void**)&wco,  w_co);
    cudaGetSymbolAddress((void**)&wc1,  w_c1);
    cudaGetSymbolAddress((void**)&wc2,  w_c2);

    cudaFuncSetAttribute(flash_k, cudaFuncAttributeMaxDynamicSharedMemorySize, FA_SMEM);
    cudaFuncSetAttribute(mgemm,   cudaFuncAttributeMaxDynamicSharedMemorySize, MG_SMEM);

    auto GE = [&](const float* A,const float* A2,int lda,const float* W,int ldb,
                  float* C,int ldc,const float* bias,const float* bias2,
                  const float* Res,int ldr,int M,int Nc,int K,int ro,float* Cr){
        dim3 gr(Nc/128, M/128);
        mgemm<<<gr,128,MG_SMEM>>>(A,A2,lda,W,ldb,C,ldc,bias,bias2,Res,ldr,K,ro,Cr);
    };

    // 1: prep
    {
        dim3 gr((2*(int)BND+255)/256, 10);
        prep_k<<<gr,256>>>(s_Wqkv,s_Wout,s_W1,s_W2,c_Wqk,c_Wv,c_Wo,c_W1,c_W2,desc0,desc1);
    }
    // 2: qkv
    GE(xr,nullptr,Dd, wqkv,Dd, qkv,3*Dd, s_bqkv,nullptr, nullptr,0, M2,3*Dd,Dd, 0,nullptr);
    // 3: rope
    {
        int total = 2*Bb*Hh*Nn*(HDd/2);
        qkv_rope_k<<<(total+255)/256,256>>>(qkv, enc0, enc1, q, k, v);
    }
    // 4: flash self -> tmp   [ncu window]
    {
        dim3 gr(Nn/128, 2*Bb*Hh);
        flash_k<<<gr,128,FA_SMEM>>>(q, k, v, tmp, 0);
    }
    // 5: msg
    GE(tmp,nullptr,Dd, wout,Dd, qkv,Dd, s_bout,nullptr, nullptr,0, M2,Dd,Dd, 1,nullptr);
    GE(xr,qkv,Dd, ws1,2*Dd, hb,2*Dd, s_b1,nullptr, nullptr,0, M2,2*Dd,2*Dd, 0,nullptr);
    ln_gelu_k<<<M2,256>>>(hb, s_g, s_be);
    GE(hb,nullptr,2*Dd, ws2,2*Dd, x,Dd, s_b2,nullptr, x,Dd, M2,Dd,2*Dd, 0,xr);

    // ======== CROSS block ========
    GE(xr,nullptr,Dd, wcqkv,Dd, hb,512, c_bqk,c_bv, nullptr,0, M2,512,Dd, 1,nullptr);
    {
        dim3 gr(Nn/128, 2*Bb*Hh);
        flash_k<<<gr,128,FA_SMEM>>>(hb, hb, hb+256, qkv, 1);
    }
    GE(qkv,nullptr,Dd, wco,Dd, tmp,Dd, c_bo,nullptr, nullptr,0, M2,Dd,Dd, 1,nullptr);
    GE(xr,tmp,Dd, wc1,2*Dd, hb,2*Dd, c_b1,nullptr, nullptr,0, M2,2*Dd,2*Dd, 0,nullptr);
    ln_gelu_k<<<M2,256>>>(hb, c_g, c_be);
    GE(hb,nullptr,2*Dd, wc2,2*Dd, out,Dd, c_b2,nullptr, x,Dd, M2,Dd,2*Dd, 0,nullptr);
}

// round 11
// speedup vs baseline: 4.4011x; 1.0761x over previous
#include <cuda_runtime.h>
#include <math.h>
#include <stdint.h>

#define Bb 4
#define Nn 2048
#define Dd 256
#define Hh 4
#define HDd 64
#define M2 (2*Bb*Nn)
#define BND ((size_t)Bb*Nn*Dd)

// ---------------- static scratch ----------------
__device__ float g_x  [(size_t)M2*Dd];
__device__ float g_xr [(size_t)M2*Dd];
__device__ float g_qkv[(size_t)M2*3*Dd];
__device__ float g_q  [(size_t)2*Bb*Hh*Nn*HDd];
__device__ float g_k  [(size_t)2*Bb*Hh*Nn*HDd];
__device__ float g_v  [(size_t)2*Bb*Hh*Nn*HDd];
__device__ float g_tmp[(size_t)M2*Dd];
__device__ float g_h  [(size_t)M2*2*Dd];
// pre-rounded weights
__device__ float w_qkv [768*256];
__device__ float w_out [256*256];
__device__ float w_s1  [512*512];
__device__ float w_s2  [256*512];
__device__ float w_cqkv[512*256];
__device__ float w_co  [256*256];
__device__ float w_c1  [512*512];
__device__ float w_c2  [256*512];

__device__ __forceinline__ float tf32f(float x){
    float y; asm("cvt.rna.tf32.f32 %0, %1;" : "=f"(y) : "f"(x)); return y;
}

// ---------------- cp.async helpers ----------------
__device__ __forceinline__ void cpa16(uint32_t s, const void* g){
    asm volatile("cp.async.cg.shared.global [%0], [%1], 16;\n" :: "r"(s), "l"(g));
}
__device__ __forceinline__ void cpa_commit(){ asm volatile("cp.async.commit_group;\n"); }
template<int N> __device__ __forceinline__ void cpa_wait(){
    asm volatile("cp.async.wait_group %0;\n" :: "n"(N));
}
__device__ __forceinline__ uint32_t smem_u32(const void* p){
    uint32_t a;
    asm("{ .reg .u64 t; cvta.to.shared.u64 t, %1; cvt.u32.u64 %0, t; }" : "=r"(a) : "l"(p));
    return a;
}

// ---------------- mma.sync m16n8k8 tf32 ----------------
__device__ __forceinline__ void mma_tf32(float* c, const float* a, const float* b){
    asm volatile(
      "mma.sync.aligned.m16n8k8.row.col.f32.tf32.tf32.f32 "
      "{%0,%1,%2,%3},{%4,%5,%6,%7},{%8,%9},{%0,%1,%2,%3};\n"
      : "+f"(c[0]),"+f"(c[1]),"+f"(c[2]),"+f"(c[3])
      : "r"(__float_as_uint(a[0])),"r"(__float_as_uint(a[1])),
        "r"(__float_as_uint(a[2])),"r"(__float_as_uint(a[3])),
        "r"(__float_as_uint(b[0])),"r"(__float_as_uint(b[1])));
}

// ---------------- NT tf32 GEMM (unchanged from R10) ----------------
#define GLD 24
#define MG_SMEM (3*128*GLD*2*4)
__global__ void __launch_bounds__(128,2)
mgemm(const float* __restrict__ A, const float* __restrict__ A2, int lda,
      const float* __restrict__ W, int ldb,
      float* __restrict__ C, int ldc,
      const float* __restrict__ bias, const float* __restrict__ bias2,
      const float* __restrict__ Res, int ldr,
      int K, int round_out, float* __restrict__ Cr)
{
    extern __shared__ float dsm[];
    float (*As)[128][GLD] = reinterpret_cast<float(*)[128][GLD]>(dsm);
    float (*Bs)[128][GLD] = reinterpret_cast<float(*)[128][GLD]>(dsm + 3*128*GLD);

    const int bm = blockIdx.y*128, bn = blockIdx.x*128;
    const int tid = threadIdx.x, warp = tid>>5, lane = tid&31;
    const int wm = warp>>1, wn = warp&1;
    const int gq = lane>>2, tq = lane&3;

    float acc[4][8][4];
    #pragma unroll
    for (int m=0;m<4;m++)
        #pragma unroll
        for (int n=0;n<8;n++){
            acc[m][n][0]=0.f; acc[m][n][1]=0.f; acc[m][n][2]=0.f; acc[m][n][3]=0.f;
        }

    auto ld_tile = [&](int st, int k0){
        const float* Ab; int ka;
        if (A2 && k0 >= 256){ Ab = A2; ka = k0 - 256; } else { Ab = A; ka = k0; }
        #pragma unroll
        for (int i=0;i<4;i++){
            int id = tid + i*128;
            int row = id>>2, c4 = id&3;
            cpa16(smem_u32(&As[st][row][c4*4]), Ab + (size_t)(bm+row)*((A2)?256:lda) + ka + c4*4);
        }
        #pragma unroll
        for (int i=0;i<4;i++){
            int id = tid + i*128;
            int row = id>>2, c4 = id&3;
            cpa16(smem_u32(&Bs[st][row][c4*4]), W + (size_t)(bn+row)*ldb + k0 + c4*4);
        }
        cpa_commit();
    };

    const int KT = K/16;
    ld_tile(0, 0);
    ld_tile(1, 16);

    for (int kt=0; kt<KT; kt++){
        const int buf = kt%3;
        if (kt+1 < KT) cpa_wait<1>(); else cpa_wait<0>();
        __syncthreads();
        if (kt+2 < KT) ld_tile((kt+2)%3, (kt+2)*16);
        #pragma unroll
        for (int ks=0; ks<16; ks+=8){
            float a[4][4], b[8][2];
            #pragma unroll
            for (int m=0;m<4;m++){
                float2 a02 = *reinterpret_cast<const float2*>(&As[buf][wm*64 + m*16 + gq    ][ks + 2*tq]);
                float2 a13 = *reinterpret_cast<const float2*>(&As[buf][wm*64 + m*16 + gq + 8][ks + 2*tq]);
                a[m][0]=a02.x; a[m][2]=a02.y; a[m][1]=a13.x; a[m][3]=a13.y;
            }
            #pragma unroll
            for (int n=0;n<8;n++){
                float2 bb = *reinterpret_cast<const float2*>(&Bs[buf][wn*64 + n*8 + gq][ks + 2*tq]);
                b[n][0]=bb.x; b[n][1]=bb.y;
            }
            #pragma unroll
            for (int m=0;m<4;m++)
                #pragma unroll
                for (int n=0;n<8;n++)
                    mma_tf32(acc[m][n], a[m], b[n]);
        }
    }

    #pragma unroll
    for (int m=0;m<4;m++){
        const int r0g = bm + wm*64 + m*16 + gq;
        #pragma unroll
        for (int n=0;n<8;n++){
            const int cg = bn + wn*64 + n*8 + 2*tq;
            float v0=acc[m][n][0], v1=acc[m][n][1], v2=acc[m][n][2], v3=acc[m][n][3];
            if (bias){
                float b0, b1;
                if (bias2 && cg >= 256){ b0 = bias2[cg-256]; b1 = bias2[cg-255]; }
                else                   { b0 = bias[cg];      b1 = bias[cg+1];    }
                v0+=b0; v1+=b1; v2+=b0; v3+=b1;
            }
            if (Res){
                const float* rp0 = Res + (size_t)r0g*ldr + cg;
                const float* rp1 = Res + (size_t)(r0g+8)*ldr + cg;
                v0+=rp0[0]; v1+=rp0[1]; v2+=rp1[0]; v3+=rp1[1];
            }
            float2 w0, w1;
            if (round_out){ w0.x=tf32f(v0); w0.y=tf32f(v1); w1.x=tf32f(v2); w1.y=tf32f(v3); }
            else          { w0.x=v0; w0.y=v1; w1.x=v2; w1.y=v3; }
            *reinterpret_cast<float2*>(C + (size_t)r0g*ldc + cg)     = w0;
            *reinterpret_cast<float2*>(C + (size_t)(r0g+8)*ldc + cg) = w1;
            if (Cr){
                float2 q0, q1;
                q0.x=tf32f(v0); q0.y=tf32f(v1); q1.x=tf32f(v2); q1.y=tf32f(v3);
                *reinterpret_cast<float2*>(Cr + (size_t)r0g*ldc + cg)     = q0;
                *reinterpret_cast<float2*>(Cr + (size_t)(r0g+8)*ldc + cg) = q1;
            }
        }
    }
}

// ---------------- flash attention: P kept in registers (accumulator==a-frag) ----------------
#define QP_LD 72
#define KV_LD 72
#define FA_SMEM ((128*QP_LD + 2*64*KV_LD + 2*64*KV_LD)*4)

__global__ void __launch_bounds__(128,2)
flash_k(const float* __restrict__ Qb, const float* __restrict__ Kb,
        const float* __restrict__ Vb, float* __restrict__ Ob, int mode)
{
    extern __shared__ float smf[];
    float* QP = smf;
    float* Ks = smf + 128*QP_LD;
    float* Vs = Ks + 2*64*KV_LD;

    const int z = blockIdx.y, it = blockIdx.x;
    const int tid = threadIdx.x, warp = tid>>5, lane = tid&31;
    const int gq = lane>>2, tq = lane&3;

    size_t qoff, kvoff, ooff;
    int ld;
    if (mode == 0){
        qoff = (size_t)z*Nn*HDd; kvoff = qoff;
        ooff = (size_t)(z>>2)*Nn*Dd + (size_t)(z&3)*HDd;
        ld = HDd;
    } else {
        int h = z>>4, zz = z&15;
        size_t f = (size_t)(zz>>2)*Nn*512 + (size_t)(zz&3)*HDd;
        qoff  = (size_t)h*((size_t)Bb*Nn*512) + f;
        kvoff = (size_t)(1-h)*((size_t)Bb*Nn*512) + f;
        ooff  = (size_t)h*BND + (size_t)(zz>>2)*Nn*Dd + (size_t)(zz&3)*HDd;
        ld = 512;
    }

    const float* Q = Qb + qoff + (size_t)it*128*ld;
    const float* K = Kb + kvoff;
    const float* V = Vb + kvoff;
    float* O = Ob + ooff + (size_t)it*128*Dd;

    const int kr = tid>>4, kc = (tid&15)*4;
    auto load_kv = [&](int buf, int j0){
        #pragma unroll
        for (int itr=0; itr<8; itr++){
            int row = kr + itr*8;
            cpa16(smem_u32(Ks + ((size_t)buf*64 + row)*KV_LD + kc), K + (size_t)(j0+row)*ld + kc);
        }
        #pragma unroll
        for (int itr=0; itr<8; itr++){
            int row = kr + itr*8;
            cpa16(smem_u32(Vs + ((size_t)buf*64 + row)*KV_LD + kc), V + (size_t)(j0+row)*ld + kc);
        }
        cpa_commit();
    };

    load_kv(0, 0);

    // stage Q (pre-rounded; *0.125 exact)
    #pragma unroll
    for (int r=0;r<16;r++){
        int idx = tid + r*128;
        int row = idx>>4, c4 = idx&15;
        float4 qv = *reinterpret_cast<const float4*>(Q + (size_t)row*ld + c4*4);
        QP[row*QP_LD + c4*4+0] = qv.x*0.125f;
        QP[row*QP_LD + c4*4+1] = qv.y*0.125f;
        QP[row*QP_LD + c4*4+2] = qv.z*0.125f;
        QP[row*QP_LD + c4*4+3] = qv.w*0.125f;
    }
    __syncthreads();

    // Q a-fragments, k-lane remap: lane tq -> col 2tq, lane tq+4 -> col 2tq+1
    const int r0 = warp*32 + gq;
    float aq[2][8][4];
    #pragma unroll
    for (int g=0; g<2; g++){
        int rg = r0 + g*16;
        #pragma unroll
        for (int kk=0;kk<8;kk++){
            float2 q02 = *reinterpret_cast<const float2*>(&QP[ rg    *QP_LD + kk*8 + 2*tq]);
            float2 q13 = *reinterpret_cast<const float2*>(&QP[(rg+8)*QP_LD + kk*8 + 2*tq]);
            aq[g][kk][0]=q02.x; aq[g][kk][2]=q02.y;
            aq[g][kk][1]=q13.x; aq[g][kk][3]=q13.y;
        }
    }

    float o[2][8][4];
    #pragma unroll
    for (int g=0;g<2;g++)
        #pragma unroll
        for (int i=0;i<8;i++){ o[g][i][0]=0.f;o[g][i][1]=0.f;o[g][i][2]=0.f;o[g][i][3]=0.f; }
    float mrow[4] = {-1e30f,-1e30f,-1e30f,-1e30f};
    float lrow[4] = {0.f,0.f,0.f,0.f};

    const int NT = Nn/64;
    for (int j=0;j<NT;j++){
        const int buf = j&1;
        cpa_wait<0>();
        __syncthreads();    // also orders compute(j-1) before prefetch below overwrites
        if (j+1 < NT) load_kv(buf^1, (j+1)*64);

        const float* Kb_ = Ks + (size_t)buf*64*KV_LD;
        const float* Vb_ = Vs + (size_t)buf*64*KV_LD;

        // S = (Q*scale) K^T ; K b-frags LDS.64 via remap
        float c[2][8][4];
        #pragma unroll
        for (int nf=0;nf<8;nf++){
            #pragma unroll
            for (int g=0;g<2;g++){ c[g][nf][0]=0.f;c[g][nf][1]=0.f;c[g][nf][2]=0.f;c[g][nf][3]=0.f; }
            #pragma unroll
            for (int kk=0;kk<8;kk++){
                float2 bb = *reinterpret_cast<const float2*>(&Kb_[(nf*8+gq)*KV_LD + kk*8 + 2*tq]);
                float b[2] = {bb.x, bb.y};
                mma_tf32(c[0][nf], aq[0][kk], b);
                mma_tf32(c[1][nf], aq[1][kk], b);
            }
        }

        // online softmax; P stays in c registers
        #pragma unroll
        for (int g=0;g<2;g++){
            float mx0=-1e30f, mx1=-1e30f;
            #pragma unroll
            for (int nf=0;nf<8;nf++){
                mx0 = fmaxf(mx0, fmaxf(c[g][nf][0], c[g][nf][1]));
                mx1 = fmaxf(mx1, fmaxf(c[g][nf][2], c[g][nf][3]));
            }
            mx0 = fmaxf(mx0, __shfl_xor_sync(0xffffffffu, mx0, 1));
            mx0 = fmaxf(mx0, __shfl_xor_sync(0xffffffffu, mx0, 2));
            mx1 = fmaxf(mx1, __shfl_xor_sync(0xffffffffu, mx1, 1));
            mx1 = fmaxf(mx1, __shfl_xor_sync(0xffffffffu, mx1, 2));
            float nm0 = fmaxf(mrow[g*2],   mx0);
            float nm1 = fmaxf(mrow[g*2+1], mx1);
            float al0 = __expf(mrow[g*2]  -nm0);
            float al1 = __expf(mrow[g*2+1]-nm1);
            float s0=0.f, s1=0.f;
            #pragma unroll
            for (int nf=0;nf<8;nf++){
                c[g][nf][0]=__expf(c[g][nf][0]-nm0); c[g][nf][1]=__expf(c[g][nf][1]-nm0);
                c[g][nf][2]=__expf(c[g][nf][2]-nm1); c[g][nf][3]=__expf(c[g][nf][3]-nm1);
                s0 += c[g][nf][0]+c[g][nf][1]; s1 += c[g][nf][2]+c[g][nf][3];
            }
            s0 += __shfl_xor_sync(0xffffffffu, s0, 1);
            s0 += __shfl_xor_sync(0xffffffffu, s0, 2);
            s1 += __shfl_xor_sync(0xffffffffu, s1, 1);
            s1 += __shfl_xor_sync(0xffffffffu, s1, 2);
            lrow[g*2]   = lrow[g*2]*al0   + s0;
            lrow[g*2+1] = lrow[g*2+1]*al1 + s1;
            mrow[g*2] = nm0; mrow[g*2+1] = nm1;
            #pragma unroll
            for (int nd=0;nd<8;nd++){
                o[g][nd][0]*=al0; o[g][nd][1]*=al0; o[g][nd][2]*=al1; o[g][nd][3]*=al1;
            }
        }

        // O += P V : P a-frag = accumulator permutation {c0,c2,c1,c3} (k-lane remap)
        #pragma unroll
        for (int kk=0;kk<8;kk++){
            float ap0[4] = { c[0][kk][0], c[0][kk][2], c[0][kk][1], c[0][kk][3] };
            float ap1[4] = { c[1][kk][0], c[1][kk][2], c[1][kk][1], c[1][kk][3] };
            #pragma unroll
            for (int nd=0;nd<8;nd++){
                float b[2];
                b[0] = Vb_[(kk*8+2*tq  )*KV_LD + nd*8 + gq];
                b[1] = Vb_[(kk*8+2*tq+1)*KV_LD + nd*8 + gq];
                mma_tf32(o[0][nd], ap0, b);
                mma_tf32(o[1][nd], ap1, b);
            }
        }
    }

    #pragma unroll
    for (int g=0;g<2;g++){
        int rg = r0 + g*16;
        const float inv0 = 1.f/lrow[g*2], inv1 = 1.f/lrow[g*2+1];
        #pragma unroll
        for (int nd=0;nd<8;nd++){
            float2 w0; w0.x = tf32f(o[g][nd][0]*inv0); w0.y = tf32f(o[g][nd][1]*inv0);
            float2 w1; w1.x = tf32f(o[g][nd][2]*inv1); w1.y = tf32f(o[g][nd][3]*inv1);
            *reinterpret_cast<float2*>(O + (size_t) rg   *Dd + nd*8 + 2*tq) = w0;
            *reinterpret_cast<float2*>(O + (size_t)(rg+8)*Dd + nd*8 + 2*tq) = w1;
        }
    }
}

// ---------------- prep: weights round + init x/xr (one launch) ----------------
__global__ void prep_k(const float* a,const float* b,const float* c,const float* d,
                       const float* e,const float* f,const float* g,const float* h,
                       const float* i, const float* d0, const float* d1)
{
    int t = blockIdx.x*blockDim.x + threadIdx.x;
    switch (blockIdx.y){
        case 0: if (t<196608) w_qkv[t]        = tf32f(a[t]); break;
        case 1: if (t<65536)  w_out[t]        = tf32f(b[t]); break;
        case 2: if (t<262144) w_s1[t]         = tf32f(c[t]); break;
        case 3: if (t<131072) w_s2[t]         = tf32f(d[t]); break;
        case 4: if (t<65536)  w_cqkv[t]       = tf32f(e[t]); break;
        case 5: if (t<65536)  w_cqkv[65536+t] = tf32f(f[t]); break;
        case 6: if (t<65536)  w_co[t]         = tf32f(g[t]); break;
        case 7: if (t<262144) w_c1[t]         = tf32f(h[t]); break;
        case 8: if (t<131072) w_c2[t]         = tf32f(i[t]); break;
        case 9:
            if (t < 2*(int)BND){
                float v = (t < (int)BND) ? d0[t] : d1[t-(int)BND];
                g_x[t] = v; g_xr[t] = tf32f(v);
            }
            break;
    }
}

__global__ void qkv_rope_k(const float* __restrict__ qkv,
                           const float* __restrict__ enc0,
                           const float* __restrict__ enc1,
                           float* __restrict__ Q, float* __restrict__ K,
                           float* __restrict__ V)
{
    int idx = blockIdx.x*blockDim.x + threadIdx.x;
    const int total = 2*Bb*Hh*Nn*(HDd/2);
    if (idx >= total) return;
    int p = idx % (HDd/2); int t = idx / (HDd/2);
    int n = t % Nn; t /= Nn;
    int h = t % Hh; t /= Hh;
    int b = t % Bb; int s = t / Bb;
    size_t r = (size_t)(s*Bb + b)*Nn + n;
    const float* row = qkv + r*(3*Dd);
    int d0 = 2*p, d1 = 2*p+1;
    float q0 = row[h*192 + d0*3 + 0], q1 = row[h*192 + d1*3 + 0];
    float k0 = row[h*192 + d0*3 + 1], k1 = row[h*192 + d1*3 + 1];
    float v0 = row[h*192 + d0*3 + 2], v1 = row[h*192 + d1*3 + 2];
    const float* enc = s ? enc1 : enc0;
    size_t eoff = ((size_t)b*Nn + n)*HDd;
    float c = enc[eoff + d0];
    float si = enc[(size_t)Bb*Nn*HDd + eoff + d0];
    float qo0 = q0*c - q1*si, qo1 = q1*c + q0*si;
    float ko0 = k0*c - k1*si, ko1 = k1*c + k0*si;
    size_t bh = (size_t)(s*Bb + b)*Hh + h;
    size_t o = (bh*Nn + n)*HDd;
    Q[o+d0]=tf32f(qo0); Q[o+d1]=tf32f(qo1);
    K[o+d0]=tf32f(ko0); K[o+d1]=tf32f(ko1);
    V[o+d0]=tf32f(v0);  V[o+d1]=tf32f(v1);
}

__global__ void ln_gelu_k(float* __restrict__ X, const float* __restrict__ g,
                          const float* __restrict__ be)
{
    float* p = X + (size_t)blockIdx.x * 512;
    int tid = threadIdx.x;
    float a = p[tid], b = p[tid+256];
    float s = a + b;
    float sq = a*a + b*b;
    #pragma unroll
    for (int o=16;o;o>>=1){ s += __shfl_xor_sync(0xffffffffu,s,o);
                            sq += __shfl_xor_sync(0xffffffffu,sq,o); }
    __shared__ float ss[8], sqs[8];
    if ((tid&31)==0){ ss[tid>>5]=s; sqs[tid>>5]=sq; }
    __syncthreads();
    s = 0.f; sq = 0.f;
    #pragma unroll
    for (int t=0;t<8;t++){ s+=ss[t]; sq+=sqs[t]; }
    float mean = s * (1.0f/512.0f);
    float var  = sq * (1.0f/512.0f) - mean*mean;
    float inv = rsqrtf(var + 1e-5f);
    float y0 = (a-mean)*inv*g[tid]     + be[tid];
    float y1 = (b-mean)*inv*g[tid+256] + be[tid+256];
    p[tid]     = tf32f(0.5f*y0*(1.0f+erff(y0*0.70710678118f)));
    p[tid+256] = tf32f(0.5f*y1*(1.0f+erff(y1*0.70710678118f)));
}

// ================= host orchestration =================
extern "C" void kernel_launch(void* const* d_in, const int* in_sizes, int n_in,
                              void* d_out, int out_size)
{
    const float* desc0  = (const float*)d_in[0];
    const float* desc1  = (const float*)d_in[1];
    const float* enc0   = (const float*)d_in[2];
    const float* enc1   = (const float*)d_in[3];
    const float* s_Wqkv = (const float*)d_in[4];
    const float* s_bqkv = (const float*)d_in[5];
    const float* s_Wout = (const float*)d_in[6];
    const float* s_bout = (const float*)d_in[7];
    const float* s_W1   = (const float*)d_in[8];
    const float* s_b1   = (const float*)d_in[9];
    const float* s_g    = (const float*)d_in[10];
    const float* s_be   = (const float*)d_in[11];
    const float* s_W2   = (const float*)d_in[12];
    const float* s_b2   = (const float*)d_in[13];
    const float* c_Wqk  = (const float*)d_in[14];
    const float* c_bqk  = (const float*)d_in[15];
    const float* c_Wv   = (const float*)d_in[16];
    const float* c_bv   = (const float*)d_in[17];
    const float* c_Wo   = (const float*)d_in[18];
    const float* c_bo   = (const float*)d_in[19];
    const float* c_W1   = (const float*)d_in[20];
    const float* c_b1   = (const float*)d_in[21];
    const float* c_g    = (const float*)d_in[22];
    const float* c_be   = (const float*)d_in[23];
    const float* c_W2   = (const float*)d_in[24];
    const float* c_b2   = (const float*)d_in[25];
    float* out = (float*)d_out;

    float *x,*xr,*qkv,*q,*k,*v,*tmp,*hb;
    float *wqkv,*wout,*ws1,*ws2,*wcqkv,*wco,*wc1,*wc2;
    cudaGetSymbolAddress((void**)&x,   g_x);
    cudaGetSymbolAddress((void**)&xr,  g_xr);
    cudaGetSymbolAddress((void**)&qkv, g_qkv);
    cudaGetSymbolAddress((void**)&q,   g_q);
    cudaGetSymbolAddress((void**)&k,   g_k);
    cudaGetSymbolAddress((void**)&v,   g_v);
    cudaGetSymbolAddress((void**)&tmp, g_tmp);
    cudaGetSymbolAddress((void**)&hb,  g_h);
    cudaGetSymbolAddress((void**)&wqkv, w_qkv);
    cudaGetSymbolAddress((void**)&wout, w_out);
    cudaGetSymbolAddress((void**)&ws1,  w_s1);
    cudaGetSymbolAddress((void**)&ws2,  w_s2);
    cudaGetSymbolAddress((void**)&wcqkv,w_cqkv);
    cudaGetSymbolAddress((void**)&wco,  w_co);
    cudaGetSymbolAddress((void**)&wc1,  w_c1);
    cudaGetSymbolAddress((void**)&wc2,  w_c2);

    cudaFuncSetAttribute(flash_k, cudaFuncAttributeMaxDynamicSharedMemorySize, FA_SMEM);
    cudaFuncSetAttribute(mgemm,   cudaFuncAttributeMaxDynamicSharedMemorySize, MG_SMEM);

    auto GE = [&](const float* A,const float* A2,int lda,const float* W,int ldb,
                  float* C,int ldc,const float* bias,const float* bias2,
                  const float* Res,int ldr,int M,int Nc,int K,int ro,float* Cr){
        dim3 gr(Nc/128, M/128);
        mgemm<<<gr,128,MG_SMEM>>>(A,A2,lda,W,ldb,C,ldc,bias,bias2,Res,ldr,K,ro,Cr);
    };

    // 1: prep
    {
        dim3 gr((2*(int)BND+255)/256, 10);
        prep_k<<<gr,256>>>(s_Wqkv,s_Wout,s_W1,s_W2,c_Wqk,c_Wv,c_Wo,c_W1,c_W2,desc0,desc1);
    }
    // 2: qkv
    GE(xr,nullptr,Dd, wqkv,Dd, qkv,3*Dd, s_bqkv,nullptr, nullptr,0, M2,3*Dd,Dd, 0,nullptr);
    // 3: rope
    {
        int total = 2*Bb*Hh*Nn*(HDd/2);
        qkv_rope_k<<<(total+255)/256,256>>>(qkv, enc0, enc1, q, k, v);
    }
    // 4: flash self -> tmp   [ncu window]
    {
        dim3 gr(Nn/128, 2*Bb*Hh);
        flash_k<<<gr,128,FA_SMEM>>>(q, k, v, tmp, 0);
    }
    // 5: msg
    GE(tmp,nullptr,Dd, wout,Dd, qkv,Dd, s_bout,nullptr, nullptr,0, M2,Dd,Dd, 1,nullptr);
    GE(xr,qkv,Dd, ws1,2*Dd, hb,2*Dd, s_b1,nullptr, nullptr,0, M2,2*Dd,2*Dd, 0,nullptr);
    ln_gelu_k<<<M2,256>>>(hb, s_g, s_be);
    GE(hb,nullptr,2*Dd, ws2,2*Dd, x,Dd, s_b2,nullptr, x,Dd, M2,Dd,2*Dd, 0,xr);

    // ======== CROSS block ========
    GE(xr,nullptr,Dd, wcqkv,Dd, hb,512, c_bqk,c_bv, nullptr,0, M2,512,Dd, 1,nullptr);
    {
        dim3 gr(Nn/128, 2*Bb*Hh);
        flash_k<<<gr,128,FA_SMEM>>>(hb, hb, hb+256, qkv, 1);
    }
    GE(qkv,nullptr,Dd, wco,Dd, tmp,Dd, c_bo,nullptr, nullptr,0, M2,Dd,Dd, 1,nullptr);
    GE(xr,tmp,Dd, wc1,2*Dd, hb,2*Dd, c_b1,nullptr, nullptr,0, M2,2*Dd,2*Dd, 0,nullptr);
    ln_gelu_k<<<M2,256>>>(hb, c_g, c_be);
    GE(hb,nullptr,2*Dd, wc2,2*Dd, out,Dd, c_b2,nullptr, x,Dd, M2,Dd,2*Dd, 0,nullptr);
}

// round 12
// speedup vs baseline: 4.4059x; 1.0011x over previous
#include <cuda_runtime.h>
#include <math.h>
#include <stdint.h>

#define Bb 4
#define Nn 2048
#define Dd 256
#define Hh 4
#define HDd 64
#define M2 (2*Bb*Nn)
#define BND ((size_t)Bb*Nn*Dd)

// ---------------- static scratch ----------------
__device__ float g_x  [(size_t)M2*Dd];
__device__ float g_xr [(size_t)M2*Dd];
__device__ float g_qkv[(size_t)M2*3*Dd];
__device__ float g_q  [(size_t)2*Bb*Hh*Nn*HDd];
__device__ float g_k  [(size_t)2*Bb*Hh*Nn*HDd];
__device__ float g_v  [(size_t)2*Bb*Hh*Nn*HDd];
__device__ float g_tmp[(size_t)M2*Dd];
__device__ float g_h  [(size_t)M2*2*Dd];
// pre-rounded weights
__device__ float w_qkv [768*256];
__device__ float w_out [256*256];
__device__ float w_s1  [512*512];
__device__ float w_s2  [256*512];
__device__ float w_cqkv[512*256];
__device__ float w_co  [256*256];
__device__ float w_c1  [512*512];
__device__ float w_c2  [256*512];

__device__ __forceinline__ float tf32f(float x){
    float y; asm("cvt.rna.tf32.f32 %0, %1;" : "=f"(y) : "f"(x)); return y;
}

// ---------------- cp.async helpers ----------------
__device__ __forceinline__ void cpa16(uint32_t s, const void* g){
    asm volatile("cp.async.cg.shared.global [%0], [%1], 16;\n" :: "r"(s), "l"(g));
}
__device__ __forceinline__ void cpa_commit(){ asm volatile("cp.async.commit_group;\n"); }
template<int N> __device__ __forceinline__ void cpa_wait(){
    asm volatile("cp.async.wait_group %0;\n" :: "n"(N));
}
__device__ __forceinline__ uint32_t smem_u32(const void* p){
    uint32_t a;
    asm("{ .reg .u64 t; cvta.to.shared.u64 t, %1; cvt.u32.u64 %0, t; }" : "=r"(a) : "l"(p));
    return a;
}

// ---------------- mma.sync m16n8k8 tf32 ----------------
__device__ __forceinline__ void mma_tf32(float* c, const float* a, const float* b){
    asm volatile(
      "mma.sync.aligned.m16n8k8.row.col.f32.tf32.tf32.f32 "
      "{%0,%1,%2,%3},{%4,%5,%6,%7},{%8,%9},{%0,%1,%2,%3};\n"
      : "+f"(c[0]),"+f"(c[1]),"+f"(c[2]),"+f"(c[3])
      : "r"(__float_as_uint(a[0])),"r"(__float_as_uint(a[1])),
        "r"(__float_as_uint(a[2])),"r"(__float_as_uint(a[3])),
        "r"(__float_as_uint(b[0])),"r"(__float_as_uint(b[1])));
}

// ---------------- NT tf32 GEMM (unchanged from R10) ----------------
#define GLD 24
#define MG_SMEM (3*128*GLD*2*4)
__global__ void __launch_bounds__(128,2)
mgemm(const float* __restrict__ A, const float* __restrict__ A2, int lda,
      const float* __restrict__ W, int ldb,
      float* __restrict__ C, int ldc,
      const float* __restrict__ bias, const float* __restrict__ bias2,
      const float* __restrict__ Res, int ldr,
      int K, int round_out, float* __restrict__ Cr)
{
    extern __shared__ float dsm[];
    float (*As)[128][GLD] = reinterpret_cast<float(*)[128][GLD]>(dsm);
    float (*Bs)[128][GLD] = reinterpret_cast<float(*)[128][GLD]>(dsm + 3*128*GLD);

    const int bm = blockIdx.y*128, bn = blockIdx.x*128;
    const int tid = threadIdx.x, warp = tid>>5, lane = tid&31;
    const int wm = warp>>1, wn = warp&1;
    const int gq = lane>>2, tq = lane&3;

    float acc[4][8][4];
    #pragma unroll
    for (int m=0;m<4;m++)
        #pragma unroll
        for (int n=0;n<8;n++){
            acc[m][n][0]=0.f; acc[m][n][1]=0.f; acc[m][n][2]=0.f; acc[m][n][3]=0.f;
        }

    auto ld_tile = [&](int st, int k0){
        const float* Ab; int ka;
        if (A2 && k0 >= 256){ Ab = A2; ka = k0 - 256; } else { Ab = A; ka = k0; }
        #pragma unroll
        for (int i=0;i<4;i++){
            int id = tid + i*128;
            int row = id>>2, c4 = id&3;
            cpa16(smem_u32(&As[st][row][c4*4]), Ab + (size_t)(bm+row)*((A2)?256:lda) + ka + c4*4);
        }
        #pragma unroll
        for (int i=0;i<4;i++){
            int id = tid + i*128;
            int row = id>>2, c4 = id&3;
            cpa16(smem_u32(&Bs[st][row][c4*4]), W + (size_t)(bn+row)*ldb + k0 + c4*4);
        }
        cpa_commit();
    };

    const int KT = K/16;
    ld_tile(0, 0);
    ld_tile(1, 16);

    for (int kt=0; kt<KT; kt++){
        const int buf = kt%3;
        if (kt+1 < KT) cpa_wait<1>(); else cpa_wait<0>();
        __syncthreads();
        if (kt+2 < KT) ld_tile((kt+2)%3, (kt+2)*16);
        #pragma unroll
        for (int ks=0; ks<16; ks+=8){
            float a[4][4], b[8][2];
            #pragma unroll
            for (int m=0;m<4;m++){
                float2 a02 = *reinterpret_cast<const float2*>(&As[buf][wm*64 + m*16 + gq    ][ks + 2*tq]);
                float2 a13 = *reinterpret_cast<const float2*>(&As[buf][wm*64 + m*16 + gq + 8][ks + 2*tq]);
                a[m][0]=a02.x; a[m][2]=a02.y; a[m][1]=a13.x; a[m][3]=a13.y;
            }
            #pragma unroll
            for (int n=0;n<8;n++){
                float2 bb = *reinterpret_cast<const float2*>(&Bs[buf][wn*64 + n*8 + gq][ks + 2*tq]);
                b[n][0]=bb.x; b[n][1]=bb.y;
            }
            #pragma unroll
            for (int m=0;m<4;m++)
                #pragma unroll
                for (int n=0;n<8;n++)
                    mma_tf32(acc[m][n], a[m], b[n]);
        }
    }

    #pragma unroll
    for (int m=0;m<4;m++){
        const int r0g = bm + wm*64 + m*16 + gq;
        #pragma unroll
        for (int n=0;n<8;n++){
            const int cg = bn + wn*64 + n*8 + 2*tq;
            float v0=acc[m][n][0], v1=acc[m][n][1], v2=acc[m][n][2], v3=acc[m][n][3];
            if (bias){
                float b0, b1;
                if (bias2 && cg >= 256){ b0 = bias2[cg-256]; b1 = bias2[cg-255]; }
                else                   { b0 = bias[cg];      b1 = bias[cg+1];    }
                v0+=b0; v1+=b1; v2+=b0; v3+=b1;
            }
            if (Res){
                const float* rp0 = Res + (size_t)r0g*ldr + cg;
                const float* rp1 = Res + (size_t)(r0g+8)*ldr + cg;
                v0+=rp0[0]; v1+=rp0[1]; v2+=rp1[0]; v3+=rp1[1];
            }
            float2 w0, w1;
            if (round_out){ w0.x=tf32f(v0); w0.y=tf32f(v1); w1.x=tf32f(v2); w1.y=tf32f(v3); }
            else          { w0.x=v0; w0.y=v1; w1.x=v2; w1.y=v3; }
            *reinterpret_cast<float2*>(C + (size_t)r0g*ldc + cg)     = w0;
            *reinterpret_cast<float2*>(C + (size_t)(r0g+8)*ldc + cg) = w1;
            if (Cr){
                float2 q0, q1;
                q0.x=tf32f(v0); q0.y=tf32f(v1); q1.x=tf32f(v2); q1.y=tf32f(v3);
                *reinterpret_cast<float2*>(Cr + (size_t)r0g*ldc + cg)     = q0;
                *reinterpret_cast<float2*>(Cr + (size_t)(r0g+8)*ldc + cg) = q1;
            }
        }
    }
}

// ---------------- flash attention: P kept in registers (accumulator==a-frag) ----------------
#define QP_LD 72
#define KV_LD 72
#define FA_SMEM ((128*QP_LD + 2*64*KV_LD + 2*64*KV_LD)*4)

__global__ void __launch_bounds__(128,2)
flash_k(const float* __restrict__ Qb, const float* __restrict__ Kb,
        const float* __restrict__ Vb, float* __restrict__ Ob, int mode)
{
    extern __shared__ float smf[];
    float* QP = smf;
    float* Ks = smf + 128*QP_LD;
    float* Vs = Ks + 2*64*KV_LD;

    const int z = blockIdx.y, it = blockIdx.x;
    const int tid = threadIdx.x, warp = tid>>5, lane = tid&31;
    const int gq = lane>>2, tq = lane&3;

    size_t qoff, kvoff, ooff;
    int ld;
    if (mode == 0){
        qoff = (size_t)z*Nn*HDd; kvoff = qoff;
        ooff = (size_t)(z>>2)*Nn*Dd + (size_t)(z&3)*HDd;
        ld = HDd;
    } else {
        int h = z>>4, zz = z&15;
        size_t f = (size_t)(zz>>2)*Nn*512 + (size_t)(zz&3)*HDd;
        qoff  = (size_t)h*((size_t)Bb*Nn*512) + f;
        kvoff = (size_t)(1-h)*((size_t)Bb*Nn*512) + f;
        ooff  = (size_t)h*BND + (size_t)(zz>>2)*Nn*Dd + (size_t)(zz&3)*HDd;
        ld = 512;
    }

    const float* Q = Qb + qoff + (size_t)it*128*ld;
    const float* K = Kb + kvoff;
    const float* V = Vb + kvoff;
    float* O = Ob + ooff + (size_t)it*128*Dd;

    const int kr = tid>>4, kc = (tid&15)*4;
    auto load_kv = [&](int buf, int j0){
        #pragma unroll
        for (int itr=0; itr<8; itr++){
            int row = kr + itr*8;
            cpa16(smem_u32(Ks + ((size_t)buf*64 + row)*KV_LD + kc), K + (size_t)(j0+row)*ld + kc);
        }
        #pragma unroll
        for (int itr=0; itr<8; itr++){
            int row = kr + itr*8;
            cpa16(smem_u32(Vs + ((size_t)buf*64 + row)*KV_LD + kc), V + (size_t)(j0+row)*ld + kc);
        }
        cpa_commit();
    };

    load_kv(0, 0);

    // stage Q (pre-rounded; *0.125 exact)
    #pragma unroll
    for (int r=0;r<16;r++){
        int idx = tid + r*128;
        int row = idx>>4, c4 = idx&15;
        float4 qv = *reinterpret_cast<const float4*>(Q + (size_t)row*ld + c4*4);
        QP[row*QP_LD + c4*4+0] = qv.x*0.125f;
        QP[row*QP_LD + c4*4+1] = qv.y*0.125f;
        QP[row*QP_LD + c4*4+2] = qv.z*0.125f;
        QP[row*QP_LD + c4*4+3] = qv.w*0.125f;
    }
    __syncthreads();

    // Q a-fragments, k-lane remap: lane tq -> col 2tq, lane tq+4 -> col 2tq+1
    const int r0 = warp*32 + gq;
    float aq[2][8][4];
    #pragma unroll
    for (int g=0; g<2; g++){
        int rg = r0 + g*16;
        #pragma unroll
        for (int kk=0;kk<8;kk++){
            float2 q02 = *reinterpret_cast<const float2*>(&QP[ rg    *QP_LD + kk*8 + 2*tq]);
            float2 q13 = *reinterpret_cast<const float2*>(&QP[(rg+8)*QP_LD + kk*8 + 2*tq]);
            aq[g][kk][0]=q02.x; aq[g][kk][2]=q02.y;
            aq[g][kk][1]=q13.x; aq[g][kk][3]=q13.y;
        }
    }

    float o[2][8][4];
    #pragma unroll
    for (int g=0;g<2;g++)
        #pragma unroll
        for (int i=0;i<8;i++){ o[g][i][0]=0.f;o[g][i][1]=0.f;o[g][i][2]=0.f;o[g][i][3]=0.f; }
    float mrow[4] = {-1e30f,-1e30f,-1e30f,-1e30f};
    float lrow[4] = {0.f,0.f,0.f,0.f};

    const int NT = Nn/64;
    for (int j=0;j<NT;j++){
        const int buf = j&1;
        cpa_wait<0>();
        __syncthreads();    // also orders compute(j-1) before prefetch below overwrites
        if (j+1 < NT) load_kv(buf^1, (j+1)*64);

        const float* Kb_ = Ks + (size_t)buf*64*KV_LD;
        const float* Vb_ = Vs + (size_t)buf*64*KV_LD;

        // S = (Q*scale) K^T ; K b-frags LDS.64 via remap
        float c[2][8][4];
        #pragma unroll
        for (int nf=0;nf<8;nf++){
            #pragma unroll
            for (int g=0;g<2;g++){ c[g][nf][0]=0.f;c[g][nf][1]=0.f;c[g][nf][2]=0.f;c[g][nf][3]=0.f; }
            #pragma unroll
            for (int kk=0;kk<8;kk++){
                float2 bb = *reinterpret_cast<const float2*>(&Kb_[(nf*8+gq)*KV_LD + kk*8 + 2*tq]);
                float b[2] = {bb.x, bb.y};
                mma_tf32(c[0][nf], aq[0][kk], b);
                mma_tf32(c[1][nf], aq[1][kk], b);
            }
        }

        // online softmax; P stays in c registers
        #pragma unroll
        for (int g=0;g<2;g++){
            float mx0=-1e30f, mx1=-1e30f;
            #pragma unroll
            for (int nf=0;nf<8;nf++){
                mx0 = fmaxf(mx0, fmaxf(c[g][nf][0], c[g][nf][1]));
                mx1 = fmaxf(mx1, fmaxf(c[g][nf][2], c[g][nf][3]));
            }
            mx0 = fmaxf(mx0, __shfl_xor_sync(0xffffffffu, mx0, 1));
            mx0 = fmaxf(mx0, __shfl_xor_sync(0xffffffffu, mx0, 2));
            mx1 = fmaxf(mx1, __shfl_xor_sync(0xffffffffu, mx1, 1));
            mx1 = fmaxf(mx1, __shfl_xor_sync(0xffffffffu, mx1, 2));
            float nm0 = fmaxf(mrow[g*2],   mx0);
            float nm1 = fmaxf(mrow[g*2+1], mx1);
            float al0 = __expf(mrow[g*2]  -nm0);
            float al1 = __expf(mrow[g*2+1]-nm1);
            float s0=0.f, s1=0.f;
            #pragma unroll
            for (int nf=0;nf<8;nf++){
                c[g][nf][0]=__expf(c[g][nf][0]-nm0); c[g][nf][1]=__expf(c[g][nf][1]-nm0);
                c[g][nf][2]=__expf(c[g][nf][2]-nm1); c[g][nf][3]=__expf(c[g][nf][3]-nm1);
                s0 += c[g][nf][0]+c[g][nf][1]; s1 += c[g][nf][2]+c[g][nf][3];
            }
            s0 += __shfl_xor_sync(0xffffffffu, s0, 1);
            s0 += __shfl_xor_sync(0xffffffffu, s0, 2);
            s1 += __shfl_xor_sync(0xffffffffu, s1, 1);
            s1 += __shfl_xor_sync(0xffffffffu, s1, 2);
            lrow[g*2]   = lrow[g*2]*al0   + s0;
            lrow[g*2+1] = lrow[g*2+1]*al1 + s1;
            mrow[g*2] = nm0; mrow[g*2+1] = nm1;
            #pragma unroll
            for (int nd=0;nd<8;nd++){
                o[g][nd][0]*=al0; o[g][nd][1]*=al0; o[g][nd][2]*=al1; o[g][nd][3]*=al1;
            }
        }

        // O += P V : P a-frag = accumulator permutation {c0,c2,c1,c3} (k-lane remap)
        #pragma unroll
        for (int kk=0;kk<8;kk++){
            float ap0[4] = { c[0][kk][0], c[0][kk][2], c[0][kk][1], c[0][kk][3] };
            float ap1[4] = { c[1][kk][0], c[1][kk][2], c[1][kk][1], c[1][kk][3] };
            #pragma unroll
            for (int nd=0;nd<8;nd++){
                float b[2];
                b[0] = Vb_[(kk*8+2*tq  )*KV_LD + nd*8 + gq];
                b[1] = Vb_[(kk*8+2*tq+1)*KV_LD + nd*8 + gq];
                mma_tf32(o[0][nd], ap0, b);
                mma_tf32(o[1][nd], ap1, b);
            }
        }
    }

    #pragma unroll
    for (int g=0;g<2;g++){
        int rg = r0 + g*16;
        const float inv0 = 1.f/lrow[g*2], inv1 = 1.f/lrow[g*2+1];
        #pragma unroll
        for (int nd=0;nd<8;nd++){
            float2 w0; w0.x = tf32f(o[g][nd][0]*inv0); w0.y = tf32f(o[g][nd][1]*inv0);
            float2 w1; w1.x = tf32f(o[g][nd][2]*inv1); w1.y = tf32f(o[g][nd][3]*inv1);
            *reinterpret_cast<float2*>(O + (size_t) rg   *Dd + nd*8 + 2*tq) = w0;
            *reinterpret_cast<float2*>(O + (size_t)(rg+8)*Dd + nd*8 + 2*tq) = w1;
        }
    }
}

// ---------------- prep: weights round + init x/xr (one launch) ----------------
__global__ void prep_k(const float* a,const float* b,const float* c,const float* d,
                       const float* e,const float* f,const float* g,const float* h,
                       const float* i, const float* d0, const float* d1)
{
    int t = blockIdx.x*blockDim.x + threadIdx.x;
    switch (blockIdx.y){
        case 0: if (t<196608) w_qkv[t]        = tf32f(a[t]); break;
        case 1: if (t<65536)  w_out[t]        = tf32f(b[t]); break;
        case 2: if (t<262144) w_s1[t]         = tf32f(c[t]); break;
        case 3: if (t<131072) w_s2[t]         = tf32f(d[t]); break;
        case 4: if (t<65536)  w_cqkv[t]       = tf32f(e[t]); break;
        case 5: if (t<65536)  w_cqkv[65536+t] = tf32f(f[t]); break;
        case 6: if (t<65536)  w_co[t]         = tf32f(g[t]); break;
        case 7: if (t<262144) w_c1[t]         = tf32f(h[t]); break;
        case 8: if (t<131072) w_c2[t]         = tf32f(i[t]); break;
        case 9:
            if (t < 2*(int)BND){
                float v = (t < (int)BND) ? d0[t] : d1[t-(int)BND];
                g_x[t] = v; g_xr[t] = tf32f(v);
            }
            break;
    }
}

__global__ void qkv_rope_k(const float* __restrict__ qkv,
                           const float* __restrict__ enc0,
                           const float* __restrict__ enc1,
                           float* __restrict__ Q, float* __restrict__ K,
                           float* __restrict__ V)
{
    int idx = blockIdx.x*blockDim.x + threadIdx.x;
    const int total = 2*Bb*Hh*Nn*(HDd/2);
    if (idx >= total) return;
    int p = idx % (HDd/2); int t = idx / (HDd/2);
    int n = t % Nn; t /= Nn;
    int h = t % Hh; t /= Hh;
    int b = t % Bb; int s = t / Bb;
    size_t r = (size_t)(s*Bb + b)*Nn + n;
    const float* row = qkv + r*(3*Dd);
    int d0 = 2*p, d1 = 2*p+1;
    float q0 = row[h*192 + d0*3 + 0], q1 = row[h*192 + d1*3 + 0];
    float k0 = row[h*192 + d0*3 + 1], k1 = row[h*192 + d1*3 + 1];
    float v0 = row[h*192 + d0*3 + 2], v1 = row[h*192 + d1*3 + 2];
    const float* enc = s ? enc1 : enc0;
    size_t eoff = ((size_t)b*Nn + n)*HDd;
    float c = enc[eoff + d0];
    float si = enc[(size_t)Bb*Nn*HDd + eoff + d0];
    float qo0 = q0*c - q1*si, qo1 = q1*c + q0*si;
    float ko0 = k0*c - k1*si, ko1 = k1*c + k0*si;
    size_t bh = (size_t)(s*Bb + b)*Hh + h;
    size_t o = (bh*Nn + n)*HDd;
    Q[o+d0]=tf32f(qo0); Q[o+d1]=tf32f(qo1);
    K[o+d0]=tf32f(ko0); K[o+d1]=tf32f(ko1);
    V[o+d0]=tf32f(v0);  V[o+d1]=tf32f(v1);
}

__global__ void ln_gelu_k(float* __restrict__ X, const float* __restrict__ g,
                          const float* __restrict__ be)
{
    float* p = X + (size_t)blockIdx.x * 512;
    int tid = threadIdx.x;
    float a = p[tid], b = p[tid+256];
    float s = a + b;
    float sq = a*a + b*b;
    #pragma unroll
    for (int o=16;o;o>>=1){ s += __shfl_xor_sync(0xffffffffu,s,o);
                            sq += __shfl_xor_sync(0xffffffffu,sq,o); }
    __shared__ float ss[8], sqs[8];
    if ((tid&31)==0){ ss[tid>>5]=s; sqs[tid>>5]=sq; }
    __syncthreads();
    s = 0.f; sq = 0.f;
    #pragma unroll
    for (int t=0;t<8;t++){ s+=ss[t]; sq+=sqs[t]; }
    float mean = s * (1.0f/512.0f);
    float var  = sq * (1.0f/512.0f) - mean*mean;
    float inv = rsqrtf(var + 1e-5f);
    float y0 = (a-mean)*inv*g[tid]     + be[tid];
    float y1 = (b-mean)*inv*g[tid+256] + be[tid+256];
    p[tid]     = tf32f(0.5f*y0*(1.0f+erff(y0*0.70710678118f)));
    p[tid+256] = tf32f(0.5f*y1*(1.0f+erff(y1*0.70710678118f)));
}

// ================= host orchestration =================
extern "C" void kernel_launch(void* const* d_in, const int* in_sizes, int n_in,
                              void* d_out, int out_size)
{
    const float* desc0  = (const float*)d_in[0];
    const float* desc1  = (const float*)d_in[1];
    const float* enc0   = (const float*)d_in[2];
    const float* enc1   = (const float*)d_in[3];
    const float* s_Wqkv = (const float*)d_in[4];
    const float* s_bqkv = (const float*)d_in[5];
    const float* s_Wout = (const float*)d_in[6];
    const float* s_bout = (const float*)d_in[7];
    const float* s_W1   = (const float*)d_in[8];
    const float* s_b1   = (const float*)d_in[9];
    const float* s_g    = (const float*)d_in[10];
    const float* s_be   = (const float*)d_in[11];
    const float* s_W2   = (const float*)d_in[12];
    const float* s_b2   = (const float*)d_in[13];
    const float* c_Wqk  = (const float*)d_in[14];
    const float* c_bqk  = (const float*)d_in[15];
    const float* c_Wv   = (const float*)d_in[16];
    const float* c_bv   = (const float*)d_in[17];
    const float* c_Wo   = (const float*)d_in[18];
    const float* c_bo   = (const float*)d_in[19];
    const float* c_W1   = (const float*)d_in[20];
    const float* c_b1   = (const float*)d_in[21];
    const float* c_g    = (const float*)d_in[22];
    const float* c_be   = (const float*)d_in[23];
    const float* c_W2   = (const float*)d_in[24];
    const float* c_b2   = (const float*)d_in[25];
    float* out = (float*)d_out;

    float *x,*xr,*qkv,*q,*k,*v,*tmp,*hb;
    float *wqkv,*wout,*ws1,*ws2,*wcqkv,*wco,*wc1,*wc2;
    cudaGetSymbolAddress((void**)&x,   g_x);
    cudaGetSymbolAddress((void**)&xr,  g_xr);
    cudaGetSymbolAddress((void**)&qkv, g_qkv);
    cudaGetSymbolAddress((void**)&q,   g_q);
    cudaGetSymbolAddress((void**)&k,   g_k);
    cudaGetSymbolAddress((void**)&v,   g_v);
    cudaGetSymbolAddress((void**)&tmp, g_tmp);
    cudaGetSymbolAddress((void**)&hb,  g_h);
    cudaGetSymbolAddress((void**)&wqkv, w_qkv);
    cudaGetSymbolAddress((void**)&wout, w_out);
    cudaGetSymbolAddress((void**)&ws1,  w_s1);
    cudaGetSymbolAddress((void**)&ws2,  w_s2);
    cudaGetSymbolAddress((void**)&wcqkv,w_cqkv);
    cudaGetSymbolAddress((void**)&wco,  w_co);
    cudaGetSymbolAddress((void**)&wc1,  w_c1);
    cudaGetSymbolAddress((void**)&wc2,  w_c2);

    cudaFuncSetAttribute(flash_k, cudaFuncAttributeMaxDynamicSharedMemorySize, FA_SMEM);
    cudaFuncSetAttribute(mgemm,   cudaFuncAttributeMaxDynamicSharedMemorySize, MG_SMEM);

    auto GE = [&](const float* A,const float* A2,int lda,const float* W,int ldb,
                  float* C,int ldc,const float* bias,const float* bias2,
                  const float* Res,int ldr,int M,int Nc,int K,int ro,float* Cr){
        dim3 gr(Nc/128, M/128);
        mgemm<<<gr,128,MG_SMEM>>>(A,A2,lda,W,ldb,C,ldc,bias,bias2,Res,ldr,K,ro,Cr);
    };

    // 1: prep
    {
        dim3 gr((2*(int)BND+255)/256, 10);
        prep_k<<<gr,256>>>(s_Wqkv,s_Wout,s_W1,s_W2,c_Wqk,c_Wv,c_Wo,c_W1,c_W2,desc0,desc1);
    }
    // 2: qkv
    GE(xr,nullptr,Dd, wqkv,Dd, qkv,3*Dd, s_bqkv,nullptr, nullptr,0, M2,3*Dd,Dd, 0,nullptr);
    // 3: rope
    {
        int total = 2*Bb*Hh*Nn*(HDd/2);
        qkv_rope_k<<<(total+255)/256,256>>>(qkv, enc0, enc1, q, k, v);
    }
    // 4: flash self -> tmp   [ncu window]
    {
        dim3 gr(Nn/128, 2*Bb*Hh);
        flash_k<<<gr,128,FA_SMEM>>>(q, k, v, tmp, 0);
    }
    // 5: msg
    GE(tmp,nullptr,Dd, wout,Dd, qkv,Dd, s_bout,nullptr, nullptr,0, M2,Dd,Dd, 1,nullptr);
    GE(xr,qkv,Dd, ws1,2*Dd, hb,2*Dd, s_b1,nullptr, nullptr,0, M2,2*Dd,2*Dd, 0,nullptr);
    ln_gelu_k<<<M2,256>>>(hb, s_g, s_be);
    GE(hb,nullptr,2*Dd, ws2,2*Dd, x,Dd, s_b2,nullptr, x,Dd, M2,Dd,2*Dd, 0,xr);

    // ======== CROSS block ========
    GE(xr,nullptr,Dd, wcqkv,Dd, hb,512, c_bqk,c_bv, nullptr,0, M2,512,Dd, 1,nullptr);
    {
        dim3 gr(Nn/128, 2*Bb*Hh);
        flash_k<<<gr,128,FA_SMEM>>>(hb, hb, hb+256, qkv, 1);
    }
    GE(qkv,nullptr,Dd, wco,Dd, tmp,Dd, c_bo,nullptr, nullptr,0, M2,Dd,Dd, 1,nullptr);
    GE(xr,tmp,Dd, wc1,2*Dd, hb,2*Dd, c_b1,nullptr, nullptr,0, M2,2*Dd,2*Dd, 0,nullptr);
    ln_gelu_k<<<M2,256>>>(hb, c_g, c_be);
    GE(hb,nullptr,2*Dd, wc2,2*Dd, out,Dd, c_b2,nullptr, x,Dd, M2,Dd,2*Dd, 0,nullptr);
}